// round 6
// baseline (speedup 1.0000x reference)
#include <cuda_runtime.h>
#include <math.h>
#include <stdint.h>

#define D32   32
#define OD    16
#define NB    4
#define KK    32
#define R2C   0.09f
#define EPSF  1e-5f
#define NMAX  100000
#define IC    128
#define MR    (IC*IC)

typedef unsigned long long u64;

// ---------------- device scratch (no allocations allowed) ----------------
__device__ float g_yA[NMAX*64];
__device__ float g_yB[NMAX*64];
__device__ float g_maskf[NMAX*OD];
__device__ float g_kernf[NMAX*OD];
__device__ float g_stats[3*128];
__device__ float g_mstats[3*128];
__device__ int   g_topk[IC];
__device__ float g_feat[IC*35];
__device__ float g_ctr[IC*3];
__device__ int   g_cb[IC];
__device__ float g_mA[MR*35];
__device__ float g_mB[MR*35];
__device__ float g_nmsbuf[NMAX];
// candidate-pair interleaved mask-head weights
__device__ float g_w1aug2[64*16*40];
__device__ float g_w2p[64*16*2];
__device__ float g_b2p[64*2];

__device__ __forceinline__ float sigmoidf_(float x) {
    return 1.0f / (1.0f + __expf(-x));
}
__device__ __forceinline__ u64 pack2(float lo, float hi) {
    u64 r; asm("mov.b64 %0, {%1, %2};" : "=l"(r) : "f"(lo), "f"(hi)); return r;
}
__device__ __forceinline__ u64 dup2(float x) { return pack2(x, x); }
__device__ __forceinline__ void unpack2(u64 v, float &lo, float &hi) {
    asm("mov.b64 {%0, %1}, %2;" : "=f"(lo), "=f"(hi) : "l"(v));
}
__device__ __forceinline__ u64 ffma2(u64 a, u64 b, u64 c) {
    u64 d; asm("fma.rn.f32x2 %0, %1, %2, %3;" : "=l"(d) : "l"(a), "l"(b), "l"(c)); return d;
}

// ---------------- init ----------------
__global__ void init_kernel() {
    int t = threadIdx.x;
    if (t < 384) { g_stats[t] = 0.f; g_mstats[t] = 0.f; }
}

// ---------------- greedy top-K NMS: heat register-resident ----------------
__global__ __launch_bounds__(1024, 1)
void nms_kernel(const float* __restrict__ heat, const float* __restrict__ coords,
                const int* __restrict__ bidx, int N) {
    int b = blockIdx.x;
    int lo = 0, hi = N;
    while (lo < hi) { int m = (lo + hi) >> 1; if (bidx[m] < b) lo = m + 1; else hi = m; }
    int s = lo; hi = N;
    while (lo < hi) { int m = (lo + hi) >> 1; if (bidx[m] <= b) lo = m + 1; else hi = m; }
    int e = lo, nb = e - s;

    __shared__ float rv[32]; __shared__ int ri[32];
    __shared__ float cc[3]; __shared__ int have;
    if (threadIdx.x == 0) have = 0;

    const float NEG = __int_as_float(0xff800000);
    int lane = threadIdx.x & 31, w = threadIdx.x >> 5;

    if (nb <= 32768) {
        // register-resident heat: element ii -> global batch offset ii*1024 + tid
        float hv[32];
        #pragma unroll
        for (int ii = 0; ii < 32; ii++) {
            int t = ii*1024 + threadIdx.x;
            hv[ii] = (t < nb) ? heat[s + t] : NEG;
        }
        __syncthreads();
        for (int k = 0; k < KK; k++) {
            int h = have;
            float cx = 0.f, cy = 0.f, cz = 0.f;
            if (h) { cx = cc[0]; cy = cc[1]; cz = cc[2]; }
            float best = NEG; int bi = 0x7fffffff;
            #pragma unroll
            for (int ii = 0; ii < 32; ii++) {
                int t = ii*1024 + threadIdx.x;
                if (t >= nb) break;
                float v = hv[ii];
                if (h && v != NEG) {
                    int g = s + t;
                    float dx = coords[g*3]   - cx;
                    float dy = coords[g*3+1] - cy;
                    float dz = coords[g*3+2] - cz;
                    if (dx*dx + dy*dy + dz*dz < R2C) { v = NEG; hv[ii] = NEG; }
                }
                if (v > best) { best = v; bi = t; }
            }
            #pragma unroll
            for (int o = 16; o; o >>= 1) {
                float ov = __shfl_down_sync(0xffffffffu, best, o);
                int   oi = __shfl_down_sync(0xffffffffu, bi, o);
                if (ov > best || (ov == best && oi < bi)) { best = ov; bi = oi; }
            }
            if (lane == 0) { rv[w] = best; ri[w] = bi; }
            __syncthreads();
            if (w == 0) {
                best = rv[lane]; bi = ri[lane];
                #pragma unroll
                for (int o = 16; o; o >>= 1) {
                    float ov = __shfl_down_sync(0xffffffffu, best, o);
                    int   oi = __shfl_down_sync(0xffffffffu, bi, o);
                    if (ov > best || (ov == best && oi < bi)) { best = ov; bi = oi; }
                }
                if (lane == 0) {
                    int chosen = (best == NEG) ? 0 : (s + bi);
                    g_topk[b*KK + k] = chosen;
                    cc[0] = coords[chosen*3]; cc[1] = coords[chosen*3+1]; cc[2] = coords[chosen*3+2];
                    have = 1;
                }
            }
            __syncthreads();
        }
    } else {
        float* buf = g_nmsbuf + s;
        for (int t = threadIdx.x; t < nb; t += 1024) buf[t] = heat[s + t];
        __syncthreads();
        for (int k = 0; k < KK; k++) {
            int h = have;
            float cx = 0.f, cy = 0.f, cz = 0.f;
            if (h) { cx = cc[0]; cy = cc[1]; cz = cc[2]; }
            float best = NEG; int bi = 0x7fffffff;
            for (int t = threadIdx.x; t < nb; t += 1024) {
                float v = buf[t];
                if (h && v != NEG) {
                    int g = s + t;
                    float dx = coords[g*3]   - cx;
                    float dy = coords[g*3+1] - cy;
                    float dz = coords[g*3+2] - cz;
                    if (dx*dx + dy*dy + dz*dz < R2C) { v = NEG; buf[t] = NEG; }
                }
                if (v > best) { best = v; bi = t; }
            }
            #pragma unroll
            for (int o = 16; o; o >>= 1) {
                float ov = __shfl_down_sync(0xffffffffu, best, o);
                int   oi = __shfl_down_sync(0xffffffffu, bi, o);
                if (ov > best || (ov == best && oi < bi)) { best = ov; bi = oi; }
            }
            if (lane == 0) { rv[w] = best; ri[w] = bi; }
            __syncthreads();
            if (w == 0) {
                best = rv[lane]; bi = ri[lane];
                #pragma unroll
                for (int o = 16; o; o >>= 1) {
                    float ov = __shfl_down_sync(0xffffffffu, best, o);
                    int   oi = __shfl_down_sync(0xffffffffu, bi, o);
                    if (ov > best || (ov == best && oi < bi)) { best = ov; bi = oi; }
                }
                if (lane == 0) {
                    int chosen = (best == NEG) ? 0 : (s + bi);
                    g_topk[b*KK + k] = chosen;
                    cc[0] = coords[chosen*3]; cc[1] = coords[chosen*3+1]; cc[2] = coords[chosen*3+2];
                    have = 1;
                }
            }
            __syncthreads();
        }
    }
}

// ---------------- tower layer (pure GEMM, FFMA2) ----------------
__global__ __launch_bounds__(256, 1)
void tower_layer_kernel(const float* __restrict__ x, float* __restrict__ y,
                        const float* __restrict__ Wml, const float* __restrict__ Wkl,
                        const float* __restrict__ pstats,
                        int N, int layer0) {
    __shared__ float Ws[32*64];
    __shared__ float smean[64], srstd[64];
    for (int t = threadIdx.x; t < 2048; t += 256) {
        int d = t >> 6, j = t & 63;
        Ws[t] = (j < 32) ? Wml[d*32 + j] : Wkl[d*32 + (j - 32)];
    }
    if (!layer0 && threadIdx.x < 64) {
        float s = pstats[threadIdx.x], q = pstats[64 + threadIdx.x];
        float m = s / (float)N;
        float v = q / (float)N - m*m;
        smean[threadIdx.x] = m;
        srstd[threadIdx.x] = rsqrtf(v + EPSF);
    }
    __syncthreads();

    int n = blockIdx.x * 256 + threadIdx.x;
    if (n >= N) return;
    int instr = (layer0 ? 32 : 64);

    #pragma unroll
    for (int half = 0; half < 2; half++) {
        float xv[32];
        u64 acc[16];
        #pragma unroll
        for (int j = 0; j < 16; j++) acc[j] = 0ull;

        int coff = layer0 ? 0 : half * 32;
        const float4* xr = (const float4*)(x + (size_t)n * instr + coff);
        if (layer0) {
            #pragma unroll
            for (int q = 0; q < 8; q++) {
                float4 v = xr[q]; int d = q*4;
                xv[d] = v.x; xv[d+1] = v.y; xv[d+2] = v.z; xv[d+3] = v.w;
            }
        } else {
            #pragma unroll
            for (int q = 0; q < 8; q++) {
                float4 v = xr[q]; int d = q*4; int c = coff + d;
                xv[d]   = fmaxf((v.x - smean[c])   * srstd[c],   0.f);
                xv[d+1] = fmaxf((v.y - smean[c+1]) * srstd[c+1], 0.f);
                xv[d+2] = fmaxf((v.z - smean[c+2]) * srstd[c+2], 0.f);
                xv[d+3] = fmaxf((v.w - smean[c+3]) * srstd[c+3], 0.f);
            }
        }
        #pragma unroll 4
        for (int d = 0; d < 32; d++) {
            u64 xd = dup2(xv[d]);
            const u64* wr = (const u64*)(Ws + d*64 + half*32);
            #pragma unroll
            for (int q = 0; q < 16; q++) acc[q] = ffma2(xd, wr[q], acc[q]);
        }
        ulonglong2* yr = (ulonglong2*)(y + (size_t)n * 64 + half*32);
        #pragma unroll
        for (int q = 0; q < 8; q++) yr[q] = make_ulonglong2(acc[2*q], acc[2*q+1]);
    }
}

// ---------------- column stats (sum + sumsq) ----------------
__global__ __launch_bounds__(256, 1)
void colstats_kernel(const float* __restrict__ y, float* __restrict__ ostats, int N) {
    int tid = threadIdx.x;
    int lane16 = tid & 15;
    float4 s = make_float4(0.f,0.f,0.f,0.f);
    float4 q = make_float4(0.f,0.f,0.f,0.f);
    #pragma unroll 4
    for (int r = blockIdx.x*16 + (tid >> 4); r < N; r += gridDim.x*16) {
        float4 v = ((const float4*)(y + (size_t)r*64))[lane16];
        s.x += v.x; s.y += v.y; s.z += v.z; s.w += v.w;
        q.x = fmaf(v.x, v.x, q.x); q.y = fmaf(v.y, v.y, q.y);
        q.z = fmaf(v.z, v.z, q.z); q.w = fmaf(v.w, v.w, q.w);
    }
    __shared__ float sm[256][8];
    sm[tid][0] = s.x; sm[tid][1] = s.y; sm[tid][2] = s.z; sm[tid][3] = s.w;
    sm[tid][4] = q.x; sm[tid][5] = q.y; sm[tid][6] = q.z; sm[tid][7] = q.w;
    __syncthreads();
    if (tid < 16) {
        float a0=0,a1=0,a2=0,a3=0,b0=0,b1=0,b2=0,b3=0;
        #pragma unroll
        for (int g = 0; g < 16; g++) {
            float* p = sm[tid + 16*g];
            a0 += p[0]; a1 += p[1]; a2 += p[2]; a3 += p[3];
            b0 += p[4]; b1 += p[5]; b2 += p[6]; b3 += p[7];
        }
        int c = tid*4;
        atomicAdd(&ostats[c],   a0); atomicAdd(&ostats[c+1], a1);
        atomicAdd(&ostats[c+2], a2); atomicAdd(&ostats[c+3], a3);
        atomicAdd(&ostats[64+c],   b0); atomicAdd(&ostats[64+c+1], b1);
        atomicAdd(&ostats[64+c+2], b2); atomicAdd(&ostats[64+c+3], b3);
    }
}

// ---------------- final projection ----------------
__global__ __launch_bounds__(256, 1)
void feats_kernel(const float* __restrict__ yin,
                  const float* __restrict__ Wmo, const float* __restrict__ bmo,
                  const float* __restrict__ Wko, const float* __restrict__ bko,
                  const float* __restrict__ pstats, int N) {
    __shared__ float Wos[32*32];
    __shared__ float bs[32];
    __shared__ float smean[64], srstd[64];
    for (int t = threadIdx.x; t < 1024; t += 256) {
        int d = t >> 5, j = t & 31;
        Wos[t] = (j < 16) ? Wmo[d*16 + j] : Wko[d*16 + (j - 16)];
    }
    if (threadIdx.x < 32) bs[threadIdx.x] = (threadIdx.x < 16) ? bmo[threadIdx.x] : bko[threadIdx.x - 16];
    if (threadIdx.x < 64) {
        float s = pstats[threadIdx.x], q = pstats[64 + threadIdx.x];
        float m = s / (float)N;
        float v = q / (float)N - m*m;
        smean[threadIdx.x] = m; srstd[threadIdx.x] = rsqrtf(v + EPSF);
    }
    __syncthreads();
    int n = blockIdx.x * 256 + threadIdx.x;
    if (n >= N) return;

    #pragma unroll
    for (int half = 0; half < 2; half++) {
        float xv[32];
        const float4* xr = (const float4*)(yin + (size_t)n * 64 + half*32);
        #pragma unroll
        for (int q = 0; q < 8; q++) {
            float4 v = xr[q]; int d = q*4; int c = half*32 + d;
            xv[d]   = fmaxf((v.x - smean[c])   * srstd[c],   0.f);
            xv[d+1] = fmaxf((v.y - smean[c+1]) * srstd[c+1], 0.f);
            xv[d+2] = fmaxf((v.z - smean[c+2]) * srstd[c+2], 0.f);
            xv[d+3] = fmaxf((v.w - smean[c+3]) * srstd[c+3], 0.f);
        }
        u64 acc[8];
        #pragma unroll
        for (int j = 0; j < 8; j++) acc[j] = 0ull;
        #pragma unroll 4
        for (int d = 0; d < 32; d++) {
            u64 xd = dup2(xv[d]);
            const u64* wr = (const u64*)(Wos + d*32 + half*16);
            #pragma unroll
            for (int q = 0; q < 8; q++) acc[q] = ffma2(xd, wr[q], acc[q]);
        }
        float* dst = half ? (g_kernf + (size_t)n * 16) : (g_maskf + (size_t)n * 16);
        #pragma unroll
        for (int q = 0; q < 8; q++) {
            float lo, hi; unpack2(acc[q], lo, hi);
            int j = q*2; int bj = half*16 + j;
            dst[j] = lo + bs[bj]; dst[j+1] = hi + bs[bj+1];
        }
    }
}

// ---------------- candidate gather + weight generator + aug-weight build ----------------
__global__ void cand_prep_kernel(const float* __restrict__ coords, const int* __restrict__ bidx,
                                 const float* __restrict__ Wwg, const float* __restrict__ bwg) {
    int i = blockIdx.x;
    int tid = threadIdx.x;
    __shared__ float ck[16];
    __shared__ float ws[337];
    __shared__ float cc[3];
    __shared__ int sidx;
    if (tid == 0) sidx = g_topk[i];
    __syncthreads();
    int idx = sidx;
    if (tid < 16) {
        float v = g_kernf[(size_t)idx*16 + tid];
        ck[tid] = v;
        g_feat[i*35 + tid] = v;
    } else if (tid < 32) {
        g_feat[i*35 + tid] = g_maskf[(size_t)idx*16 + (tid - 16)];
    } else if (tid < 35) {
        float c = coords[(size_t)idx*3 + (tid - 32)];
        g_feat[i*35 + tid] = c;
        g_ctr[i*3 + (tid - 32)] = c;
        cc[tid - 32] = c;
    } else if (tid == 35) {
        g_cb[i] = bidx[idx];
    }
    __syncthreads();
    if (tid < 337) {
        float w = bwg[tid];
        #pragma unroll
        for (int d = 0; d < 16; d++) w = fmaf(ck[d], Wwg[d*337 + tid], w);
        ws[tid] = w;
    }
    __syncthreads();
    int pair = i >> 1, hf = i & 1;
    float cx = cc[0], cy = cc[1], cz = cc[2];
    for (int t = tid; t < 320; t += blockDim.x) {
        int j = t / 20, d = t % 20;
        float v;
        if (d < 16)      v = ws[d*16 + j];
        else if (d < 19) v = ws[(16 + (d-16))*16 + j];
        else             v = ws[304 + j] - cx*ws[256 + j] - cy*ws[272 + j] - cz*ws[288 + j];
        g_w1aug2[pair*640 + j*40 + d*2 + hf] = v;
    }
    if (tid < 16) g_w2p[pair*32 + tid*2 + hf] = ws[320 + tid];
    if (tid == 16) g_b2p[pair*2 + hf] = ws[336];
}

// ---------------- dynamic mask head: FFMA2, 8 cand-pairs/block, 2 pts/thread ----------------
__global__ __launch_bounds__(128, 1)
void masks_kernel(const float* __restrict__ coords, float* __restrict__ out, int N) {
    __shared__ float w1t[8*16*40];    // 20480 B
    __shared__ float w2s[8*16*2];
    __shared__ float b2s[8*2];
    int tid = threadIdx.x;
    int pbase = blockIdx.y * 8;       // candidate-pair base

    {
        const float4* src = (const float4*)(g_w1aug2 + pbase*640);
        float4* dst = (float4*)w1t;
        for (int t = tid; t < 1280; t += 128) dst[t] = src[t];
        for (int t = tid; t < 256; t += 128) w2s[t] = g_w2p[pbase*32 + t];
        if (tid < 16) b2s[tid] = g_b2p[pbase*2 + tid];
    }
    __syncthreads();

    int n0 = blockIdx.x * 256 + tid;
    int n1 = n0 + 128;
    bool v0 = (n0 < N), v1 = (n1 < N);
    int s0 = v0 ? n0 : (N - 1);
    int s1 = v1 ? n1 : (N - 1);

    u64 x0[19], x1[19];
    {
        const float4* mr = (const float4*)(g_maskf + (size_t)s0 * 16);
        #pragma unroll
        for (int q = 0; q < 4; q++) {
            float4 m = mr[q];
            x0[q*4]   = dup2(m.x); x0[q*4+1] = dup2(m.y);
            x0[q*4+2] = dup2(m.z); x0[q*4+3] = dup2(m.w);
        }
        x0[16] = dup2(coords[(size_t)s0*3]);
        x0[17] = dup2(coords[(size_t)s0*3+1]);
        x0[18] = dup2(coords[(size_t)s0*3+2]);
    }
    {
        const float4* mr = (const float4*)(g_maskf + (size_t)s1 * 16);
        #pragma unroll
        for (int q = 0; q < 4; q++) {
            float4 m = mr[q];
            x1[q*4]   = dup2(m.x); x1[q*4+1] = dup2(m.y);
            x1[q*4+2] = dup2(m.z); x1[q*4+3] = dup2(m.w);
        }
        x1[16] = dup2(coords[(size_t)s1*3]);
        x1[17] = dup2(coords[(size_t)s1*3+1]);
        x1[18] = dup2(coords[(size_t)s1*3+2]);
    }

    size_t ostride = (size_t)N + IC;
    const u64* w2q = (const u64*)w2s;

    #pragma unroll
    for (int cp = 0; cp < 8; cp++) {
        u64 macc0 = 0ull, macc1 = 0ull;
        const float* wb = w1t + cp*640;
        #pragma unroll 4
        for (int j = 0; j < 16; j++) {
            const u64* wq = (const u64*)(wb + j*40);
            u64 h0 = wq[19];
            u64 h1 = h0;
            #pragma unroll
            for (int d = 0; d < 19; d++) {
                u64 wd = wq[d];
                h0 = ffma2(x0[d], wd, h0);
                h1 = ffma2(x1[d], wd, h1);
            }
            u64 w2v = w2q[cp*16 + j];
            float a, b;
            unpack2(h0, a, b);
            h0 = pack2(fmaxf(a, 0.f), fmaxf(b, 0.f));
            macc0 = ffma2(h0, w2v, macc0);
            unpack2(h1, a, b);
            h1 = pack2(fmaxf(a, 0.f), fmaxf(b, 0.f));
            macc1 = ffma2(h1, w2v, macc1);
        }
        float ba = b2s[cp*2], bb = b2s[cp*2+1];
        int ci0 = (pbase + cp) * 2;
        float* row0 = out + (size_t)ci0 * ostride;
        float* row1 = out + (size_t)(ci0 + 1) * ostride;
        float a, b;
        unpack2(macc0, a, b);
        if (v0) { row0[n0] = sigmoidf_(a + ba); row1[n0] = sigmoidf_(b + bb); }
        unpack2(macc1, a, b);
        if (v1) { row0[n1] = sigmoidf_(a + ba); row1[n1] = sigmoidf_(b + bb); }
    }
}

// ---------------- merge tower layer ----------------
__global__ __launch_bounds__(256, 1)
void merge_layer_kernel(const float* __restrict__ xin, float* __restrict__ yout,
                        const float* __restrict__ Wgl,
                        const float* __restrict__ pstats, float* __restrict__ ostats,
                        int layer0) {
    __shared__ float Ws[35*35];
    __shared__ float featS[IC*35];
    __shared__ float smean[35], srstd[35];
    __shared__ float ps[8][70];
    int tid = threadIdx.x;
    for (int t = tid; t < 1225; t += 256) Ws[t] = Wgl[t];
    if (layer0) {
        for (int t = tid; t < IC*35; t += 256) featS[t] = g_feat[t];
    } else if (tid < 35) {
        float s = pstats[tid], q = pstats[64 + tid];
        float m = s / (float)MR;
        float v = q / (float)MR - m*m;
        smean[tid] = m; srstd[tid] = rsqrtf(v + EPSF);
    }
    __syncthreads();

    int row = blockIdx.x * 256 + tid;
    float xv[35];
    if (layer0) {
        int i = row >> 7, j = row & 127;
        #pragma unroll
        for (int c = 0; c < 35; c++)
            xv[c] = fmaxf(fabsf(featS[i*35 + c] - featS[j*35 + c]), 1e-6f);
    } else {
        #pragma unroll
        for (int c = 0; c < 35; c++)
            xv[c] = fmaxf((xin[(size_t)row*35 + c] - smean[c]) * srstd[c], 0.f);
    }
    float acc[35];
    #pragma unroll
    for (int c = 0; c < 35; c++) acc[c] = 0.f;
    for (int c = 0; c < 35; c++) {
        float xa = xv[c];
        const float* wr = Ws + c*35;
        #pragma unroll
        for (int c2 = 0; c2 < 35; c2++) acc[c2] = fmaf(xa, wr[c2], acc[c2]);
    }
    #pragma unroll
    for (int c = 0; c < 35; c++) yout[(size_t)row*35 + c] = acc[c];

    int lane = tid & 31, warp = tid >> 5;
    for (int c = 0; c < 35; c++) {
        float s = acc[c]; float q = s * s;
        #pragma unroll
        for (int o = 16; o; o >>= 1) {
            s += __shfl_down_sync(0xffffffffu, s, o);
            q += __shfl_down_sync(0xffffffffu, q, o);
        }
        if (lane == 0) { ps[warp][c] = s; ps[warp][35 + c] = q; }
    }
    __syncthreads();
    if (tid < 70) {
        float t = 0.f;
        #pragma unroll
        for (int w = 0; w < 8; w++) t += ps[w][tid];
        int target = (tid < 35) ? tid : (64 + tid - 35);
        atomicAdd(&ostats[target], t);
    }
}

// ---------------- merge output ----------------
__global__ __launch_bounds__(256, 1)
void merge_out_kernel(const float* __restrict__ xin,
                      const float* __restrict__ Wgo, const float* __restrict__ bgo,
                      const float* __restrict__ pstats,
                      float* __restrict__ out, int N) {
    __shared__ float wout[35];
    __shared__ float smean[35], srstd[35];
    int tid = threadIdx.x;
    if (tid < 35) {
        wout[tid] = Wgo[tid];
        float s = pstats[tid], q = pstats[64 + tid];
        float m = s / (float)MR;
        float v = q / (float)MR - m*m;
        smean[tid] = m; srstd[tid] = rsqrtf(v + EPSF);
    }
    __syncthreads();
    int row = blockIdx.x * 256 + tid;
    int i = row >> 7, j = row & 127;
    float acc = bgo[0];
    #pragma unroll
    for (int c = 0; c < 35; c++) {
        float x = fmaxf((xin[(size_t)row*35 + c] - smean[c]) * srstd[c], 0.f);
        acc = fmaf(x, wout[c], acc);
    }
    float v = (g_cb[i] != g_cb[j]) ? 0.f : sigmoidf_(acc);
    out[(size_t)i * ((size_t)N + IC) + (size_t)N + j] = v;
}

// ---------------- launch ----------------
extern "C" void kernel_launch(void* const* d_in, const int* in_sizes, int n_in,
                              void* d_out, int out_size) {
    const float* output_feats = (const float*)d_in[0];
    const float* coords       = (const float*)d_in[1];
    const float* heat         = (const float*)d_in[2];
    const int*   batch_idxs   = (const int*)  d_in[3];
    const float* Wm           = (const float*)d_in[4];
    const float* Wm_out       = (const float*)d_in[5];
    const float* bm_out       = (const float*)d_in[6];
    const float* Wk           = (const float*)d_in[7];
    const float* Wk_out       = (const float*)d_in[8];
    const float* bk_out       = (const float*)d_in[9];
    const float* Wg           = (const float*)d_in[10];
    const float* Wg_out       = (const float*)d_in[11];
    const float* bg_out       = (const float*)d_in[12];
    const float* Wwg          = (const float*)d_in[13];
    const float* bwg          = (const float*)d_in[14];
    float* out = (float*)d_out;
    int N = in_sizes[2];

    float *yA, *yB, *mA, *mB, *stats, *mstats;
    cudaGetSymbolAddress((void**)&yA, g_yA);
    cudaGetSymbolAddress((void**)&yB, g_yB);
    cudaGetSymbolAddress((void**)&mA, g_mA);
    cudaGetSymbolAddress((void**)&mB, g_mB);
    cudaGetSymbolAddress((void**)&stats, g_stats);
    cudaGetSymbolAddress((void**)&mstats, g_mstats);

    init_kernel<<<1, 384>>>();
    nms_kernel<<<NB, 1024>>>(heat, coords, batch_idxs, N);

    int tg = (N + 255) / 256;
    tower_layer_kernel<<<tg, 256>>>(output_feats, yA, Wm,        Wk,        nullptr,     N, 1);
    colstats_kernel<<<2048, 256>>>(yA, stats, N);
    tower_layer_kernel<<<tg, 256>>>(yA,           yB, Wm + 1024, Wk + 1024, stats,       N, 0);
    colstats_kernel<<<2048, 256>>>(yB, stats + 128, N);
    tower_layer_kernel<<<tg, 256>>>(yB,           yA, Wm + 2048, Wk + 2048, stats + 128, N, 0);
    colstats_kernel<<<2048, 256>>>(yA, stats + 256, N);
    feats_kernel<<<tg, 256>>>(yA, Wm_out, bm_out, Wk_out, bk_out, stats + 256, N);

    cand_prep_kernel<<<IC, 352>>>(coords, batch_idxs, Wwg, bwg);

    dim3 mg((N + 255) / 256, 8);
    masks_kernel<<<mg, 128>>>(coords, out, N);

    merge_layer_kernel<<<64, 256>>>(nullptr, mA, Wg,        nullptr,      mstats,       1);
    merge_layer_kernel<<<64, 256>>>(mA,      mB, Wg + 1225, mstats,       mstats + 128, 0);
    merge_layer_kernel<<<64, 256>>>(mB,      mA, Wg + 2450, mstats + 128, mstats + 256, 0);
    merge_out_kernel<<<64, 256>>>(mA, Wg_out, bg_out, mstats + 256, out, N);
}

// round 7
// speedup vs baseline: 1.5107x; 1.5107x over previous
#include <cuda_runtime.h>
#include <math.h>
#include <stdint.h>

#define D32   32
#define OD    16
#define NB    4
#define KK    32
#define R2C   0.09f
#define EPSF  1e-5f
#define NMAX  100000
#define IC    128
#define MR    (IC*IC)

typedef unsigned long long u64;

// ---------------- device scratch (no allocations allowed) ----------------
__device__ float g_yA[NMAX*64];
__device__ float g_yB[NMAX*64];
__device__ float g_maskf[NMAX*OD];
__device__ float g_kernf[NMAX*OD];
__device__ float g_stats[3*128];
__device__ float g_mstats[3*128];
__device__ int   g_topk[IC];
__device__ float g_feat[IC*35];
__device__ float g_ctr[IC*3];
__device__ int   g_cb[IC];
__device__ float g_mA[MR*35];
__device__ float g_mB[MR*35];
__device__ float g_nmsbuf[NMAX];
// candidate-pair interleaved mask-head weights
__device__ float g_w1aug2[64*16*40];
__device__ float g_w2p[64*16*2];
__device__ float g_b2p[64*2];

__device__ __forceinline__ float sigmoidf_(float x) {
    return 1.0f / (1.0f + __expf(-x));
}
__device__ __forceinline__ u64 pack2(float lo, float hi) {
    u64 r; asm("mov.b64 %0, {%1, %2};" : "=l"(r) : "f"(lo), "f"(hi)); return r;
}
__device__ __forceinline__ u64 dup2(float x) { return pack2(x, x); }
__device__ __forceinline__ void unpack2(u64 v, float &lo, float &hi) {
    asm("mov.b64 {%0, %1}, %2;" : "=f"(lo), "=f"(hi) : "l"(v));
}
__device__ __forceinline__ u64 ffma2(u64 a, u64 b, u64 c) {
    u64 d; asm("fma.rn.f32x2 %0, %1, %2, %3;" : "=l"(d) : "l"(a), "l"(b), "l"(c)); return d;
}

// ---------------- init ----------------
__global__ void init_kernel() {
    int t = threadIdx.x;
    if (t < 384) { g_stats[t] = 0.f; g_mstats[t] = 0.f; }
}

// ---------------- greedy top-K NMS: heat register-resident ----------------
__global__ __launch_bounds__(1024, 1)
void nms_kernel(const float* __restrict__ heat, const float* __restrict__ coords,
                const int* __restrict__ bidx, int N) {
    int b = blockIdx.x;
    int lo = 0, hi = N;
    while (lo < hi) { int m = (lo + hi) >> 1; if (bidx[m] < b) lo = m + 1; else hi = m; }
    int s = lo; hi = N;
    while (lo < hi) { int m = (lo + hi) >> 1; if (bidx[m] <= b) lo = m + 1; else hi = m; }
    int e = lo, nb = e - s;

    __shared__ float rv[32]; __shared__ int ri[32];
    __shared__ float cc[3]; __shared__ int have;
    if (threadIdx.x == 0) have = 0;

    const float NEG = __int_as_float(0xff800000);
    int lane = threadIdx.x & 31, w = threadIdx.x >> 5;

    if (nb <= 32768) {
        float hv[32];
        #pragma unroll
        for (int ii = 0; ii < 32; ii++) {
            int t = ii*1024 + threadIdx.x;
            hv[ii] = (t < nb) ? heat[s + t] : NEG;
        }
        __syncthreads();
        for (int k = 0; k < KK; k++) {
            int h = have;
            float cx = 0.f, cy = 0.f, cz = 0.f;
            if (h) { cx = cc[0]; cy = cc[1]; cz = cc[2]; }
            float best = NEG; int bi = 0x7fffffff;
            #pragma unroll
            for (int ii = 0; ii < 32; ii++) {
                int t = ii*1024 + threadIdx.x;
                if (t >= nb) break;
                float v = hv[ii];
                if (h && v != NEG) {
                    int g = s + t;
                    float dx = coords[g*3]   - cx;
                    float dy = coords[g*3+1] - cy;
                    float dz = coords[g*3+2] - cz;
                    if (dx*dx + dy*dy + dz*dz < R2C) { v = NEG; hv[ii] = NEG; }
                }
                if (v > best) { best = v; bi = t; }
            }
            #pragma unroll
            for (int o = 16; o; o >>= 1) {
                float ov = __shfl_down_sync(0xffffffffu, best, o);
                int   oi = __shfl_down_sync(0xffffffffu, bi, o);
                if (ov > best || (ov == best && oi < bi)) { best = ov; bi = oi; }
            }
            if (lane == 0) { rv[w] = best; ri[w] = bi; }
            __syncthreads();
            if (w == 0) {
                best = rv[lane]; bi = ri[lane];
                #pragma unroll
                for (int o = 16; o; o >>= 1) {
                    float ov = __shfl_down_sync(0xffffffffu, best, o);
                    int   oi = __shfl_down_sync(0xffffffffu, bi, o);
                    if (ov > best || (ov == best && oi < bi)) { best = ov; bi = oi; }
                }
                if (lane == 0) {
                    int chosen = (best == NEG) ? 0 : (s + bi);
                    g_topk[b*KK + k] = chosen;
                    cc[0] = coords[chosen*3]; cc[1] = coords[chosen*3+1]; cc[2] = coords[chosen*3+2];
                    have = 1;
                }
            }
            __syncthreads();
        }
    } else {
        float* buf = g_nmsbuf + s;
        for (int t = threadIdx.x; t < nb; t += 1024) buf[t] = heat[s + t];
        __syncthreads();
        for (int k = 0; k < KK; k++) {
            int h = have;
            float cx = 0.f, cy = 0.f, cz = 0.f;
            if (h) { cx = cc[0]; cy = cc[1]; cz = cc[2]; }
            float best = NEG; int bi = 0x7fffffff;
            for (int t = threadIdx.x; t < nb; t += 1024) {
                float v = buf[t];
                if (h && v != NEG) {
                    int g = s + t;
                    float dx = coords[g*3]   - cx;
                    float dy = coords[g*3+1] - cy;
                    float dz = coords[g*3+2] - cz;
                    if (dx*dx + dy*dy + dz*dz < R2C) { v = NEG; buf[t] = NEG; }
                }
                if (v > best) { best = v; bi = t; }
            }
            #pragma unroll
            for (int o = 16; o; o >>= 1) {
                float ov = __shfl_down_sync(0xffffffffu, best, o);
                int   oi = __shfl_down_sync(0xffffffffu, bi, o);
                if (ov > best || (ov == best && oi < bi)) { best = ov; bi = oi; }
            }
            if (lane == 0) { rv[w] = best; ri[w] = bi; }
            __syncthreads();
            if (w == 0) {
                best = rv[lane]; bi = ri[lane];
                #pragma unroll
                for (int o = 16; o; o >>= 1) {
                    float ov = __shfl_down_sync(0xffffffffu, best, o);
                    int   oi = __shfl_down_sync(0xffffffffu, bi, o);
                    if (ov > best || (ov == best && oi < bi)) { best = ov; bi = oi; }
                }
                if (lane == 0) {
                    int chosen = (best == NEG) ? 0 : (s + bi);
                    g_topk[b*KK + k] = chosen;
                    cc[0] = coords[chosen*3]; cc[1] = coords[chosen*3+1]; cc[2] = coords[chosen*3+2];
                    have = 1;
                }
            }
            __syncthreads();
        }
    }
}

// ---------------- tower layer (pure GEMM, FFMA2) ----------------
__global__ __launch_bounds__(256, 1)
void tower_layer_kernel(const float* __restrict__ x, float* __restrict__ y,
                        const float* __restrict__ Wml, const float* __restrict__ Wkl,
                        const float* __restrict__ pstats,
                        int N, int layer0) {
    __shared__ float Ws[32*64];
    __shared__ float smean[64], srstd[64];
    for (int t = threadIdx.x; t < 2048; t += 256) {
        int d = t >> 6, j = t & 63;
        Ws[t] = (j < 32) ? Wml[d*32 + j] : Wkl[d*32 + (j - 32)];
    }
    if (!layer0 && threadIdx.x < 64) {
        float s = pstats[threadIdx.x], q = pstats[64 + threadIdx.x];
        float m = s / (float)N;
        float v = q / (float)N - m*m;
        smean[threadIdx.x] = m;
        srstd[threadIdx.x] = rsqrtf(v + EPSF);
    }
    __syncthreads();

    int n = blockIdx.x * 256 + threadIdx.x;
    if (n >= N) return;
    int instr = (layer0 ? 32 : 64);

    #pragma unroll
    for (int half = 0; half < 2; half++) {
        float xv[32];
        u64 acc[16];
        #pragma unroll
        for (int j = 0; j < 16; j++) acc[j] = 0ull;

        int coff = layer0 ? 0 : half * 32;
        const float4* xr = (const float4*)(x + (size_t)n * instr + coff);
        if (layer0) {
            #pragma unroll
            for (int q = 0; q < 8; q++) {
                float4 v = xr[q]; int d = q*4;
                xv[d] = v.x; xv[d+1] = v.y; xv[d+2] = v.z; xv[d+3] = v.w;
            }
        } else {
            #pragma unroll
            for (int q = 0; q < 8; q++) {
                float4 v = xr[q]; int d = q*4; int c = coff + d;
                xv[d]   = fmaxf((v.x - smean[c])   * srstd[c],   0.f);
                xv[d+1] = fmaxf((v.y - smean[c+1]) * srstd[c+1], 0.f);
                xv[d+2] = fmaxf((v.z - smean[c+2]) * srstd[c+2], 0.f);
                xv[d+3] = fmaxf((v.w - smean[c+3]) * srstd[c+3], 0.f);
            }
        }
        #pragma unroll 4
        for (int d = 0; d < 32; d++) {
            u64 xd = dup2(xv[d]);
            const u64* wr = (const u64*)(Ws + d*64 + half*32);
            #pragma unroll
            for (int q = 0; q < 16; q++) acc[q] = ffma2(xd, wr[q], acc[q]);
        }
        ulonglong2* yr = (ulonglong2*)(y + (size_t)n * 64 + half*32);
        #pragma unroll
        for (int q = 0; q < 8; q++) yr[q] = make_ulonglong2(acc[2*q], acc[2*q+1]);
    }
}

// ---------------- column stats: 2 row-streams per thread, grid 512 ----------------
__global__ __launch_bounds__(256, 1)
void colstats_kernel(const float* __restrict__ y, float* __restrict__ ostats, int N) {
    int tid = threadIdx.x;
    int lane16 = tid & 15;
    int rg = tid >> 4;                 // 0..15
    float4 sA = make_float4(0.f,0.f,0.f,0.f), qA = sA;
    float4 sB = sA, qB = sA;
    int r = blockIdx.x * 32 + rg;
    int stride = gridDim.x * 32;
    #pragma unroll 2
    for (; r + 16 < N; r += stride) {
        float4 vA = ((const float4*)(y + (size_t)r*64))[lane16];
        float4 vB = ((const float4*)(y + (size_t)(r+16)*64))[lane16];
        sA.x += vA.x; sA.y += vA.y; sA.z += vA.z; sA.w += vA.w;
        qA.x = fmaf(vA.x, vA.x, qA.x); qA.y = fmaf(vA.y, vA.y, qA.y);
        qA.z = fmaf(vA.z, vA.z, qA.z); qA.w = fmaf(vA.w, vA.w, qA.w);
        sB.x += vB.x; sB.y += vB.y; sB.z += vB.z; sB.w += vB.w;
        qB.x = fmaf(vB.x, vB.x, qB.x); qB.y = fmaf(vB.y, vB.y, qB.y);
        qB.z = fmaf(vB.z, vB.z, qB.z); qB.w = fmaf(vB.w, vB.w, qB.w);
    }
    if (r < N) {
        float4 vA = ((const float4*)(y + (size_t)r*64))[lane16];
        sA.x += vA.x; sA.y += vA.y; sA.z += vA.z; sA.w += vA.w;
        qA.x = fmaf(vA.x, vA.x, qA.x); qA.y = fmaf(vA.y, vA.y, qA.y);
        qA.z = fmaf(vA.z, vA.z, qA.z); qA.w = fmaf(vA.w, vA.w, qA.w);
    }
    float4 s = make_float4(sA.x+sB.x, sA.y+sB.y, sA.z+sB.z, sA.w+sB.w);
    float4 q = make_float4(qA.x+qB.x, qA.y+qB.y, qA.z+qB.z, qA.w+qB.w);
    __shared__ float sm[256][8];
    sm[tid][0] = s.x; sm[tid][1] = s.y; sm[tid][2] = s.z; sm[tid][3] = s.w;
    sm[tid][4] = q.x; sm[tid][5] = q.y; sm[tid][6] = q.z; sm[tid][7] = q.w;
    __syncthreads();
    if (tid < 16) {
        float a0=0,a1=0,a2=0,a3=0,b0=0,b1=0,b2=0,b3=0;
        #pragma unroll
        for (int g = 0; g < 16; g++) {
            float* p = sm[tid + 16*g];
            a0 += p[0]; a1 += p[1]; a2 += p[2]; a3 += p[3];
            b0 += p[4]; b1 += p[5]; b2 += p[6]; b3 += p[7];
        }
        int c = tid*4;
        atomicAdd(&ostats[c],   a0); atomicAdd(&ostats[c+1], a1);
        atomicAdd(&ostats[c+2], a2); atomicAdd(&ostats[c+3], a3);
        atomicAdd(&ostats[64+c],   b0); atomicAdd(&ostats[64+c+1], b1);
        atomicAdd(&ostats[64+c+2], b2); atomicAdd(&ostats[64+c+3], b3);
    }
}

// ---------------- final projection ----------------
__global__ __launch_bounds__(256, 1)
void feats_kernel(const float* __restrict__ yin,
                  const float* __restrict__ Wmo, const float* __restrict__ bmo,
                  const float* __restrict__ Wko, const float* __restrict__ bko,
                  const float* __restrict__ pstats, int N) {
    __shared__ float Wos[32*32];
    __shared__ float bs[32];
    __shared__ float smean[64], srstd[64];
    for (int t = threadIdx.x; t < 1024; t += 256) {
        int d = t >> 5, j = t & 31;
        Wos[t] = (j < 16) ? Wmo[d*16 + j] : Wko[d*16 + (j - 16)];
    }
    if (threadIdx.x < 32) bs[threadIdx.x] = (threadIdx.x < 16) ? bmo[threadIdx.x] : bko[threadIdx.x - 16];
    if (threadIdx.x < 64) {
        float s = pstats[threadIdx.x], q = pstats[64 + threadIdx.x];
        float m = s / (float)N;
        float v = q / (float)N - m*m;
        smean[threadIdx.x] = m; srstd[threadIdx.x] = rsqrtf(v + EPSF);
    }
    __syncthreads();
    int n = blockIdx.x * 256 + threadIdx.x;
    if (n >= N) return;

    #pragma unroll
    for (int half = 0; half < 2; half++) {
        float xv[32];
        const float4* xr = (const float4*)(yin + (size_t)n * 64 + half*32);
        #pragma unroll
        for (int q = 0; q < 8; q++) {
            float4 v = xr[q]; int d = q*4; int c = half*32 + d;
            xv[d]   = fmaxf((v.x - smean[c])   * srstd[c],   0.f);
            xv[d+1] = fmaxf((v.y - smean[c+1]) * srstd[c+1], 0.f);
            xv[d+2] = fmaxf((v.z - smean[c+2]) * srstd[c+2], 0.f);
            xv[d+3] = fmaxf((v.w - smean[c+3]) * srstd[c+3], 0.f);
        }
        u64 acc[8];
        #pragma unroll
        for (int j = 0; j < 8; j++) acc[j] = 0ull;
        #pragma unroll 4
        for (int d = 0; d < 32; d++) {
            u64 xd = dup2(xv[d]);
            const u64* wr = (const u64*)(Wos + d*32 + half*16);
            #pragma unroll
            for (int q = 0; q < 8; q++) acc[q] = ffma2(xd, wr[q], acc[q]);
        }
        float* dst = half ? (g_kernf + (size_t)n * 16) : (g_maskf + (size_t)n * 16);
        #pragma unroll
        for (int q = 0; q < 8; q++) {
            float lo, hi; unpack2(acc[q], lo, hi);
            int j = q*2; int bj = half*16 + j;
            dst[j] = lo + bs[bj]; dst[j+1] = hi + bs[bj+1];
        }
    }
}

// ---------------- candidate gather + weight generator + aug-weight build ----------------
__global__ void cand_prep_kernel(const float* __restrict__ coords, const int* __restrict__ bidx,
                                 const float* __restrict__ Wwg, const float* __restrict__ bwg) {
    int i = blockIdx.x;
    int tid = threadIdx.x;
    __shared__ float ck[16];
    __shared__ float ws[337];
    __shared__ float cc[3];
    __shared__ int sidx;
    if (tid == 0) sidx = g_topk[i];
    __syncthreads();
    int idx = sidx;
    if (tid < 16) {
        float v = g_kernf[(size_t)idx*16 + tid];
        ck[tid] = v;
        g_feat[i*35 + tid] = v;
    } else if (tid < 32) {
        g_feat[i*35 + tid] = g_maskf[(size_t)idx*16 + (tid - 16)];
    } else if (tid < 35) {
        float c = coords[(size_t)idx*3 + (tid - 32)];
        g_feat[i*35 + tid] = c;
        g_ctr[i*3 + (tid - 32)] = c;
        cc[tid - 32] = c;
    } else if (tid == 35) {
        g_cb[i] = bidx[idx];
    }
    __syncthreads();
    if (tid < 337) {
        float w = bwg[tid];
        #pragma unroll
        for (int d = 0; d < 16; d++) w = fmaf(ck[d], Wwg[d*337 + tid], w);
        ws[tid] = w;
    }
    __syncthreads();
    int pair = i >> 1, hf = i & 1;
    float cx = cc[0], cy = cc[1], cz = cc[2];
    for (int t = tid; t < 320; t += blockDim.x) {
        int j = t / 20, d = t % 20;
        float v;
        if (d < 16)      v = ws[d*16 + j];
        else if (d < 19) v = ws[(16 + (d-16))*16 + j];
        else             v = ws[304 + j] - cx*ws[256 + j] - cy*ws[272 + j] - cz*ws[288 + j];
        g_w1aug2[pair*640 + j*40 + d*2 + hf] = v;
    }
    if (tid < 16) g_w2p[pair*32 + tid*2 + hf] = ws[320 + tid];
    if (tid == 16) g_b2p[pair*2 + hf] = ws[336];
}

// ---------------- dynamic mask head: FFMA2, 8 cand-pairs/block, 2 pts/thread ----------------
__global__ __launch_bounds__(128, 1)
void masks_kernel(const float* __restrict__ coords, float* __restrict__ out, int N) {
    __shared__ float w1t[8*16*40];
    __shared__ float w2s[8*16*2];
    __shared__ float b2s[8*2];
    int tid = threadIdx.x;
    int pbase = blockIdx.y * 8;

    {
        const float4* src = (const float4*)(g_w1aug2 + pbase*640);
        float4* dst = (float4*)w1t;
        for (int t = tid; t < 1280; t += 128) dst[t] = src[t];
        for (int t = tid; t < 256; t += 128) w2s[t] = g_w2p[pbase*32 + t];
        if (tid < 16) b2s[tid] = g_b2p[pbase*2 + tid];
    }
    __syncthreads();

    int n0 = blockIdx.x * 256 + tid;
    int n1 = n0 + 128;
    bool v0 = (n0 < N), v1 = (n1 < N);
    int s0 = v0 ? n0 : (N - 1);
    int s1 = v1 ? n1 : (N - 1);

    u64 x0[19], x1[19];
    {
        const float4* mr = (const float4*)(g_maskf + (size_t)s0 * 16);
        #pragma unroll
        for (int q = 0; q < 4; q++) {
            float4 m = mr[q];
            x0[q*4]   = dup2(m.x); x0[q*4+1] = dup2(m.y);
            x0[q*4+2] = dup2(m.z); x0[q*4+3] = dup2(m.w);
        }
        x0[16] = dup2(coords[(size_t)s0*3]);
        x0[17] = dup2(coords[(size_t)s0*3+1]);
        x0[18] = dup2(coords[(size_t)s0*3+2]);
    }
    {
        const float4* mr = (const float4*)(g_maskf + (size_t)s1 * 16);
        #pragma unroll
        for (int q = 0; q < 4; q++) {
            float4 m = mr[q];
            x1[q*4]   = dup2(m.x); x1[q*4+1] = dup2(m.y);
            x1[q*4+2] = dup2(m.z); x1[q*4+3] = dup2(m.w);
        }
        x1[16] = dup2(coords[(size_t)s1*3]);
        x1[17] = dup2(coords[(size_t)s1*3+1]);
        x1[18] = dup2(coords[(size_t)s1*3+2]);
    }

    size_t ostride = (size_t)N + IC;
    const u64* w2q = (const u64*)w2s;

    #pragma unroll
    for (int cp = 0; cp < 8; cp++) {
        u64 macc0 = 0ull, macc1 = 0ull;
        const float* wb = w1t + cp*640;
        #pragma unroll 4
        for (int j = 0; j < 16; j++) {
            const u64* wq = (const u64*)(wb + j*40);
            u64 h0 = wq[19];
            u64 h1 = h0;
            #pragma unroll
            for (int d = 0; d < 19; d++) {
                u64 wd = wq[d];
                h0 = ffma2(x0[d], wd, h0);
                h1 = ffma2(x1[d], wd, h1);
            }
            u64 w2v = w2q[cp*16 + j];
            float a, b;
            unpack2(h0, a, b);
            h0 = pack2(fmaxf(a, 0.f), fmaxf(b, 0.f));
            macc0 = ffma2(h0, w2v, macc0);
            unpack2(h1, a, b);
            h1 = pack2(fmaxf(a, 0.f), fmaxf(b, 0.f));
            macc1 = ffma2(h1, w2v, macc1);
        }
        float ba = b2s[cp*2], bb = b2s[cp*2+1];
        int ci0 = (pbase + cp) * 2;
        float* row0 = out + (size_t)ci0 * ostride;
        float* row1 = out + (size_t)(ci0 + 1) * ostride;
        float a, b;
        unpack2(macc0, a, b);
        if (v0) { row0[n0] = sigmoidf_(a + ba); row1[n0] = sigmoidf_(b + bb); }
        unpack2(macc1, a, b);
        if (v1) { row0[n1] = sigmoidf_(a + ba); row1[n1] = sigmoidf_(b + bb); }
    }
}

// ---------------- merge tower layer ----------------
__global__ __launch_bounds__(256, 1)
void merge_layer_kernel(const float* __restrict__ xin, float* __restrict__ yout,
                        const float* __restrict__ Wgl,
                        const float* __restrict__ pstats, float* __restrict__ ostats,
                        int layer0) {
    __shared__ float Ws[35*35];
    __shared__ float featS[IC*35];
    __shared__ float smean[35], srstd[35];
    __shared__ float ps[8][70];
    int tid = threadIdx.x;
    for (int t = tid; t < 1225; t += 256) Ws[t] = Wgl[t];
    if (layer0) {
        for (int t = tid; t < IC*35; t += 256) featS[t] = g_feat[t];
    } else if (tid < 35) {
        float s = pstats[tid], q = pstats[64 + tid];
        float m = s / (float)MR;
        float v = q / (float)MR - m*m;
        smean[tid] = m; srstd[tid] = rsqrtf(v + EPSF);
    }
    __syncthreads();

    int row = blockIdx.x * 256 + tid;
    float xv[35];
    if (layer0) {
        int i = row >> 7, j = row & 127;
        #pragma unroll
        for (int c = 0; c < 35; c++)
            xv[c] = fmaxf(fabsf(featS[i*35 + c] - featS[j*35 + c]), 1e-6f);
    } else {
        #pragma unroll
        for (int c = 0; c < 35; c++)
            xv[c] = fmaxf((xin[(size_t)row*35 + c] - smean[c]) * srstd[c], 0.f);
    }
    float acc[35];
    #pragma unroll
    for (int c = 0; c < 35; c++) acc[c] = 0.f;
    for (int c = 0; c < 35; c++) {
        float xa = xv[c];
        const float* wr = Ws + c*35;
        #pragma unroll
        for (int c2 = 0; c2 < 35; c2++) acc[c2] = fmaf(xa, wr[c2], acc[c2]);
    }
    #pragma unroll
    for (int c = 0; c < 35; c++) yout[(size_t)row*35 + c] = acc[c];

    int lane = tid & 31, warp = tid >> 5;
    for (int c = 0; c < 35; c++) {
        float s = acc[c]; float q = s * s;
        #pragma unroll
        for (int o = 16; o; o >>= 1) {
            s += __shfl_down_sync(0xffffffffu, s, o);
            q += __shfl_down_sync(0xffffffffu, q, o);
        }
        if (lane == 0) { ps[warp][c] = s; ps[warp][35 + c] = q; }
    }
    __syncthreads();
    if (tid < 70) {
        float t = 0.f;
        #pragma unroll
        for (int w = 0; w < 8; w++) t += ps[w][tid];
        int target = (tid < 35) ? tid : (64 + tid - 35);
        atomicAdd(&ostats[target], t);
    }
}

// ---------------- merge output ----------------
__global__ __launch_bounds__(256, 1)
void merge_out_kernel(const float* __restrict__ xin,
                      const float* __restrict__ Wgo, const float* __restrict__ bgo,
                      const float* __restrict__ pstats,
                      float* __restrict__ out, int N) {
    __shared__ float wout[35];
    __shared__ float smean[35], srstd[35];
    int tid = threadIdx.x;
    if (tid < 35) {
        wout[tid] = Wgo[tid];
        float s = pstats[tid], q = pstats[64 + tid];
        float m = s / (float)MR;
        float v = q / (float)MR - m*m;
        smean[tid] = m; srstd[tid] = rsqrtf(v + EPSF);
    }
    __syncthreads();
    int row = blockIdx.x * 256 + tid;
    int i = row >> 7, j = row & 127;
    float acc = bgo[0];
    #pragma unroll
    for (int c = 0; c < 35; c++) {
        float x = fmaxf((xin[(size_t)row*35 + c] - smean[c]) * srstd[c], 0.f);
        acc = fmaf(x, wout[c], acc);
    }
    float v = (g_cb[i] != g_cb[j]) ? 0.f : sigmoidf_(acc);
    out[(size_t)i * ((size_t)N + IC) + (size_t)N + j] = v;
}

// ---------------- launch ----------------
extern "C" void kernel_launch(void* const* d_in, const int* in_sizes, int n_in,
                              void* d_out, int out_size) {
    const float* output_feats = (const float*)d_in[0];
    const float* coords       = (const float*)d_in[1];
    const float* heat         = (const float*)d_in[2];
    const int*   batch_idxs   = (const int*)  d_in[3];
    const float* Wm           = (const float*)d_in[4];
    const float* Wm_out       = (const float*)d_in[5];
    const float* bm_out       = (const float*)d_in[6];
    const float* Wk           = (const float*)d_in[7];
    const float* Wk_out       = (const float*)d_in[8];
    const float* bk_out       = (const float*)d_in[9];
    const float* Wg           = (const float*)d_in[10];
    const float* Wg_out       = (const float*)d_in[11];
    const float* bg_out       = (const float*)d_in[12];
    const float* Wwg          = (const float*)d_in[13];
    const float* bwg          = (const float*)d_in[14];
    float* out = (float*)d_out;
    int N = in_sizes[2];

    // lazily-created side stream + events for NMS/tower overlap (fork-join capture)
    static cudaStream_t s_nms = nullptr;
    static cudaEvent_t ev_fork = nullptr, ev_join = nullptr;
    if (s_nms == nullptr) {
        cudaStreamCreateWithFlags(&s_nms, cudaStreamNonBlocking);
        cudaEventCreateWithFlags(&ev_fork, cudaEventDisableTiming);
        cudaEventCreateWithFlags(&ev_join, cudaEventDisableTiming);
    }

    float *yA, *yB, *mA, *mB, *stats, *mstats;
    cudaGetSymbolAddress((void**)&yA, g_yA);
    cudaGetSymbolAddress((void**)&yB, g_yB);
    cudaGetSymbolAddress((void**)&mA, g_mA);
    cudaGetSymbolAddress((void**)&mB, g_mB);
    cudaGetSymbolAddress((void**)&stats, g_stats);
    cudaGetSymbolAddress((void**)&mstats, g_mstats);

    init_kernel<<<1, 384>>>();

    // fork: NMS on side stream, towers on main stream
    cudaEventRecord(ev_fork, (cudaStream_t)0);
    cudaStreamWaitEvent(s_nms, ev_fork, 0);
    nms_kernel<<<NB, 1024, 0, s_nms>>>(heat, coords, batch_idxs, N);
    cudaEventRecord(ev_join, s_nms);

    int tg = (N + 255) / 256;
    tower_layer_kernel<<<tg, 256>>>(output_feats, yA, Wm,        Wk,        nullptr,     N, 1);
    colstats_kernel<<<512, 256>>>(yA, stats, N);
    tower_layer_kernel<<<tg, 256>>>(yA,           yB, Wm + 1024, Wk + 1024, stats,       N, 0);
    colstats_kernel<<<512, 256>>>(yB, stats + 128, N);
    tower_layer_kernel<<<tg, 256>>>(yB,           yA, Wm + 2048, Wk + 2048, stats + 128, N, 0);
    colstats_kernel<<<512, 256>>>(yA, stats + 256, N);
    feats_kernel<<<tg, 256>>>(yA, Wm_out, bm_out, Wk_out, bk_out, stats + 256, N);

    // join: cand_prep needs both NMS results and feats
    cudaStreamWaitEvent((cudaStream_t)0, ev_join, 0);
    cand_prep_kernel<<<IC, 352>>>(coords, batch_idxs, Wwg, bwg);

    dim3 mg((N + 255) / 256, 8);
    masks_kernel<<<mg, 128>>>(coords, out, N);

    merge_layer_kernel<<<64, 256>>>(nullptr, mA, Wg,        nullptr,      mstats,       1);
    merge_layer_kernel<<<64, 256>>>(mA,      mB, Wg + 1225, mstats,       mstats + 128, 0);
    merge_layer_kernel<<<64, 256>>>(mB,      mA, Wg + 2450, mstats + 128, mstats + 256, 0);
    merge_out_kernel<<<64, 256>>>(mA, Wg_out, bg_out, mstats + 256, out, N);
}

// round 9
// speedup vs baseline: 1.6024x; 1.0607x over previous
#include <cuda_runtime.h>
#include <math.h>
#include <stdint.h>

#define D32   32
#define OD    16
#define NB    4
#define KK    32
#define R2C   0.09f
#define EPSF  1e-5f
#define NMAX  100000
#define IC    128
#define MR    (IC*IC)

typedef unsigned long long u64;

// ---------------- device scratch (no allocations allowed) ----------------
__device__ float g_yA[NMAX*64];
__device__ float g_yB[NMAX*64];
__device__ float g_maskf[NMAX*OD];
__device__ float g_kernf[NMAX*OD];
__device__ float g_stats[3*128];
__device__ float g_mstats[3*128];
__device__ int   g_topk[IC];
__device__ float g_feat[IC*35];
__device__ float g_ctr[IC*3];
__device__ int   g_cb[IC];
__device__ float g_mA[MR*35];
__device__ float g_mB[MR*35];
__device__ float g_nmsbuf[NMAX];
__device__ float g_w1aug2[64*16*40];
__device__ float g_w2p[64*16*2];
__device__ float g_b2p[64*2];

__device__ __forceinline__ float sigmoidf_(float x) {
    return 1.0f / (1.0f + __expf(-x));
}
__device__ __forceinline__ u64 pack2(float lo, float hi) {
    u64 r; asm("mov.b64 %0, {%1, %2};" : "=l"(r) : "f"(lo), "f"(hi)); return r;
}
__device__ __forceinline__ u64 dup2(float x) { return pack2(x, x); }
__device__ __forceinline__ void unpack2(u64 v, float &lo, float &hi) {
    asm("mov.b64 {%0, %1}, %2;" : "=f"(lo), "=f"(hi) : "l"(v));
}
__device__ __forceinline__ u64 ffma2(u64 a, u64 b, u64 c) {
    u64 d; asm("fma.rn.f32x2 %0, %1, %2, %3;" : "=l"(d) : "l"(a), "l"(b), "l"(c)); return d;
}

// ---------------- greedy top-K NMS: heat register-resident ----------------
__global__ __launch_bounds__(1024, 1)
void nms_kernel(const float* __restrict__ heat, const float* __restrict__ coords,
                const int* __restrict__ bidx, int N) {
    int b = blockIdx.x;
    int lo = 0, hi = N;
    while (lo < hi) { int m = (lo + hi) >> 1; if (bidx[m] < b) lo = m + 1; else hi = m; }
    int s = lo; hi = N;
    while (lo < hi) { int m = (lo + hi) >> 1; if (bidx[m] <= b) lo = m + 1; else hi = m; }
    int e = lo, nb = e - s;

    __shared__ float rv[32]; __shared__ int ri[32];
    __shared__ float cc[3]; __shared__ int have;
    if (threadIdx.x == 0) have = 0;

    const float NEG = __int_as_float(0xff800000);
    int lane = threadIdx.x & 31, w = threadIdx.x >> 5;

    if (nb <= 32768) {
        float hv[32];
        #pragma unroll
        for (int ii = 0; ii < 32; ii++) {
            int t = ii*1024 + threadIdx.x;
            hv[ii] = (t < nb) ? heat[s + t] : NEG;
        }
        __syncthreads();
        for (int k = 0; k < KK; k++) {
            int h = have;
            float cx = 0.f, cy = 0.f, cz = 0.f;
            if (h) { cx = cc[0]; cy = cc[1]; cz = cc[2]; }
            float best = NEG; int bi = 0x7fffffff;
            #pragma unroll
            for (int ii = 0; ii < 32; ii++) {
                int t = ii*1024 + threadIdx.x;
                if (t >= nb) break;
                float v = hv[ii];
                if (h && v != NEG) {
                    int g = s + t;
                    float dx = coords[g*3]   - cx;
                    float dy = coords[g*3+1] - cy;
                    float dz = coords[g*3+2] - cz;
                    if (dx*dx + dy*dy + dz*dz < R2C) { v = NEG; hv[ii] = NEG; }
                }
                if (v > best) { best = v; bi = t; }
            }
            #pragma unroll
            for (int o = 16; o; o >>= 1) {
                float ov = __shfl_down_sync(0xffffffffu, best, o);
                int   oi = __shfl_down_sync(0xffffffffu, bi, o);
                if (ov > best || (ov == best && oi < bi)) { best = ov; bi = oi; }
            }
            if (lane == 0) { rv[w] = best; ri[w] = bi; }
            __syncthreads();
            if (w == 0) {
                best = rv[lane]; bi = ri[lane];
                #pragma unroll
                for (int o = 16; o; o >>= 1) {
                    float ov = __shfl_down_sync(0xffffffffu, best, o);
                    int   oi = __shfl_down_sync(0xffffffffu, bi, o);
                    if (ov > best || (ov == best && oi < bi)) { best = ov; bi = oi; }
                }
                if (lane == 0) {
                    int chosen = (best == NEG) ? 0 : (s + bi);
                    g_topk[b*KK + k] = chosen;
                    cc[0] = coords[chosen*3]; cc[1] = coords[chosen*3+1]; cc[2] = coords[chosen*3+2];
                    have = 1;
                }
            }
            __syncthreads();
        }
    } else {
        float* buf = g_nmsbuf + s;
        for (int t = threadIdx.x; t < nb; t += 1024) buf[t] = heat[s + t];
        __syncthreads();
        for (int k = 0; k < KK; k++) {
            int h = have;
            float cx = 0.f, cy = 0.f, cz = 0.f;
            if (h) { cx = cc[0]; cy = cc[1]; cz = cc[2]; }
            float best = NEG; int bi = 0x7fffffff;
            for (int t = threadIdx.x; t < nb; t += 1024) {
                float v = buf[t];
                if (h && v != NEG) {
                    int g = s + t;
                    float dx = coords[g*3]   - cx;
                    float dy = coords[g*3+1] - cy;
                    float dz = coords[g*3+2] - cz;
                    if (dx*dx + dy*dy + dz*dz < R2C) { v = NEG; buf[t] = NEG; }
                }
                if (v > best) { best = v; bi = t; }
            }
            #pragma unroll
            for (int o = 16; o; o >>= 1) {
                float ov = __shfl_down_sync(0xffffffffu, best, o);
                int   oi = __shfl_down_sync(0xffffffffu, bi, o);
                if (ov > best || (ov == best && oi < bi)) { best = ov; bi = oi; }
            }
            if (lane == 0) { rv[w] = best; ri[w] = bi; }
            __syncthreads();
            if (w == 0) {
                best = rv[lane]; bi = ri[lane];
                #pragma unroll
                for (int o = 16; o; o >>= 1) {
                    float ov = __shfl_down_sync(0xffffffffu, best, o);
                    int   oi = __shfl_down_sync(0xffffffffu, bi, o);
                    if (ov > best || (ov == best && oi < bi)) { best = ov; bi = oi; }
                }
                if (lane == 0) {
                    int chosen = (best == NEG) ? 0 : (s + bi);
                    g_topk[b*KK + k] = chosen;
                    cc[0] = coords[chosen*3]; cc[1] = coords[chosen*3+1]; cc[2] = coords[chosen*3+2];
                    have = 1;
                }
            }
            __syncthreads();
        }
    }
}

// ---------------- tower layer (pure GEMM, FFMA2); layer0 block0 zeroes ALL stat arrays ----------------
__global__ __launch_bounds__(256, 1)
void tower_layer_kernel(const float* __restrict__ x, float* __restrict__ y,
                        const float* __restrict__ Wml, const float* __restrict__ Wkl,
                        const float* __restrict__ pstats,
                        int N, int layer0) {
    if (layer0 && blockIdx.x == 0) {
        // zero all 768 stat floats with strided loop (blockDim=256!)
        for (int t = threadIdx.x; t < 768; t += 256) {
            if (t < 384) g_stats[t] = 0.f;
            else         g_mstats[t - 384] = 0.f;
        }
    }
    __shared__ float Ws[32*64];
    __shared__ float smean[64], srstd[64];
    for (int t = threadIdx.x; t < 2048; t += 256) {
        int d = t >> 6, j = t & 63;
        Ws[t] = (j < 32) ? Wml[d*32 + j] : Wkl[d*32 + (j - 32)];
    }
    if (!layer0 && threadIdx.x < 64) {
        float s = pstats[threadIdx.x], q = pstats[64 + threadIdx.x];
        float m = s / (float)N;
        float v = q / (float)N - m*m;
        smean[threadIdx.x] = m;
        srstd[threadIdx.x] = rsqrtf(v + EPSF);
    }
    __syncthreads();

    int n = blockIdx.x * 256 + threadIdx.x;
    if (n >= N) return;
    int instr = (layer0 ? 32 : 64);

    #pragma unroll
    for (int half = 0; half < 2; half++) {
        float xv[32];
        u64 acc[16];
        #pragma unroll
        for (int j = 0; j < 16; j++) acc[j] = 0ull;

        int coff = layer0 ? 0 : half * 32;
        const float4* xr = (const float4*)(x + (size_t)n * instr + coff);
        if (layer0) {
            #pragma unroll
            for (int q = 0; q < 8; q++) {
                float4 v = xr[q]; int d = q*4;
                xv[d] = v.x; xv[d+1] = v.y; xv[d+2] = v.z; xv[d+3] = v.w;
            }
        } else {
            #pragma unroll
            for (int q = 0; q < 8; q++) {
                float4 v = xr[q]; int d = q*4; int c = coff + d;
                xv[d]   = fmaxf((v.x - smean[c])   * srstd[c],   0.f);
                xv[d+1] = fmaxf((v.y - smean[c+1]) * srstd[c+1], 0.f);
                xv[d+2] = fmaxf((v.z - smean[c+2]) * srstd[c+2], 0.f);
                xv[d+3] = fmaxf((v.w - smean[c+3]) * srstd[c+3], 0.f);
            }
        }
        #pragma unroll 4
        for (int d = 0; d < 32; d++) {
            u64 xd = dup2(xv[d]);
            const u64* wr = (const u64*)(Ws + d*64 + half*32);
            #pragma unroll
            for (int q = 0; q < 16; q++) acc[q] = ffma2(xd, wr[q], acc[q]);
        }
        ulonglong2* yr = (ulonglong2*)(y + (size_t)n * 64 + half*32);
        #pragma unroll
        for (int q = 0; q < 8; q++) yr[q] = make_ulonglong2(acc[2*q], acc[2*q+1]);
    }
}

// ---------------- column stats: 4 row-streams per thread, grid 256 ----------------
#define CS_ACC(vv, ss, qq) \
    ss.x += vv.x; ss.y += vv.y; ss.z += vv.z; ss.w += vv.w; \
    qq.x = fmaf(vv.x, vv.x, qq.x); qq.y = fmaf(vv.y, vv.y, qq.y); \
    qq.z = fmaf(vv.z, vv.z, qq.z); qq.w = fmaf(vv.w, vv.w, qq.w);

__global__ __launch_bounds__(256, 1)
void colstats_kernel(const float* __restrict__ y, float* __restrict__ ostats, int N) {
    int tid = threadIdx.x;
    int lane16 = tid & 15;
    int rg = tid >> 4;                 // 0..15
    float4 z = make_float4(0.f,0.f,0.f,0.f);
    float4 s0 = z, q0 = z, s1 = z, q1 = z, s2 = z, q2 = z, s3 = z, q3 = z;
    int r = blockIdx.x * 64 + rg;
    int stride = gridDim.x * 64;
    for (; r + 48 < N; r += stride) {
        float4 v0 = ((const float4*)(y + (size_t)r*64))[lane16];
        float4 v1 = ((const float4*)(y + (size_t)(r+16)*64))[lane16];
        float4 v2 = ((const float4*)(y + (size_t)(r+32)*64))[lane16];
        float4 v3 = ((const float4*)(y + (size_t)(r+48)*64))[lane16];
        CS_ACC(v0, s0, q0) CS_ACC(v1, s1, q1) CS_ACC(v2, s2, q2) CS_ACC(v3, s3, q3)
    }
    if (r < N)      { float4 v = ((const float4*)(y + (size_t)r*64))[lane16];      CS_ACC(v, s0, q0) }
    if (r + 16 < N) { float4 v = ((const float4*)(y + (size_t)(r+16)*64))[lane16]; CS_ACC(v, s1, q1) }
    if (r + 32 < N) { float4 v = ((const float4*)(y + (size_t)(r+32)*64))[lane16]; CS_ACC(v, s2, q2) }
    float4 s = make_float4(s0.x+s1.x+s2.x+s3.x, s0.y+s1.y+s2.y+s3.y,
                           s0.z+s1.z+s2.z+s3.z, s0.w+s1.w+s2.w+s3.w);
    float4 q = make_float4(q0.x+q1.x+q2.x+q3.x, q0.y+q1.y+q2.y+q3.y,
                           q0.z+q1.z+q2.z+q3.z, q0.w+q1.w+q2.w+q3.w);
    __shared__ float sm[256][8];
    sm[tid][0] = s.x; sm[tid][1] = s.y; sm[tid][2] = s.z; sm[tid][3] = s.w;
    sm[tid][4] = q.x; sm[tid][5] = q.y; sm[tid][6] = q.z; sm[tid][7] = q.w;
    __syncthreads();
    if (tid < 16) {
        float a0=0,a1=0,a2=0,a3=0,b0=0,b1=0,b2=0,b3=0;
        #pragma unroll
        for (int g = 0; g < 16; g++) {
            float* p = sm[tid + 16*g];
            a0 += p[0]; a1 += p[1]; a2 += p[2]; a3 += p[3];
            b0 += p[4]; b1 += p[5]; b2 += p[6]; b3 += p[7];
        }
        int c = tid*4;
        atomicAdd(&ostats[c],   a0); atomicAdd(&ostats[c+1], a1);
        atomicAdd(&ostats[c+2], a2); atomicAdd(&ostats[c+3], a3);
        atomicAdd(&ostats[64+c],   b0); atomicAdd(&ostats[64+c+1], b1);
        atomicAdd(&ostats[64+c+2], b2); atomicAdd(&ostats[64+c+3], b3);
    }
}

// ---------------- final projection ----------------
__global__ __launch_bounds__(256, 1)
void feats_kernel(const float* __restrict__ yin,
                  const float* __restrict__ Wmo, const float* __restrict__ bmo,
                  const float* __restrict__ Wko, const float* __restrict__ bko,
                  const float* __restrict__ pstats, int N) {
    __shared__ float Wos[32*32];
    __shared__ float bs[32];
    __shared__ float smean[64], srstd[64];
    for (int t = threadIdx.x; t < 1024; t += 256) {
        int d = t >> 5, j = t & 31;
        Wos[t] = (j < 16) ? Wmo[d*16 + j] : Wko[d*16 + (j - 16)];
    }
    if (threadIdx.x < 32) bs[threadIdx.x] = (threadIdx.x < 16) ? bmo[threadIdx.x] : bko[threadIdx.x - 16];
    if (threadIdx.x < 64) {
        float s = pstats[threadIdx.x], q = pstats[64 + threadIdx.x];
        float m = s / (float)N;
        float v = q / (float)N - m*m;
        smean[threadIdx.x] = m; srstd[threadIdx.x] = rsqrtf(v + EPSF);
    }
    __syncthreads();
    int n = blockIdx.x * 256 + threadIdx.x;
    if (n >= N) return;

    #pragma unroll
    for (int half = 0; half < 2; half++) {
        float xv[32];
        const float4* xr = (const float4*)(yin + (size_t)n * 64 + half*32);
        #pragma unroll
        for (int q = 0; q < 8; q++) {
            float4 v = xr[q]; int d = q*4; int c = half*32 + d;
            xv[d]   = fmaxf((v.x - smean[c])   * srstd[c],   0.f);
            xv[d+1] = fmaxf((v.y - smean[c+1]) * srstd[c+1], 0.f);
            xv[d+2] = fmaxf((v.z - smean[c+2]) * srstd[c+2], 0.f);
            xv[d+3] = fmaxf((v.w - smean[c+3]) * srstd[c+3], 0.f);
        }
        u64 acc[8];
        #pragma unroll
        for (int j = 0; j < 8; j++) acc[j] = 0ull;
        #pragma unroll 4
        for (int d = 0; d < 32; d++) {
            u64 xd = dup2(xv[d]);
            const u64* wr = (const u64*)(Wos + d*32 + half*16);
            #pragma unroll
            for (int q = 0; q < 8; q++) acc[q] = ffma2(xd, wr[q], acc[q]);
        }
        float* dst = half ? (g_kernf + (size_t)n * 16) : (g_maskf + (size_t)n * 16);
        #pragma unroll
        for (int q = 0; q < 8; q++) {
            float lo, hi; unpack2(acc[q], lo, hi);
            int j = q*2; int bj = half*16 + j;
            dst[j] = lo + bs[bj]; dst[j+1] = hi + bs[bj+1];
        }
    }
}

// ---------------- candidate gather + weight generator + aug-weight build ----------------
__global__ void cand_prep_kernel(const float* __restrict__ coords, const int* __restrict__ bidx,
                                 const float* __restrict__ Wwg, const float* __restrict__ bwg) {
    int i = blockIdx.x;
    int tid = threadIdx.x;
    __shared__ float ck[16];
    __shared__ float ws[337];
    __shared__ float cc[3];
    __shared__ int sidx;
    if (tid == 0) sidx = g_topk[i];
    __syncthreads();
    int idx = sidx;
    if (tid < 16) {
        float v = g_kernf[(size_t)idx*16 + tid];
        ck[tid] = v;
        g_feat[i*35 + tid] = v;
    } else if (tid < 32) {
        g_feat[i*35 + tid] = g_maskf[(size_t)idx*16 + (tid - 16)];
    } else if (tid < 35) {
        float c = coords[(size_t)idx*3 + (tid - 32)];
        g_feat[i*35 + tid] = c;
        g_ctr[i*3 + (tid - 32)] = c;
        cc[tid - 32] = c;
    } else if (tid == 35) {
        g_cb[i] = bidx[idx];
    }
    __syncthreads();
    if (tid < 337) {
        float w = bwg[tid];
        #pragma unroll
        for (int d = 0; d < 16; d++) w = fmaf(ck[d], Wwg[d*337 + tid], w);
        ws[tid] = w;
    }
    __syncthreads();
    int pair = i >> 1, hf = i & 1;
    float cx = cc[0], cy = cc[1], cz = cc[2];
    for (int t = tid; t < 320; t += blockDim.x) {
        int j = t / 20, d = t % 20;
        float v;
        if (d < 16)      v = ws[d*16 + j];
        else if (d < 19) v = ws[(16 + (d-16))*16 + j];
        else             v = ws[304 + j] - cx*ws[256 + j] - cy*ws[272 + j] - cz*ws[288 + j];
        g_w1aug2[pair*640 + j*40 + d*2 + hf] = v;
    }
    if (tid < 16) g_w2p[pair*32 + tid*2 + hf] = ws[320 + tid];
    if (tid == 16) g_b2p[pair*2 + hf] = ws[336];
}

// ---------------- dynamic mask head: FFMA2, 8 cand-pairs/block, 2 pts/thread ----------------
__global__ __launch_bounds__(128, 1)
void masks_kernel(const float* __restrict__ coords, float* __restrict__ out, int N) {
    __shared__ float w1t[8*16*40];
    __shared__ float w2s[8*16*2];
    __shared__ float b2s[8*2];
    int tid = threadIdx.x;
    int pbase = blockIdx.y * 8;

    {
        const float4* src = (const float4*)(g_w1aug2 + pbase*640);
        float4* dst = (float4*)w1t;
        for (int t = tid; t < 1280; t += 128) dst[t] = src[t];
        for (int t = tid; t < 256; t += 128) w2s[t] = g_w2p[pbase*32 + t];
        if (tid < 16) b2s[tid] = g_b2p[pbase*2 + tid];
    }
    __syncthreads();

    int n0 = blockIdx.x * 256 + tid;
    int n1 = n0 + 128;
    bool v0 = (n0 < N), v1 = (n1 < N);
    int s0 = v0 ? n0 : (N - 1);
    int s1 = v1 ? n1 : (N - 1);

    u64 x0[19], x1[19];
    {
        const float4* mr = (const float4*)(g_maskf + (size_t)s0 * 16);
        #pragma unroll
        for (int q = 0; q < 4; q++) {
            float4 m = mr[q];
            x0[q*4]   = dup2(m.x); x0[q*4+1] = dup2(m.y);
            x0[q*4+2] = dup2(m.z); x0[q*4+3] = dup2(m.w);
        }
        x0[16] = dup2(coords[(size_t)s0*3]);
        x0[17] = dup2(coords[(size_t)s0*3+1]);
        x0[18] = dup2(coords[(size_t)s0*3+2]);
    }
    {
        const float4* mr = (const float4*)(g_maskf + (size_t)s1 * 16);
        #pragma unroll
        for (int q = 0; q < 4; q++) {
            float4 m = mr[q];
            x1[q*4]   = dup2(m.x); x1[q*4+1] = dup2(m.y);
            x1[q*4+2] = dup2(m.z); x1[q*4+3] = dup2(m.w);
        }
        x1[16] = dup2(coords[(size_t)s1*3]);
        x1[17] = dup2(coords[(size_t)s1*3+1]);
        x1[18] = dup2(coords[(size_t)s1*3+2]);
    }

    size_t ostride = (size_t)N + IC;
    const u64* w2q = (const u64*)w2s;

    #pragma unroll
    for (int cp = 0; cp < 8; cp++) {
        u64 macc0 = 0ull, macc1 = 0ull;
        const float* wb = w1t + cp*640;
        #pragma unroll 4
        for (int j = 0; j < 16; j++) {
            const u64* wq = (const u64*)(wb + j*40);
            u64 h0 = wq[19];
            u64 h1 = h0;
            #pragma unroll
            for (int d = 0; d < 19; d++) {
                u64 wd = wq[d];
                h0 = ffma2(x0[d], wd, h0);
                h1 = ffma2(x1[d], wd, h1);
            }
            u64 w2v = w2q[cp*16 + j];
            float a, b;
            unpack2(h0, a, b);
            h0 = pack2(fmaxf(a, 0.f), fmaxf(b, 0.f));
            macc0 = ffma2(h0, w2v, macc0);
            unpack2(h1, a, b);
            h1 = pack2(fmaxf(a, 0.f), fmaxf(b, 0.f));
            macc1 = ffma2(h1, w2v, macc1);
        }
        float ba = b2s[cp*2], bb = b2s[cp*2+1];
        int ci0 = (pbase + cp) * 2;
        float* row0 = out + (size_t)ci0 * ostride;
        float* row1 = out + (size_t)(ci0 + 1) * ostride;
        float a, b;
        unpack2(macc0, a, b);
        if (v0) { row0[n0] = sigmoidf_(a + ba); row1[n0] = sigmoidf_(b + bb); }
        unpack2(macc1, a, b);
        if (v1) { row0[n1] = sigmoidf_(a + ba); row1[n1] = sigmoidf_(b + bb); }
    }
}

// ---------------- merge tower layer ----------------
__global__ __launch_bounds__(256, 1)
void merge_layer_kernel(const float* __restrict__ xin, float* __restrict__ yout,
                        const float* __restrict__ Wgl,
                        const float* __restrict__ pstats, float* __restrict__ ostats,
                        int layer0) {
    __shared__ float Ws[35*35];
    __shared__ float featS[IC*35];
    __shared__ float smean[35], srstd[35];
    __shared__ float ps[8][70];
    int tid = threadIdx.x;
    for (int t = tid; t < 1225; t += 256) Ws[t] = Wgl[t];
    if (layer0) {
        for (int t = tid; t < IC*35; t += 256) featS[t] = g_feat[t];
    } else if (tid < 35) {
        float s = pstats[tid], q = pstats[64 + tid];
        float m = s / (float)MR;
        float v = q / (float)MR - m*m;
        smean[tid] = m; srstd[tid] = rsqrtf(v + EPSF);
    }
    __syncthreads();

    int row = blockIdx.x * 256 + tid;
    float xv[35];
    if (layer0) {
        int i = row >> 7, j = row & 127;
        #pragma unroll
        for (int c = 0; c < 35; c++)
            xv[c] = fmaxf(fabsf(featS[i*35 + c] - featS[j*35 + c]), 1e-6f);
    } else {
        #pragma unroll
        for (int c = 0; c < 35; c++)
            xv[c] = fmaxf((xin[(size_t)row*35 + c] - smean[c]) * srstd[c], 0.f);
    }
    float acc[35];
    #pragma unroll
    for (int c = 0; c < 35; c++) acc[c] = 0.f;
    for (int c = 0; c < 35; c++) {
        float xa = xv[c];
        const float* wr = Ws + c*35;
        #pragma unroll
        for (int c2 = 0; c2 < 35; c2++) acc[c2] = fmaf(xa, wr[c2], acc[c2]);
    }
    #pragma unroll
    for (int c = 0; c < 35; c++) yout[(size_t)row*35 + c] = acc[c];

    int lane = tid & 31, warp = tid >> 5;
    for (int c = 0; c < 35; c++) {
        float s = acc[c]; float q = s * s;
        #pragma unroll
        for (int o = 16; o; o >>= 1) {
            s += __shfl_down_sync(0xffffffffu, s, o);
            q += __shfl_down_sync(0xffffffffu, q, o);
        }
        if (lane == 0) { ps[warp][c] = s; ps[warp][35 + c] = q; }
    }
    __syncthreads();
    if (tid < 70) {
        float t = 0.f;
        #pragma unroll
        for (int w = 0; w < 8; w++) t += ps[w][tid];
        int target = (tid < 35) ? tid : (64 + tid - 35);
        atomicAdd(&ostats[target], t);
    }
}

// ---------------- merge output ----------------
__global__ __launch_bounds__(256, 1)
void merge_out_kernel(const float* __restrict__ xin,
                      const float* __restrict__ Wgo, const float* __restrict__ bgo,
                      const float* __restrict__ pstats,
                      float* __restrict__ out, int N) {
    __shared__ float wout[35];
    __shared__ float smean[35], srstd[35];
    int tid = threadIdx.x;
    if (tid < 35) {
        wout[tid] = Wgo[tid];
        float s = pstats[tid], q = pstats[64 + tid];
        float m = s / (float)MR;
        float v = q / (float)MR - m*m;
        smean[tid] = m; srstd[tid] = rsqrtf(v + EPSF);
    }
    __syncthreads();
    int row = blockIdx.x * 256 + tid;
    int i = row >> 7, j = row & 127;
    float acc = bgo[0];
    #pragma unroll
    for (int c = 0; c < 35; c++) {
        float x = fmaxf((xin[(size_t)row*35 + c] - smean[c]) * srstd[c], 0.f);
        acc = fmaf(x, wout[c], acc);
    }
    float v = (g_cb[i] != g_cb[j]) ? 0.f : sigmoidf_(acc);
    out[(size_t)i * ((size_t)N + IC) + (size_t)N + j] = v;
}

// ---------------- launch ----------------
extern "C" void kernel_launch(void* const* d_in, const int* in_sizes, int n_in,
                              void* d_out, int out_size) {
    const float* output_feats = (const float*)d_in[0];
    const float* coords       = (const float*)d_in[1];
    const float* heat         = (const float*)d_in[2];
    const int*   batch_idxs   = (const int*)  d_in[3];
    const float* Wm           = (const float*)d_in[4];
    const float* Wm_out       = (const float*)d_in[5];
    const float* bm_out       = (const float*)d_in[6];
    const float* Wk           = (const float*)d_in[7];
    const float* Wk_out       = (const float*)d_in[8];
    const float* bk_out       = (const float*)d_in[9];
    const float* Wg           = (const float*)d_in[10];
    const float* Wg_out       = (const float*)d_in[11];
    const float* bg_out       = (const float*)d_in[12];
    const float* Wwg          = (const float*)d_in[13];
    const float* bwg          = (const float*)d_in[14];
    float* out = (float*)d_out;
    int N = in_sizes[2];

    static cudaStream_t s_side = nullptr;
    static cudaEvent_t ev_fork = nullptr, ev_nms = nullptr, ev_cand = nullptr, ev_merge = nullptr;
    if (s_side == nullptr) {
        cudaStreamCreateWithFlags(&s_side, cudaStreamNonBlocking);
        cudaEventCreateWithFlags(&ev_fork, cudaEventDisableTiming);
        cudaEventCreateWithFlags(&ev_nms, cudaEventDisableTiming);
        cudaEventCreateWithFlags(&ev_cand, cudaEventDisableTiming);
        cudaEventCreateWithFlags(&ev_merge, cudaEventDisableTiming);
    }

    float *yA, *yB, *mA, *mB, *stats, *mstats;
    cudaGetSymbolAddress((void**)&yA, g_yA);
    cudaGetSymbolAddress((void**)&yB, g_yB);
    cudaGetSymbolAddress((void**)&mA, g_mA);
    cudaGetSymbolAddress((void**)&mB, g_mB);
    cudaGetSymbolAddress((void**)&stats, g_stats);
    cudaGetSymbolAddress((void**)&mstats, g_mstats);

    // fork: NMS on side stream, towers on main
    cudaEventRecord(ev_fork, (cudaStream_t)0);
    cudaStreamWaitEvent(s_side, ev_fork, 0);
    nms_kernel<<<NB, 1024, 0, s_side>>>(heat, coords, batch_idxs, N);
    cudaEventRecord(ev_nms, s_side);

    int tg = (N + 255) / 256;
    tower_layer_kernel<<<tg, 256>>>(output_feats, yA, Wm,        Wk,        nullptr,     N, 1);
    colstats_kernel<<<256, 256>>>(yA, stats, N);
    tower_layer_kernel<<<tg, 256>>>(yA,           yB, Wm + 1024, Wk + 1024, stats,       N, 0);
    colstats_kernel<<<256, 256>>>(yB, stats + 128, N);
    tower_layer_kernel<<<tg, 256>>>(yB,           yA, Wm + 2048, Wk + 2048, stats + 128, N, 0);
    colstats_kernel<<<256, 256>>>(yA, stats + 256, N);
    feats_kernel<<<tg, 256>>>(yA, Wm_out, bm_out, Wk_out, bk_out, stats + 256, N);

    // join NMS; cand_prep needs NMS + feats
    cudaStreamWaitEvent((cudaStream_t)0, ev_nms, 0);
    cand_prep_kernel<<<IC, 352>>>(coords, batch_idxs, Wwg, bwg);
    cudaEventRecord(ev_cand, (cudaStream_t)0);

    // merge chain on side stream, overlapped with masks on main
    cudaStreamWaitEvent(s_side, ev_cand, 0);
    merge_layer_kernel<<<64, 256, 0, s_side>>>(nullptr, mA, Wg,        nullptr,      mstats,       1);
    merge_layer_kernel<<<64, 256, 0, s_side>>>(mA,      mB, Wg + 1225, mstats,       mstats + 128, 0);
    merge_layer_kernel<<<64, 256, 0, s_side>>>(mB,      mA, Wg + 2450, mstats + 128, mstats + 256, 0);
    merge_out_kernel<<<64, 256, 0, s_side>>>(mA, Wg_out, bg_out, mstats + 256, out, N);
    cudaEventRecord(ev_merge, s_side);

    dim3 mg((N + 255) / 256, 8);
    masks_kernel<<<mg, 128>>>(coords, out, N);

    // ensure graph end depends on merge chain
    cudaStreamWaitEvent((cudaStream_t)0, ev_merge, 0);
}

// round 10
// speedup vs baseline: 1.6027x; 1.0001x over previous
#include <cuda_runtime.h>
#include <math.h>
#include <stdint.h>

#define D32   32
#define OD    16
#define NB    4
#define KK    32
#define R2C   0.09f
#define EPSF  1e-5f
#define NMAX  100000
#define IC    128
#define MR    (IC*IC)

typedef unsigned long long u64;

// ---------------- device scratch (no allocations allowed) ----------------
__device__ float g_yA[NMAX*64];
__device__ float g_yB[NMAX*64];
__device__ float g_maskf[NMAX*OD];
__device__ float g_kernf[NMAX*OD];
__device__ float g_stats[3*128];
__device__ float g_mstats[3*128];
__device__ int   g_topk[IC];
__device__ float g_feat[IC*35];
__device__ float g_ctr[IC*3];
__device__ int   g_cb[IC];
__device__ float g_mA[MR*35];
__device__ float g_mB[MR*35];
__device__ float g_nmsbuf[NMAX];
__device__ float g_w1aug2[64*16*40];
__device__ float g_w2p[64*16*2];
__device__ float g_b2p[64*2];

__device__ __forceinline__ float sigmoidf_(float x) {
    return 1.0f / (1.0f + __expf(-x));
}
__device__ __forceinline__ u64 pack2(float lo, float hi) {
    u64 r; asm("mov.b64 %0, {%1, %2};" : "=l"(r) : "f"(lo), "f"(hi)); return r;
}
__device__ __forceinline__ u64 dup2(float x) { return pack2(x, x); }
__device__ __forceinline__ void unpack2(u64 v, float &lo, float &hi) {
    asm("mov.b64 {%0, %1}, %2;" : "=f"(lo), "=f"(hi) : "l"(v));
}
__device__ __forceinline__ u64 ffma2(u64 a, u64 b, u64 c) {
    u64 d; asm("fma.rn.f32x2 %0, %1, %2, %3;" : "=l"(d) : "l"(a), "l"(b), "l"(c)); return d;
}

// ---------------- greedy top-K NMS: heat register-resident ----------------
__global__ __launch_bounds__(1024, 1)
void nms_kernel(const float* __restrict__ heat, const float* __restrict__ coords,
                const int* __restrict__ bidx, int N) {
    int b = blockIdx.x;
    int lo = 0, hi = N;
    while (lo < hi) { int m = (lo + hi) >> 1; if (bidx[m] < b) lo = m + 1; else hi = m; }
    int s = lo; hi = N;
    while (lo < hi) { int m = (lo + hi) >> 1; if (bidx[m] <= b) lo = m + 1; else hi = m; }
    int e = lo, nb = e - s;

    __shared__ float rv[32]; __shared__ int ri[32];
    __shared__ float cc[3]; __shared__ int have;
    if (threadIdx.x == 0) have = 0;

    const float NEG = __int_as_float(0xff800000);
    int lane = threadIdx.x & 31, w = threadIdx.x >> 5;

    if (nb <= 32768) {
        float hv[32];
        #pragma unroll
        for (int ii = 0; ii < 32; ii++) {
            int t = ii*1024 + threadIdx.x;
            hv[ii] = (t < nb) ? heat[s + t] : NEG;
        }
        __syncthreads();
        for (int k = 0; k < KK; k++) {
            int h = have;
            float cx = 0.f, cy = 0.f, cz = 0.f;
            if (h) { cx = cc[0]; cy = cc[1]; cz = cc[2]; }
            float best = NEG; int bi = 0x7fffffff;
            #pragma unroll
            for (int ii = 0; ii < 32; ii++) {
                int t = ii*1024 + threadIdx.x;
                if (t >= nb) break;
                float v = hv[ii];
                if (h && v != NEG) {
                    int g = s + t;
                    float dx = coords[g*3]   - cx;
                    float dy = coords[g*3+1] - cy;
                    float dz = coords[g*3+2] - cz;
                    if (dx*dx + dy*dy + dz*dz < R2C) { v = NEG; hv[ii] = NEG; }
                }
                if (v > best) { best = v; bi = t; }
            }
            #pragma unroll
            for (int o = 16; o; o >>= 1) {
                float ov = __shfl_down_sync(0xffffffffu, best, o);
                int   oi = __shfl_down_sync(0xffffffffu, bi, o);
                if (ov > best || (ov == best && oi < bi)) { best = ov; bi = oi; }
            }
            if (lane == 0) { rv[w] = best; ri[w] = bi; }
            __syncthreads();
            if (w == 0) {
                best = rv[lane]; bi = ri[lane];
                #pragma unroll
                for (int o = 16; o; o >>= 1) {
                    float ov = __shfl_down_sync(0xffffffffu, best, o);
                    int   oi = __shfl_down_sync(0xffffffffu, bi, o);
                    if (ov > best || (ov == best && oi < bi)) { best = ov; bi = oi; }
                }
                if (lane == 0) {
                    int chosen = (best == NEG) ? 0 : (s + bi);
                    g_topk[b*KK + k] = chosen;
                    cc[0] = coords[chosen*3]; cc[1] = coords[chosen*3+1]; cc[2] = coords[chosen*3+2];
                    have = 1;
                }
            }
            __syncthreads();
        }
    } else {
        float* buf = g_nmsbuf + s;
        for (int t = threadIdx.x; t < nb; t += 1024) buf[t] = heat[s + t];
        __syncthreads();
        for (int k = 0; k < KK; k++) {
            int h = have;
            float cx = 0.f, cy = 0.f, cz = 0.f;
            if (h) { cx = cc[0]; cy = cc[1]; cz = cc[2]; }
            float best = NEG; int bi = 0x7fffffff;
            for (int t = threadIdx.x; t < nb; t += 1024) {
                float v = buf[t];
                if (h && v != NEG) {
                    int g = s + t;
                    float dx = coords[g*3]   - cx;
                    float dy = coords[g*3+1] - cy;
                    float dz = coords[g*3+2] - cz;
                    if (dx*dx + dy*dy + dz*dz < R2C) { v = NEG; buf[t] = NEG; }
                }
                if (v > best) { best = v; bi = t; }
            }
            #pragma unroll
            for (int o = 16; o; o >>= 1) {
                float ov = __shfl_down_sync(0xffffffffu, best, o);
                int   oi = __shfl_down_sync(0xffffffffu, bi, o);
                if (ov > best || (ov == best && oi < bi)) { best = ov; bi = oi; }
            }
            if (lane == 0) { rv[w] = best; ri[w] = bi; }
            __syncthreads();
            if (w == 0) {
                best = rv[lane]; bi = ri[lane];
                #pragma unroll
                for (int o = 16; o; o >>= 1) {
                    float ov = __shfl_down_sync(0xffffffffu, best, o);
                    int   oi = __shfl_down_sync(0xffffffffu, bi, o);
                    if (ov > best || (ov == best && oi < bi)) { best = ov; bi = oi; }
                }
                if (lane == 0) {
                    int chosen = (best == NEG) ? 0 : (s + bi);
                    g_topk[b*KK + k] = chosen;
                    cc[0] = coords[chosen*3]; cc[1] = coords[chosen*3+1]; cc[2] = coords[chosen*3+2];
                    have = 1;
                }
            }
            __syncthreads();
        }
    }
}

// ---------------- tower layer (pure GEMM, FFMA2); layer0 block0 zeroes ALL stat arrays ----------------
// sequential halves (unroll 1) + occupancy bound: regs <= 128 -> 2 CTAs/SM
__global__ __launch_bounds__(256, 2)
void tower_layer_kernel(const float* __restrict__ x, float* __restrict__ y,
                        const float* __restrict__ Wml, const float* __restrict__ Wkl,
                        const float* __restrict__ pstats,
                        int N, int layer0) {
    if (layer0 && blockIdx.x == 0) {
        for (int t = threadIdx.x; t < 768; t += 256) {
            if (t < 384) g_stats[t] = 0.f;
            else         g_mstats[t - 384] = 0.f;
        }
    }
    __shared__ float Ws[32*64];
    __shared__ float smean[64], srstd[64];
    for (int t = threadIdx.x; t < 2048; t += 256) {
        int d = t >> 6, j = t & 63;
        Ws[t] = (j < 32) ? Wml[d*32 + j] : Wkl[d*32 + (j - 32)];
    }
    if (!layer0 && threadIdx.x < 64) {
        float s = pstats[threadIdx.x], q = pstats[64 + threadIdx.x];
        float m = s / (float)N;
        float v = q / (float)N - m*m;
        smean[threadIdx.x] = m;
        srstd[threadIdx.x] = rsqrtf(v + EPSF);
    }
    __syncthreads();

    int n = blockIdx.x * 256 + threadIdx.x;
    if (n >= N) return;
    int instr = (layer0 ? 32 : 64);

    #pragma unroll 1
    for (int half = 0; half < 2; half++) {
        float xv[32];
        u64 acc[16];
        #pragma unroll
        for (int j = 0; j < 16; j++) acc[j] = 0ull;

        int coff = layer0 ? 0 : half * 32;
        const float4* xr = (const float4*)(x + (size_t)n * instr + coff);
        if (layer0) {
            #pragma unroll
            for (int q = 0; q < 8; q++) {
                float4 v = xr[q]; int d = q*4;
                xv[d] = v.x; xv[d+1] = v.y; xv[d+2] = v.z; xv[d+3] = v.w;
            }
        } else {
            #pragma unroll
            for (int q = 0; q < 8; q++) {
                float4 v = xr[q]; int d = q*4; int c = coff + d;
                xv[d]   = fmaxf((v.x - smean[c])   * srstd[c],   0.f);
                xv[d+1] = fmaxf((v.y - smean[c+1]) * srstd[c+1], 0.f);
                xv[d+2] = fmaxf((v.z - smean[c+2]) * srstd[c+2], 0.f);
                xv[d+3] = fmaxf((v.w - smean[c+3]) * srstd[c+3], 0.f);
            }
        }
        #pragma unroll 4
        for (int d = 0; d < 32; d++) {
            u64 xd = dup2(xv[d]);
            const u64* wr = (const u64*)(Ws + d*64 + half*32);
            #pragma unroll
            for (int q = 0; q < 16; q++) acc[q] = ffma2(xd, wr[q], acc[q]);
        }
        ulonglong2* yr = (ulonglong2*)(y + (size_t)n * 64 + half*32);
        #pragma unroll
        for (int q = 0; q < 8; q++) yr[q] = make_ulonglong2(acc[2*q], acc[2*q+1]);
    }
}

// ---------------- column stats: 4 row-streams per thread, grid 256 ----------------
#define CS_ACC(vv, ss, qq) \
    ss.x += vv.x; ss.y += vv.y; ss.z += vv.z; ss.w += vv.w; \
    qq.x = fmaf(vv.x, vv.x, qq.x); qq.y = fmaf(vv.y, vv.y, qq.y); \
    qq.z = fmaf(vv.z, vv.z, qq.z); qq.w = fmaf(vv.w, vv.w, qq.w);

__global__ __launch_bounds__(256, 1)
void colstats_kernel(const float* __restrict__ y, float* __restrict__ ostats, int N) {
    int tid = threadIdx.x;
    int lane16 = tid & 15;
    int rg = tid >> 4;                 // 0..15
    float4 z = make_float4(0.f,0.f,0.f,0.f);
    float4 s0 = z, q0 = z, s1 = z, q1 = z, s2 = z, q2 = z, s3 = z, q3 = z;
    int r = blockIdx.x * 64 + rg;
    int stride = gridDim.x * 64;
    for (; r + 48 < N; r += stride) {
        float4 v0 = ((const float4*)(y + (size_t)r*64))[lane16];
        float4 v1 = ((const float4*)(y + (size_t)(r+16)*64))[lane16];
        float4 v2 = ((const float4*)(y + (size_t)(r+32)*64))[lane16];
        float4 v3 = ((const float4*)(y + (size_t)(r+48)*64))[lane16];
        CS_ACC(v0, s0, q0) CS_ACC(v1, s1, q1) CS_ACC(v2, s2, q2) CS_ACC(v3, s3, q3)
    }
    if (r < N)      { float4 v = ((const float4*)(y + (size_t)r*64))[lane16];      CS_ACC(v, s0, q0) }
    if (r + 16 < N) { float4 v = ((const float4*)(y + (size_t)(r+16)*64))[lane16]; CS_ACC(v, s1, q1) }
    if (r + 32 < N) { float4 v = ((const float4*)(y + (size_t)(r+32)*64))[lane16]; CS_ACC(v, s2, q2) }
    float4 s = make_float4(s0.x+s1.x+s2.x+s3.x, s0.y+s1.y+s2.y+s3.y,
                           s0.z+s1.z+s2.z+s3.z, s0.w+s1.w+s2.w+s3.w);
    float4 q = make_float4(q0.x+q1.x+q2.x+q3.x, q0.y+q1.y+q2.y+q3.y,
                           q0.z+q1.z+q2.z+q3.z, q0.w+q1.w+q2.w+q3.w);
    __shared__ float sm[256][8];
    sm[tid][0] = s.x; sm[tid][1] = s.y; sm[tid][2] = s.z; sm[tid][3] = s.w;
    sm[tid][4] = q.x; sm[tid][5] = q.y; sm[tid][6] = q.z; sm[tid][7] = q.w;
    __syncthreads();
    if (tid < 16) {
        float a0=0,a1=0,a2=0,a3=0,b0=0,b1=0,b2=0,b3=0;
        #pragma unroll
        for (int g = 0; g < 16; g++) {
            float* p = sm[tid + 16*g];
            a0 += p[0]; a1 += p[1]; a2 += p[2]; a3 += p[3];
            b0 += p[4]; b1 += p[5]; b2 += p[6]; b3 += p[7];
        }
        int c = tid*4;
        atomicAdd(&ostats[c],   a0); atomicAdd(&ostats[c+1], a1);
        atomicAdd(&ostats[c+2], a2); atomicAdd(&ostats[c+3], a3);
        atomicAdd(&ostats[64+c],   b0); atomicAdd(&ostats[64+c+1], b1);
        atomicAdd(&ostats[64+c+2], b2); atomicAdd(&ostats[64+c+3], b3);
    }
}

// ---------------- final projection ----------------
__global__ __launch_bounds__(256, 2)
void feats_kernel(const float* __restrict__ yin,
                  const float* __restrict__ Wmo, const float* __restrict__ bmo,
                  const float* __restrict__ Wko, const float* __restrict__ bko,
                  const float* __restrict__ pstats, int N) {
    __shared__ float Wos[32*32];
    __shared__ float bs[32];
    __shared__ float smean[64], srstd[64];
    for (int t = threadIdx.x; t < 1024; t += 256) {
        int d = t >> 5, j = t & 31;
        Wos[t] = (j < 16) ? Wmo[d*16 + j] : Wko[d*16 + (j - 16)];
    }
    if (threadIdx.x < 32) bs[threadIdx.x] = (threadIdx.x < 16) ? bmo[threadIdx.x] : bko[threadIdx.x - 16];
    if (threadIdx.x < 64) {
        float s = pstats[threadIdx.x], q = pstats[64 + threadIdx.x];
        float m = s / (float)N;
        float v = q / (float)N - m*m;
        smean[threadIdx.x] = m; srstd[threadIdx.x] = rsqrtf(v + EPSF);
    }
    __syncthreads();
    int n = blockIdx.x * 256 + threadIdx.x;
    if (n >= N) return;

    #pragma unroll 1
    for (int half = 0; half < 2; half++) {
        float xv[32];
        const float4* xr = (const float4*)(yin + (size_t)n * 64 + half*32);
        #pragma unroll
        for (int q = 0; q < 8; q++) {
            float4 v = xr[q]; int d = q*4; int c = half*32 + d;
            xv[d]   = fmaxf((v.x - smean[c])   * srstd[c],   0.f);
            xv[d+1] = fmaxf((v.y - smean[c+1]) * srstd[c+1], 0.f);
            xv[d+2] = fmaxf((v.z - smean[c+2]) * srstd[c+2], 0.f);
            xv[d+3] = fmaxf((v.w - smean[c+3]) * srstd[c+3], 0.f);
        }
        u64 acc[8];
        #pragma unroll
        for (int j = 0; j < 8; j++) acc[j] = 0ull;
        #pragma unroll 4
        for (int d = 0; d < 32; d++) {
            u64 xd = dup2(xv[d]);
            const u64* wr = (const u64*)(Wos + d*32 + half*16);
            #pragma unroll
            for (int q = 0; q < 8; q++) acc[q] = ffma2(xd, wr[q], acc[q]);
        }
        float* dst = half ? (g_kernf + (size_t)n * 16) : (g_maskf + (size_t)n * 16);
        #pragma unroll
        for (int q = 0; q < 8; q++) {
            float lo, hi; unpack2(acc[q], lo, hi);
            int j = q*2; int bj = half*16 + j;
            dst[j] = lo + bs[bj]; dst[j+1] = hi + bs[bj+1];
        }
    }
}

// ---------------- candidate gather + weight generator + aug-weight build ----------------
__global__ void cand_prep_kernel(const float* __restrict__ coords, const int* __restrict__ bidx,
                                 const float* __restrict__ Wwg, const float* __restrict__ bwg) {
    int i = blockIdx.x;
    int tid = threadIdx.x;
    __shared__ float ck[16];
    __shared__ float ws[337];
    __shared__ float cc[3];
    __shared__ int sidx;
    if (tid == 0) sidx = g_topk[i];
    __syncthreads();
    int idx = sidx;
    if (tid < 16) {
        float v = g_kernf[(size_t)idx*16 + tid];
        ck[tid] = v;
        g_feat[i*35 + tid] = v;
    } else if (tid < 32) {
        g_feat[i*35 + tid] = g_maskf[(size_t)idx*16 + (tid - 16)];
    } else if (tid < 35) {
        float c = coords[(size_t)idx*3 + (tid - 32)];
        g_feat[i*35 + tid] = c;
        g_ctr[i*3 + (tid - 32)] = c;
        cc[tid - 32] = c;
    } else if (tid == 35) {
        g_cb[i] = bidx[idx];
    }
    __syncthreads();
    if (tid < 337) {
        float w = bwg[tid];
        #pragma unroll
        for (int d = 0; d < 16; d++) w = fmaf(ck[d], Wwg[d*337 + tid], w);
        ws[tid] = w;
    }
    __syncthreads();
    int pair = i >> 1, hf = i & 1;
    float cx = cc[0], cy = cc[1], cz = cc[2];
    for (int t = tid; t < 320; t += blockDim.x) {
        int j = t / 20, d = t % 20;
        float v;
        if (d < 16)      v = ws[d*16 + j];
        else if (d < 19) v = ws[(16 + (d-16))*16 + j];
        else             v = ws[304 + j] - cx*ws[256 + j] - cy*ws[272 + j] - cz*ws[288 + j];
        g_w1aug2[pair*640 + j*40 + d*2 + hf] = v;
    }
    if (tid < 16) g_w2p[pair*32 + tid*2 + hf] = ws[320 + tid];
    if (tid == 16) g_b2p[pair*2 + hf] = ws[336];
}

// ---------------- dynamic mask head: FFMA2, 8 cand-pairs/block, 2 pts/thread ----------------
__global__ __launch_bounds__(128, 1)
void masks_kernel(const float* __restrict__ coords, float* __restrict__ out, int N) {
    __shared__ float w1t[8*16*40];
    __shared__ float w2s[8*16*2];
    __shared__ float b2s[8*2];
    int tid = threadIdx.x;
    int pbase = blockIdx.y * 8;

    {
        const float4* src = (const float4*)(g_w1aug2 + pbase*640);
        float4* dst = (float4*)w1t;
        for (int t = tid; t < 1280; t += 128) dst[t] = src[t];
        for (int t = tid; t < 256; t += 128) w2s[t] = g_w2p[pbase*32 + t];
        if (tid < 16) b2s[tid] = g_b2p[pbase*2 + tid];
    }
    __syncthreads();

    int n0 = blockIdx.x * 256 + tid;
    int n1 = n0 + 128;
    bool v0 = (n0 < N), v1 = (n1 < N);
    int s0 = v0 ? n0 : (N - 1);
    int s1 = v1 ? n1 : (N - 1);

    u64 x0[19], x1[19];
    {
        const float4* mr = (const float4*)(g_maskf + (size_t)s0 * 16);
        #pragma unroll
        for (int q = 0; q < 4; q++) {
            float4 m = mr[q];
            x0[q*4]   = dup2(m.x); x0[q*4+1] = dup2(m.y);
            x0[q*4+2] = dup2(m.z); x0[q*4+3] = dup2(m.w);
        }
        x0[16] = dup2(coords[(size_t)s0*3]);
        x0[17] = dup2(coords[(size_t)s0*3+1]);
        x0[18] = dup2(coords[(size_t)s0*3+2]);
    }
    {
        const float4* mr = (const float4*)(g_maskf + (size_t)s1 * 16);
        #pragma unroll
        for (int q = 0; q < 4; q++) {
            float4 m = mr[q];
            x1[q*4]   = dup2(m.x); x1[q*4+1] = dup2(m.y);
            x1[q*4+2] = dup2(m.z); x1[q*4+3] = dup2(m.w);
        }
        x1[16] = dup2(coords[(size_t)s1*3]);
        x1[17] = dup2(coords[(size_t)s1*3+1]);
        x1[18] = dup2(coords[(size_t)s1*3+2]);
    }

    size_t ostride = (size_t)N + IC;
    const u64* w2q = (const u64*)w2s;

    #pragma unroll
    for (int cp = 0; cp < 8; cp++) {
        u64 macc0 = 0ull, macc1 = 0ull;
        const float* wb = w1t + cp*640;
        #pragma unroll 4
        for (int j = 0; j < 16; j++) {
            const u64* wq = (const u64*)(wb + j*40);
            u64 h0 = wq[19];
            u64 h1 = h0;
            #pragma unroll
            for (int d = 0; d < 19; d++) {
                u64 wd = wq[d];
                h0 = ffma2(x0[d], wd, h0);
                h1 = ffma2(x1[d], wd, h1);
            }
            u64 w2v = w2q[cp*16 + j];
            float a, b;
            unpack2(h0, a, b);
            h0 = pack2(fmaxf(a, 0.f), fmaxf(b, 0.f));
            macc0 = ffma2(h0, w2v, macc0);
            unpack2(h1, a, b);
            h1 = pack2(fmaxf(a, 0.f), fmaxf(b, 0.f));
            macc1 = ffma2(h1, w2v, macc1);
        }
        float ba = b2s[cp*2], bb = b2s[cp*2+1];
        int ci0 = (pbase + cp) * 2;
        float* row0 = out + (size_t)ci0 * ostride;
        float* row1 = out + (size_t)(ci0 + 1) * ostride;
        float a, b;
        unpack2(macc0, a, b);
        if (v0) { row0[n0] = sigmoidf_(a + ba); row1[n0] = sigmoidf_(b + bb); }
        unpack2(macc1, a, b);
        if (v1) { row0[n1] = sigmoidf_(a + ba); row1[n1] = sigmoidf_(b + bb); }
    }
}

// ---------------- merge tower layer ----------------
__global__ __launch_bounds__(256, 1)
void merge_layer_kernel(const float* __restrict__ xin, float* __restrict__ yout,
                        const float* __restrict__ Wgl,
                        const float* __restrict__ pstats, float* __restrict__ ostats,
                        int layer0) {
    __shared__ float Ws[35*35];
    __shared__ float featS[IC*35];
    __shared__ float smean[35], srstd[35];
    __shared__ float ps[8][70];
    int tid = threadIdx.x;
    for (int t = tid; t < 1225; t += 256) Ws[t] = Wgl[t];
    if (layer0) {
        for (int t = tid; t < IC*35; t += 256) featS[t] = g_feat[t];
    } else if (tid < 35) {
        float s = pstats[tid], q = pstats[64 + tid];
        float m = s / (float)MR;
        float v = q / (float)MR - m*m;
        smean[tid] = m; srstd[tid] = rsqrtf(v + EPSF);
    }
    __syncthreads();

    int row = blockIdx.x * 256 + tid;
    float xv[35];
    if (layer0) {
        int i = row >> 7, j = row & 127;
        #pragma unroll
        for (int c = 0; c < 35; c++)
            xv[c] = fmaxf(fabsf(featS[i*35 + c] - featS[j*35 + c]), 1e-6f);
    } else {
        #pragma unroll
        for (int c = 0; c < 35; c++)
            xv[c] = fmaxf((xin[(size_t)row*35 + c] - smean[c]) * srstd[c], 0.f);
    }
    float acc[35];
    #pragma unroll
    for (int c = 0; c < 35; c++) acc[c] = 0.f;
    for (int c = 0; c < 35; c++) {
        float xa = xv[c];
        const float* wr = Ws + c*35;
        #pragma unroll
        for (int c2 = 0; c2 < 35; c2++) acc[c2] = fmaf(xa, wr[c2], acc[c2]);
    }
    #pragma unroll
    for (int c = 0; c < 35; c++) yout[(size_t)row*35 + c] = acc[c];

    int lane = tid & 31, warp = tid >> 5;
    for (int c = 0; c < 35; c++) {
        float s = acc[c]; float q = s * s;
        #pragma unroll
        for (int o = 16; o; o >>= 1) {
            s += __shfl_down_sync(0xffffffffu, s, o);
            q += __shfl_down_sync(0xffffffffu, q, o);
        }
        if (lane == 0) { ps[warp][c] = s; ps[warp][35 + c] = q; }
    }
    __syncthreads();
    if (tid < 70) {
        float t = 0.f;
        #pragma unroll
        for (int w = 0; w < 8; w++) t += ps[w][tid];
        int target = (tid < 35) ? tid : (64 + tid - 35);
        atomicAdd(&ostats[target], t);
    }
}

// ---------------- merge output ----------------
__global__ __launch_bounds__(256, 1)
void merge_out_kernel(const float* __restrict__ xin,
                      const float* __restrict__ Wgo, const float* __restrict__ bgo,
                      const float* __restrict__ pstats,
                      float* __restrict__ out, int N) {
    __shared__ float wout[35];
    __shared__ float smean[35], srstd[35];
    int tid = threadIdx.x;
    if (tid < 35) {
        wout[tid] = Wgo[tid];
        float s = pstats[tid], q = pstats[64 + tid];
        float m = s / (float)MR;
        float v = q / (float)MR - m*m;
        smean[tid] = m; srstd[tid] = rsqrtf(v + EPSF);
    }
    __syncthreads();
    int row = blockIdx.x * 256 + tid;
    int i = row >> 7, j = row & 127;
    float acc = bgo[0];
    #pragma unroll
    for (int c = 0; c < 35; c++) {
        float x = fmaxf((xin[(size_t)row*35 + c] - smean[c]) * srstd[c], 0.f);
        acc = fmaf(x, wout[c], acc);
    }
    float v = (g_cb[i] != g_cb[j]) ? 0.f : sigmoidf_(acc);
    out[(size_t)i * ((size_t)N + IC) + (size_t)N + j] = v;
}

// ---------------- launch ----------------
extern "C" void kernel_launch(void* const* d_in, const int* in_sizes, int n_in,
                              void* d_out, int out_size) {
    const float* output_feats = (const float*)d_in[0];
    const float* coords       = (const float*)d_in[1];
    const float* heat         = (const float*)d_in[2];
    const int*   batch_idxs   = (const int*)  d_in[3];
    const float* Wm           = (const float*)d_in[4];
    const float* Wm_out       = (const float*)d_in[5];
    const float* bm_out       = (const float*)d_in[6];
    const float* Wk           = (const float*)d_in[7];
    const float* Wk_out       = (const float*)d_in[8];
    const float* bk_out       = (const float*)d_in[9];
    const float* Wg           = (const float*)d_in[10];
    const float* Wg_out       = (const float*)d_in[11];
    const float* bg_out       = (const float*)d_in[12];
    const float* Wwg          = (const float*)d_in[13];
    const float* bwg          = (const float*)d_in[14];
    float* out = (float*)d_out;
    int N = in_sizes[2];

    static cudaStream_t s_side = nullptr;
    static cudaEvent_t ev_fork = nullptr, ev_nms = nullptr, ev_cand = nullptr, ev_merge = nullptr;
    if (s_side == nullptr) {
        cudaStreamCreateWithFlags(&s_side, cudaStreamNonBlocking);
        cudaEventCreateWithFlags(&ev_fork, cudaEventDisableTiming);
        cudaEventCreateWithFlags(&ev_nms, cudaEventDisableTiming);
        cudaEventCreateWithFlags(&ev_cand, cudaEventDisableTiming);
        cudaEventCreateWithFlags(&ev_merge, cudaEventDisableTiming);
    }

    float *yA, *yB, *mA, *mB, *stats, *mstats;
    cudaGetSymbolAddress((void**)&yA, g_yA);
    cudaGetSymbolAddress((void**)&yB, g_yB);
    cudaGetSymbolAddress((void**)&mA, g_mA);
    cudaGetSymbolAddress((void**)&mB, g_mB);
    cudaGetSymbolAddress((void**)&stats, g_stats);
    cudaGetSymbolAddress((void**)&mstats, g_mstats);

    // fork: NMS on side stream, towers on main
    cudaEventRecord(ev_fork, (cudaStream_t)0);
    cudaStreamWaitEvent(s_side, ev_fork, 0);
    nms_kernel<<<NB, 1024, 0, s_side>>>(heat, coords, batch_idxs, N);
    cudaEventRecord(ev_nms, s_side);

    int tg = (N + 255) / 256;
    tower_layer_kernel<<<tg, 256>>>(output_feats, yA, Wm,        Wk,        nullptr,     N, 1);
    colstats_kernel<<<256, 256>>>(yA, stats, N);
    tower_layer_kernel<<<tg, 256>>>(yA,           yB, Wm + 1024, Wk + 1024, stats,       N, 0);
    colstats_kernel<<<256, 256>>>(yB, stats + 128, N);
    tower_layer_kernel<<<tg, 256>>>(yB,           yA, Wm + 2048, Wk + 2048, stats + 128, N, 0);
    colstats_kernel<<<256, 256>>>(yA, stats + 256, N);
    feats_kernel<<<tg, 256>>>(yA, Wm_out, bm_out, Wk_out, bk_out, stats + 256, N);

    // join NMS; cand_prep needs NMS + feats
    cudaStreamWaitEvent((cudaStream_t)0, ev_nms, 0);
    cand_prep_kernel<<<IC, 352>>>(coords, batch_idxs, Wwg, bwg);
    cudaEventRecord(ev_cand, (cudaStream_t)0);

    // merge chain on side stream, overlapped with masks on main
    cudaStreamWaitEvent(s_side, ev_cand, 0);
    merge_layer_kernel<<<64, 256, 0, s_side>>>(nullptr, mA, Wg,        nullptr,      mstats,       1);
    merge_layer_kernel<<<64, 256, 0, s_side>>>(mA,      mB, Wg + 1225, mstats,       mstats + 128, 0);
    merge_layer_kernel<<<64, 256, 0, s_side>>>(mB,      mA, Wg + 2450, mstats + 128, mstats + 256, 0);
    merge_out_kernel<<<64, 256, 0, s_side>>>(mA, Wg_out, bg_out, mstats + 256, out, N);
    cudaEventRecord(ev_merge, s_side);

    dim3 mg((N + 255) / 256, 8);
    masks_kernel<<<mg, 128>>>(coords, out, N);

    // ensure graph end depends on merge chain
    cudaStreamWaitEvent((cudaStream_t)0, ev_merge, 0);
}

// round 11
// speedup vs baseline: 1.6101x; 1.0046x over previous
#include <cuda_runtime.h>
#include <math.h>
#include <stdint.h>

#define D32   32
#define OD    16
#define NB    4
#define KK    32
#define R2C   0.09f
#define EPSF  1e-5f
#define NMAX  100000
#define IC    128
#define MR    (IC*IC)

typedef unsigned long long u64;

// ---------------- device scratch (no allocations allowed) ----------------
__device__ float g_yA[NMAX*64];
__device__ float g_yB[NMAX*64];
__device__ float g_maskf[NMAX*OD];
__device__ float g_kernf[NMAX*OD];
__device__ float g_stats[3*128];
__device__ float g_mstats[3*128];
__device__ int   g_topk[IC];
__device__ float g_feat[IC*35];
__device__ float g_ctr[IC*3];
__device__ int   g_cb[IC];
__device__ float g_mA[MR*35];
__device__ float g_mB[MR*35];
__device__ float g_nmsbuf[NMAX];
__device__ float g_w1aug2[64*16*40];
__device__ float g_w2p[64*16*2];
__device__ float g_b2p[64*2];

__device__ __forceinline__ float sigmoidf_(float x) {
    return 1.0f / (1.0f + __expf(-x));
}
__device__ __forceinline__ u64 pack2(float lo, float hi) {
    u64 r; asm("mov.b64 %0, {%1, %2};" : "=l"(r) : "f"(lo), "f"(hi)); return r;
}
__device__ __forceinline__ u64 dup2(float x) { return pack2(x, x); }
__device__ __forceinline__ void unpack2(u64 v, float &lo, float &hi) {
    asm("mov.b64 {%0, %1}, %2;" : "=f"(lo), "=f"(hi) : "l"(v));
}
__device__ __forceinline__ u64 ffma2(u64 a, u64 b, u64 c) {
    u64 d; asm("fma.rn.f32x2 %0, %1, %2, %3;" : "=l"(d) : "l"(a), "l"(b), "l"(c)); return d;
}

// ---------------- greedy top-K NMS: heat register-resident ----------------
__global__ __launch_bounds__(1024, 1)
void nms_kernel(const float* __restrict__ heat, const float* __restrict__ coords,
                const int* __restrict__ bidx, int N) {
    int b = blockIdx.x;
    int lo = 0, hi = N;
    while (lo < hi) { int m = (lo + hi) >> 1; if (bidx[m] < b) lo = m + 1; else hi = m; }
    int s = lo; hi = N;
    while (lo < hi) { int m = (lo + hi) >> 1; if (bidx[m] <= b) lo = m + 1; else hi = m; }
    int e = lo, nb = e - s;

    __shared__ float rv[32]; __shared__ int ri[32];
    __shared__ float cc[3]; __shared__ int have;
    if (threadIdx.x == 0) have = 0;

    const float NEG = __int_as_float(0xff800000);
    int lane = threadIdx.x & 31, w = threadIdx.x >> 5;

    if (nb <= 32768) {
        float hv[32];
        #pragma unroll
        for (int ii = 0; ii < 32; ii++) {
            int t = ii*1024 + threadIdx.x;
            hv[ii] = (t < nb) ? heat[s + t] : NEG;
        }
        __syncthreads();
        for (int k = 0; k < KK; k++) {
            int h = have;
            float cx = 0.f, cy = 0.f, cz = 0.f;
            if (h) { cx = cc[0]; cy = cc[1]; cz = cc[2]; }
            float best = NEG; int bi = 0x7fffffff;
            #pragma unroll
            for (int ii = 0; ii < 32; ii++) {
                int t = ii*1024 + threadIdx.x;
                if (t >= nb) break;
                float v = hv[ii];
                if (h && v != NEG) {
                    int g = s + t;
                    float dx = coords[g*3]   - cx;
                    float dy = coords[g*3+1] - cy;
                    float dz = coords[g*3+2] - cz;
                    if (dx*dx + dy*dy + dz*dz < R2C) { v = NEG; hv[ii] = NEG; }
                }
                if (v > best) { best = v; bi = t; }
            }
            #pragma unroll
            for (int o = 16; o; o >>= 1) {
                float ov = __shfl_down_sync(0xffffffffu, best, o);
                int   oi = __shfl_down_sync(0xffffffffu, bi, o);
                if (ov > best || (ov == best && oi < bi)) { best = ov; bi = oi; }
            }
            if (lane == 0) { rv[w] = best; ri[w] = bi; }
            __syncthreads();
            if (w == 0) {
                best = rv[lane]; bi = ri[lane];
                #pragma unroll
                for (int o = 16; o; o >>= 1) {
                    float ov = __shfl_down_sync(0xffffffffu, best, o);
                    int   oi = __shfl_down_sync(0xffffffffu, bi, o);
                    if (ov > best || (ov == best && oi < bi)) { best = ov; bi = oi; }
                }
                if (lane == 0) {
                    int chosen = (best == NEG) ? 0 : (s + bi);
                    g_topk[b*KK + k] = chosen;
                    cc[0] = coords[chosen*3]; cc[1] = coords[chosen*3+1]; cc[2] = coords[chosen*3+2];
                    have = 1;
                }
            }
            __syncthreads();
        }
    } else {
        float* buf = g_nmsbuf + s;
        for (int t = threadIdx.x; t < nb; t += 1024) buf[t] = heat[s + t];
        __syncthreads();
        for (int k = 0; k < KK; k++) {
            int h = have;
            float cx = 0.f, cy = 0.f, cz = 0.f;
            if (h) { cx = cc[0]; cy = cc[1]; cz = cc[2]; }
            float best = NEG; int bi = 0x7fffffff;
            for (int t = threadIdx.x; t < nb; t += 1024) {
                float v = buf[t];
                if (h && v != NEG) {
                    int g = s + t;
                    float dx = coords[g*3]   - cx;
                    float dy = coords[g*3+1] - cy;
                    float dz = coords[g*3+2] - cz;
                    if (dx*dx + dy*dy + dz*dz < R2C) { v = NEG; buf[t] = NEG; }
                }
                if (v > best) { best = v; bi = t; }
            }
            #pragma unroll
            for (int o = 16; o; o >>= 1) {
                float ov = __shfl_down_sync(0xffffffffu, best, o);
                int   oi = __shfl_down_sync(0xffffffffu, bi, o);
                if (ov > best || (ov == best && oi < bi)) { best = ov; bi = oi; }
            }
            if (lane == 0) { rv[w] = best; ri[w] = bi; }
            __syncthreads();
            if (w == 0) {
                best = rv[lane]; bi = ri[lane];
                #pragma unroll
                for (int o = 16; o; o >>= 1) {
                    float ov = __shfl_down_sync(0xffffffffu, best, o);
                    int   oi = __shfl_down_sync(0xffffffffu, bi, o);
                    if (ov > best || (ov == best && oi < bi)) { best = ov; bi = oi; }
                }
                if (lane == 0) {
                    int chosen = (best == NEG) ? 0 : (s + bi);
                    g_topk[b*KK + k] = chosen;
                    cc[0] = coords[chosen*3]; cc[1] = coords[chosen*3+1]; cc[2] = coords[chosen*3+2];
                    have = 1;
                }
            }
            __syncthreads();
        }
    }
}

// ---------------- tower layer (pure GEMM, FFMA2, LDS.128 weights) ----------------
__global__ __launch_bounds__(256, 2)
void tower_layer_kernel(const float* __restrict__ x, float* __restrict__ y,
                        const float* __restrict__ Wml, const float* __restrict__ Wkl,
                        const float* __restrict__ pstats,
                        int N, int layer0) {
    if (layer0 && blockIdx.x == 0) {
        for (int t = threadIdx.x; t < 768; t += 256) {
            if (t < 384) g_stats[t] = 0.f;
            else         g_mstats[t - 384] = 0.f;
        }
    }
    __shared__ float Ws[32*64];
    __shared__ float smean[64], srstd[64];
    for (int t = threadIdx.x; t < 2048; t += 256) {
        int d = t >> 6, j = t & 63;
        Ws[t] = (j < 32) ? Wml[d*32 + j] : Wkl[d*32 + (j - 32)];
    }
    if (!layer0 && threadIdx.x < 64) {
        float s = pstats[threadIdx.x], q = pstats[64 + threadIdx.x];
        float m = s / (float)N;
        float v = q / (float)N - m*m;
        smean[threadIdx.x] = m;
        srstd[threadIdx.x] = rsqrtf(v + EPSF);
    }
    __syncthreads();

    int n = blockIdx.x * 256 + threadIdx.x;
    if (n >= N) return;
    int instr = (layer0 ? 32 : 64);

    #pragma unroll 1
    for (int half = 0; half < 2; half++) {
        float xv[32];
        u64 acc[16];
        #pragma unroll
        for (int j = 0; j < 16; j++) acc[j] = 0ull;

        int coff = layer0 ? 0 : half * 32;
        const float4* xr = (const float4*)(x + (size_t)n * instr + coff);
        if (layer0) {
            #pragma unroll
            for (int q = 0; q < 8; q++) {
                float4 v = xr[q]; int d = q*4;
                xv[d] = v.x; xv[d+1] = v.y; xv[d+2] = v.z; xv[d+3] = v.w;
            }
        } else {
            #pragma unroll
            for (int q = 0; q < 8; q++) {
                float4 v = xr[q]; int d = q*4; int c = coff + d;
                xv[d]   = fmaxf((v.x - smean[c])   * srstd[c],   0.f);
                xv[d+1] = fmaxf((v.y - smean[c+1]) * srstd[c+1], 0.f);
                xv[d+2] = fmaxf((v.z - smean[c+2]) * srstd[c+2], 0.f);
                xv[d+3] = fmaxf((v.w - smean[c+3]) * srstd[c+3], 0.f);
            }
        }
        #pragma unroll 4
        for (int d = 0; d < 32; d++) {
            u64 xd = dup2(xv[d]);
            const ulonglong2* wr = (const ulonglong2*)(Ws + d*64 + half*32);
            #pragma unroll
            for (int q = 0; q < 8; q++) {
                ulonglong2 w = wr[q];           // one LDS.128 = 2 col-pairs
                acc[2*q]   = ffma2(xd, w.x, acc[2*q]);
                acc[2*q+1] = ffma2(xd, w.y, acc[2*q+1]);
            }
        }
        ulonglong2* yr = (ulonglong2*)(y + (size_t)n * 64 + half*32);
        #pragma unroll
        for (int q = 0; q < 8; q++) yr[q] = make_ulonglong2(acc[2*q], acc[2*q+1]);
    }
}

// ---------------- column stats: 4 row-streams per thread, grid 256 ----------------
#define CS_ACC(vv, ss, qq) \
    ss.x += vv.x; ss.y += vv.y; ss.z += vv.z; ss.w += vv.w; \
    qq.x = fmaf(vv.x, vv.x, qq.x); qq.y = fmaf(vv.y, vv.y, qq.y); \
    qq.z = fmaf(vv.z, vv.z, qq.z); qq.w = fmaf(vv.w, vv.w, qq.w);

__global__ __launch_bounds__(256, 1)
void colstats_kernel(const float* __restrict__ y, float* __restrict__ ostats, int N) {
    int tid = threadIdx.x;
    int lane16 = tid & 15;
    int rg = tid >> 4;                 // 0..15
    float4 z = make_float4(0.f,0.f,0.f,0.f);
    float4 s0 = z, q0 = z, s1 = z, q1 = z, s2 = z, q2 = z, s3 = z, q3 = z;
    int r = blockIdx.x * 64 + rg;
    int stride = gridDim.x * 64;
    for (; r + 48 < N; r += stride) {
        float4 v0 = ((const float4*)(y + (size_t)r*64))[lane16];
        float4 v1 = ((const float4*)(y + (size_t)(r+16)*64))[lane16];
        float4 v2 = ((const float4*)(y + (size_t)(r+32)*64))[lane16];
        float4 v3 = ((const float4*)(y + (size_t)(r+48)*64))[lane16];
        CS_ACC(v0, s0, q0) CS_ACC(v1, s1, q1) CS_ACC(v2, s2, q2) CS_ACC(v3, s3, q3)
    }
    if (r < N)      { float4 v = ((const float4*)(y + (size_t)r*64))[lane16];      CS_ACC(v, s0, q0) }
    if (r + 16 < N) { float4 v = ((const float4*)(y + (size_t)(r+16)*64))[lane16]; CS_ACC(v, s1, q1) }
    if (r + 32 < N) { float4 v = ((const float4*)(y + (size_t)(r+32)*64))[lane16]; CS_ACC(v, s2, q2) }
    float4 s = make_float4(s0.x+s1.x+s2.x+s3.x, s0.y+s1.y+s2.y+s3.y,
                           s0.z+s1.z+s2.z+s3.z, s0.w+s1.w+s2.w+s3.w);
    float4 q = make_float4(q0.x+q1.x+q2.x+q3.x, q0.y+q1.y+q2.y+q3.y,
                           q0.z+q1.z+q2.z+q3.z, q0.w+q1.w+q2.w+q3.w);
    __shared__ float sm[256][8];
    sm[tid][0] = s.x; sm[tid][1] = s.y; sm[tid][2] = s.z; sm[tid][3] = s.w;
    sm[tid][4] = q.x; sm[tid][5] = q.y; sm[tid][6] = q.z; sm[tid][7] = q.w;
    __syncthreads();
    if (tid < 16) {
        float a0=0,a1=0,a2=0,a3=0,b0=0,b1=0,b2=0,b3=0;
        #pragma unroll
        for (int g = 0; g < 16; g++) {
            float* p = sm[tid + 16*g];
            a0 += p[0]; a1 += p[1]; a2 += p[2]; a3 += p[3];
            b0 += p[4]; b1 += p[5]; b2 += p[6]; b3 += p[7];
        }
        int c = tid*4;
        atomicAdd(&ostats[c],   a0); atomicAdd(&ostats[c+1], a1);
        atomicAdd(&ostats[c+2], a2); atomicAdd(&ostats[c+3], a3);
        atomicAdd(&ostats[64+c],   b0); atomicAdd(&ostats[64+c+1], b1);
        atomicAdd(&ostats[64+c+2], b2); atomicAdd(&ostats[64+c+3], b3);
    }
}

// ---------------- final projection (LDS.128 weights) ----------------
__global__ __launch_bounds__(256, 2)
void feats_kernel(const float* __restrict__ yin,
                  const float* __restrict__ Wmo, const float* __restrict__ bmo,
                  const float* __restrict__ Wko, const float* __restrict__ bko,
                  const float* __restrict__ pstats, int N) {
    __shared__ float Wos[32*32];
    __shared__ float bs[32];
    __shared__ float smean[64], srstd[64];
    for (int t = threadIdx.x; t < 1024; t += 256) {
        int d = t >> 5, j = t & 31;
        Wos[t] = (j < 16) ? Wmo[d*16 + j] : Wko[d*16 + (j - 16)];
    }
    if (threadIdx.x < 32) bs[threadIdx.x] = (threadIdx.x < 16) ? bmo[threadIdx.x] : bko[threadIdx.x - 16];
    if (threadIdx.x < 64) {
        float s = pstats[threadIdx.x], q = pstats[64 + threadIdx.x];
        float m = s / (float)N;
        float v = q / (float)N - m*m;
        smean[threadIdx.x] = m; srstd[threadIdx.x] = rsqrtf(v + EPSF);
    }
    __syncthreads();
    int n = blockIdx.x * 256 + threadIdx.x;
    if (n >= N) return;

    #pragma unroll 1
    for (int half = 0; half < 2; half++) {
        float xv[32];
        const float4* xr = (const float4*)(yin + (size_t)n * 64 + half*32);
        #pragma unroll
        for (int q = 0; q < 8; q++) {
            float4 v = xr[q]; int d = q*4; int c = half*32 + d;
            xv[d]   = fmaxf((v.x - smean[c])   * srstd[c],   0.f);
            xv[d+1] = fmaxf((v.y - smean[c+1]) * srstd[c+1], 0.f);
            xv[d+2] = fmaxf((v.z - smean[c+2]) * srstd[c+2], 0.f);
            xv[d+3] = fmaxf((v.w - smean[c+3]) * srstd[c+3], 0.f);
        }
        u64 acc[8];
        #pragma unroll
        for (int j = 0; j < 8; j++) acc[j] = 0ull;
        #pragma unroll 4
        for (int d = 0; d < 32; d++) {
            u64 xd = dup2(xv[d]);
            const ulonglong2* wr = (const ulonglong2*)(Wos + d*32 + half*16);
            #pragma unroll
            for (int q = 0; q < 4; q++) {
                ulonglong2 w = wr[q];
                acc[2*q]   = ffma2(xd, w.x, acc[2*q]);
                acc[2*q+1] = ffma2(xd, w.y, acc[2*q+1]);
            }
        }
        float* dst = half ? (g_kernf + (size_t)n * 16) : (g_maskf + (size_t)n * 16);
        #pragma unroll
        for (int q = 0; q < 8; q++) {
            float lo, hi; unpack2(acc[q], lo, hi);
            int j = q*2; int bj = half*16 + j;
            dst[j] = lo + bs[bj]; dst[j+1] = hi + bs[bj+1];
        }
    }
}

// ---------------- candidate gather + weight generator + aug-weight build ----------------
__global__ void cand_prep_kernel(const float* __restrict__ coords, const int* __restrict__ bidx,
                                 const float* __restrict__ Wwg, const float* __restrict__ bwg) {
    int i = blockIdx.x;
    int tid = threadIdx.x;
    __shared__ float ck[16];
    __shared__ float ws[337];
    __shared__ float cc[3];
    __shared__ int sidx;
    if (tid == 0) sidx = g_topk[i];
    __syncthreads();
    int idx = sidx;
    if (tid < 16) {
        float v = g_kernf[(size_t)idx*16 + tid];
        ck[tid] = v;
        g_feat[i*35 + tid] = v;
    } else if (tid < 32) {
        g_feat[i*35 + tid] = g_maskf[(size_t)idx*16 + (tid - 16)];
    } else if (tid < 35) {
        float c = coords[(size_t)idx*3 + (tid - 32)];
        g_feat[i*35 + tid] = c;
        g_ctr[i*3 + (tid - 32)] = c;
        cc[tid - 32] = c;
    } else if (tid == 35) {
        g_cb[i] = bidx[idx];
    }
    __syncthreads();
    if (tid < 337) {
        float w = bwg[tid];
        #pragma unroll
        for (int d = 0; d < 16; d++) w = fmaf(ck[d], Wwg[d*337 + tid], w);
        ws[tid] = w;
    }
    __syncthreads();
    int pair = i >> 1, hf = i & 1;
    float cx = cc[0], cy = cc[1], cz = cc[2];
    for (int t = tid; t < 320; t += blockDim.x) {
        int j = t / 20, d = t % 20;
        float v;
        if (d < 16)      v = ws[d*16 + j];
        else if (d < 19) v = ws[(16 + (d-16))*16 + j];
        else             v = ws[304 + j] - cx*ws[256 + j] - cy*ws[272 + j] - cz*ws[288 + j];
        g_w1aug2[pair*640 + j*40 + d*2 + hf] = v;
    }
    if (tid < 16) g_w2p[pair*32 + tid*2 + hf] = ws[320 + tid];
    if (tid == 16) g_b2p[pair*2 + hf] = ws[336];
}

// ---------------- dynamic mask head: FFMA2, LDS.128 weights, 8 cand-pairs/block ----------------
__global__ __launch_bounds__(128, 1)
void masks_kernel(const float* __restrict__ coords, float* __restrict__ out, int N) {
    __shared__ float w1t[8*16*40];
    __shared__ float w2s[8*16*2];
    __shared__ float b2s[8*2];
    int tid = threadIdx.x;
    int pbase = blockIdx.y * 8;

    {
        const float4* src = (const float4*)(g_w1aug2 + pbase*640);
        float4* dst = (float4*)w1t;
        for (int t = tid; t < 1280; t += 128) dst[t] = src[t];
        for (int t = tid; t < 256; t += 128) w2s[t] = g_w2p[pbase*32 + t];
        if (tid < 16) b2s[tid] = g_b2p[pbase*2 + tid];
    }
    __syncthreads();

    int n0 = blockIdx.x * 256 + tid;
    int n1 = n0 + 128;
    bool v0 = (n0 < N), v1 = (n1 < N);
    int s0 = v0 ? n0 : (N - 1);
    int s1 = v1 ? n1 : (N - 1);

    u64 x0[19], x1[19];
    {
        const float4* mr = (const float4*)(g_maskf + (size_t)s0 * 16);
        #pragma unroll
        for (int q = 0; q < 4; q++) {
            float4 m = mr[q];
            x0[q*4]   = dup2(m.x); x0[q*4+1] = dup2(m.y);
            x0[q*4+2] = dup2(m.z); x0[q*4+3] = dup2(m.w);
        }
        x0[16] = dup2(coords[(size_t)s0*3]);
        x0[17] = dup2(coords[(size_t)s0*3+1]);
        x0[18] = dup2(coords[(size_t)s0*3+2]);
    }
    {
        const float4* mr = (const float4*)(g_maskf + (size_t)s1 * 16);
        #pragma unroll
        for (int q = 0; q < 4; q++) {
            float4 m = mr[q];
            x1[q*4]   = dup2(m.x); x1[q*4+1] = dup2(m.y);
            x1[q*4+2] = dup2(m.z); x1[q*4+3] = dup2(m.w);
        }
        x1[16] = dup2(coords[(size_t)s1*3]);
        x1[17] = dup2(coords[(size_t)s1*3+1]);
        x1[18] = dup2(coords[(size_t)s1*3+2]);
    }

    size_t ostride = (size_t)N + IC;
    const u64* w2q = (const u64*)w2s;

    #pragma unroll
    for (int cp = 0; cp < 8; cp++) {
        u64 macc0 = 0ull, macc1 = 0ull;
        const float* wb = w1t + cp*640;
        #pragma unroll 4
        for (int j = 0; j < 16; j++) {
            // weight row: 20 u64 = 10 ulonglong2 (160B, 16B-aligned); [9] = {w18, bias}
            const ulonglong2* wq2 = (const ulonglong2*)(wb + j*40);
            ulonglong2 wtail = wq2[9];
            u64 h0 = wtail.y;
            u64 h1 = wtail.y;
            #pragma unroll
            for (int q = 0; q < 9; q++) {
                ulonglong2 w = wq2[q];          // one LDS.128 = 2 d-slices
                h0 = ffma2(x0[2*q],   w.x, h0);
                h1 = ffma2(x1[2*q],   w.x, h1);
                h0 = ffma2(x0[2*q+1], w.y, h0);
                h1 = ffma2(x1[2*q+1], w.y, h1);
            }
            h0 = ffma2(x0[18], wtail.x, h0);
            h1 = ffma2(x1[18], wtail.x, h1);

            u64 w2v = w2q[cp*16 + j];
            float a, b;
            unpack2(h0, a, b);
            h0 = pack2(fmaxf(a, 0.f), fmaxf(b, 0.f));
            macc0 = ffma2(h0, w2v, macc0);
            unpack2(h1, a, b);
            h1 = pack2(fmaxf(a, 0.f), fmaxf(b, 0.f));
            macc1 = ffma2(h1, w2v, macc1);
        }
        float ba = b2s[cp*2], bb = b2s[cp*2+1];
        int ci0 = (pbase + cp) * 2;
        float* row0 = out + (size_t)ci0 * ostride;
        float* row1 = out + (size_t)(ci0 + 1) * ostride;
        float a, b;
        unpack2(macc0, a, b);
        if (v0) { row0[n0] = sigmoidf_(a + ba); row1[n0] = sigmoidf_(b + bb); }
        unpack2(macc1, a, b);
        if (v1) { row0[n1] = sigmoidf_(a + ba); row1[n1] = sigmoidf_(b + bb); }
    }
}

// ---------------- merge tower layer ----------------
__global__ __launch_bounds__(256, 1)
void merge_layer_kernel(const float* __restrict__ xin, float* __restrict__ yout,
                        const float* __restrict__ Wgl,
                        const float* __restrict__ pstats, float* __restrict__ ostats,
                        int layer0) {
    __shared__ float Ws[35*35];
    __shared__ float featS[IC*35];
    __shared__ float smean[35], srstd[35];
    __shared__ float ps[8][70];
    int tid = threadIdx.x;
    for (int t = tid; t < 1225; t += 256) Ws[t] = Wgl[t];
    if (layer0) {
        for (int t = tid; t < IC*35; t += 256) featS[t] = g_feat[t];
    } else if (tid < 35) {
        float s = pstats[tid], q = pstats[64 + tid];
        float m = s / (float)MR;
        float v = q / (float)MR - m*m;
        smean[tid] = m; srstd[tid] = rsqrtf(v + EPSF);
    }
    __syncthreads();

    int row = blockIdx.x * 256 + tid;
    float xv[35];
    if (layer0) {
        int i = row >> 7, j = row & 127;
        #pragma unroll
        for (int c = 0; c < 35; c++)
            xv[c] = fmaxf(fabsf(featS[i*35 + c] - featS[j*35 + c]), 1e-6f);
    } else {
        #pragma unroll
        for (int c = 0; c < 35; c++)
            xv[c] = fmaxf((xin[(size_t)row*35 + c] - smean[c]) * srstd[c], 0.f);
    }
    float acc[35];
    #pragma unroll
    for (int c = 0; c < 35; c++) acc[c] = 0.f;
    for (int c = 0; c < 35; c++) {
        float xa = xv[c];
        const float* wr = Ws + c*35;
        #pragma unroll
        for (int c2 = 0; c2 < 35; c2++) acc[c2] = fmaf(xa, wr[c2], acc[c2]);
    }
    #pragma unroll
    for (int c = 0; c < 35; c++) yout[(size_t)row*35 + c] = acc[c];

    int lane = tid & 31, warp = tid >> 5;
    for (int c = 0; c < 35; c++) {
        float s = acc[c]; float q = s * s;
        #pragma unroll
        for (int o = 16; o; o >>= 1) {
            s += __shfl_down_sync(0xffffffffu, s, o);
            q += __shfl_down_sync(0xffffffffu, q, o);
        }
        if (lane == 0) { ps[warp][c] = s; ps[warp][35 + c] = q; }
    }
    __syncthreads();
    if (tid < 70) {
        float t = 0.f;
        #pragma unroll
        for (int w = 0; w < 8; w++) t += ps[w][tid];
        int target = (tid < 35) ? tid : (64 + tid - 35);
        atomicAdd(&ostats[target], t);
    }
}

// ---------------- merge output ----------------
__global__ __launch_bounds__(256, 1)
void merge_out_kernel(const float* __restrict__ xin,
                      const float* __restrict__ Wgo, const float* __restrict__ bgo,
                      const float* __restrict__ pstats,
                      float* __restrict__ out, int N) {
    __shared__ float wout[35];
    __shared__ float smean[35], srstd[35];
    int tid = threadIdx.x;
    if (tid < 35) {
        wout[tid] = Wgo[tid];
        float s = pstats[tid], q = pstats[64 + tid];
        float m = s / (float)MR;
        float v = q / (float)MR - m*m;
        smean[tid] = m; srstd[tid] = rsqrtf(v + EPSF);
    }
    __syncthreads();
    int row = blockIdx.x * 256 + tid;
    int i = row >> 7, j = row & 127;
    float acc = bgo[0];
    #pragma unroll
    for (int c = 0; c < 35; c++) {
        float x = fmaxf((xin[(size_t)row*35 + c] - smean[c]) * srstd[c], 0.f);
        acc = fmaf(x, wout[c], acc);
    }
    float v = (g_cb[i] != g_cb[j]) ? 0.f : sigmoidf_(acc);
    out[(size_t)i * ((size_t)N + IC) + (size_t)N + j] = v;
}

// ---------------- launch ----------------
extern "C" void kernel_launch(void* const* d_in, const int* in_sizes, int n_in,
                              void* d_out, int out_size) {
    const float* output_feats = (const float*)d_in[0];
    const float* coords       = (const float*)d_in[1];
    const float* heat         = (const float*)d_in[2];
    const int*   batch_idxs   = (const int*)  d_in[3];
    const float* Wm           = (const float*)d_in[4];
    const float* Wm_out       = (const float*)d_in[5];
    const float* bm_out       = (const float*)d_in[6];
    const float* Wk           = (const float*)d_in[7];
    const float* Wk_out       = (const float*)d_in[8];
    const float* bk_out       = (const float*)d_in[9];
    const float* Wg           = (const float*)d_in[10];
    const float* Wg_out       = (const float*)d_in[11];
    const float* bg_out       = (const float*)d_in[12];
    const float* Wwg          = (const float*)d_in[13];
    const float* bwg          = (const float*)d_in[14];
    float* out = (float*)d_out;
    int N = in_sizes[2];

    static cudaStream_t s_side = nullptr;
    static cudaEvent_t ev_fork = nullptr, ev_nms = nullptr, ev_cand = nullptr, ev_merge = nullptr;
    if (s_side == nullptr) {
        cudaStreamCreateWithFlags(&s_side, cudaStreamNonBlocking);
        cudaEventCreateWithFlags(&ev_fork, cudaEventDisableTiming);
        cudaEventCreateWithFlags(&ev_nms, cudaEventDisableTiming);
        cudaEventCreateWithFlags(&ev_cand, cudaEventDisableTiming);
        cudaEventCreateWithFlags(&ev_merge, cudaEventDisableTiming);
    }

    float *yA, *yB, *mA, *mB, *stats, *mstats;
    cudaGetSymbolAddress((void**)&yA, g_yA);
    cudaGetSymbolAddress((void**)&yB, g_yB);
    cudaGetSymbolAddress((void**)&mA, g_mA);
    cudaGetSymbolAddress((void**)&mB, g_mB);
    cudaGetSymbolAddress((void**)&stats, g_stats);
    cudaGetSymbolAddress((void**)&mstats, g_mstats);

    // fork: NMS on side stream, towers on main
    cudaEventRecord(ev_fork, (cudaStream_t)0);
    cudaStreamWaitEvent(s_side, ev_fork, 0);
    nms_kernel<<<NB, 1024, 0, s_side>>>(heat, coords, batch_idxs, N);
    cudaEventRecord(ev_nms, s_side);

    int tg = (N + 255) / 256;
    tower_layer_kernel<<<tg, 256>>>(output_feats, yA, Wm,        Wk,        nullptr,     N, 1);
    colstats_kernel<<<256, 256>>>(yA, stats, N);
    tower_layer_kernel<<<tg, 256>>>(yA,           yB, Wm + 1024, Wk + 1024, stats,       N, 0);
    colstats_kernel<<<256, 256>>>(yB, stats + 128, N);
    tower_layer_kernel<<<tg, 256>>>(yB,           yA, Wm + 2048, Wk + 2048, stats + 128, N, 0);
    colstats_kernel<<<256, 256>>>(yA, stats + 256, N);
    feats_kernel<<<tg, 256>>>(yA, Wm_out, bm_out, Wk_out, bk_out, stats + 256, N);

    // join NMS; cand_prep needs NMS + feats
    cudaStreamWaitEvent((cudaStream_t)0, ev_nms, 0);
    cand_prep_kernel<<<IC, 352>>>(coords, batch_idxs, Wwg, bwg);
    cudaEventRecord(ev_cand, (cudaStream_t)0);

    // merge chain on side stream, overlapped with masks on main
    cudaStreamWaitEvent(s_side, ev_cand, 0);
    merge_layer_kernel<<<64, 256, 0, s_side>>>(nullptr, mA, Wg,        nullptr,      mstats,       1);
    merge_layer_kernel<<<64, 256, 0, s_side>>>(mA,      mB, Wg + 1225, mstats,       mstats + 128, 0);
    merge_layer_kernel<<<64, 256, 0, s_side>>>(mB,      mA, Wg + 2450, mstats + 128, mstats + 256, 0);
    merge_out_kernel<<<64, 256, 0, s_side>>>(mA, Wg_out, bg_out, mstats + 256, out, N);
    cudaEventRecord(ev_merge, s_side);

    dim3 mg((N + 255) / 256, 8);
    masks_kernel<<<mg, 128>>>(coords, out, N);

    // ensure graph end depends on merge chain
    cudaStreamWaitEvent((cudaStream_t)0, ev_merge, 0);
}

// round 12
// speedup vs baseline: 1.6175x; 1.0046x over previous
#include <cuda_runtime.h>
#include <math.h>
#include <stdint.h>

#define D32   32
#define OD    16
#define NB    4
#define KK    32
#define R2C   0.09f
#define EPSF  1e-5f
#define NMAX  100000
#define IC    128
#define MR    (IC*IC)

typedef unsigned long long u64;

// ---------------- device scratch (no allocations allowed) ----------------
__device__ float g_yA[NMAX*64];
__device__ float g_yB[NMAX*64];
__device__ float g_maskf[NMAX*OD];
__device__ float g_kernf[NMAX*OD];
__device__ float g_stats[3*128];
__device__ float g_mstats[3*128];
__device__ int   g_topk[IC];
__device__ float g_feat[IC*35];
__device__ float g_ctr[IC*3];
__device__ int   g_cb[IC];
__device__ float g_mA[MR*35];
__device__ float g_mB[MR*35];
__device__ float g_nmsbuf[NMAX];
__device__ float g_w1aug2[64*16*40];
__device__ float g_w2p[64*16*2];
__device__ float g_b2p[64*2];

__device__ __forceinline__ float sigmoidf_(float x) {
    return 1.0f / (1.0f + __expf(-x));
}
__device__ __forceinline__ u64 pack2(float lo, float hi) {
    u64 r; asm("mov.b64 %0, {%1, %2};" : "=l"(r) : "f"(lo), "f"(hi)); return r;
}
__device__ __forceinline__ u64 dup2(float x) { return pack2(x, x); }
__device__ __forceinline__ void unpack2(u64 v, float &lo, float &hi) {
    asm("mov.b64 {%0, %1}, %2;" : "=f"(lo), "=f"(hi) : "l"(v));
}
__device__ __forceinline__ u64 ffma2(u64 a, u64 b, u64 c) {
    u64 d; asm("fma.rn.f32x2 %0, %1, %2, %3;" : "=l"(d) : "l"(a), "l"(b), "l"(c)); return d;
}

// ---------------- greedy top-K NMS: heat register-resident ----------------
__global__ __launch_bounds__(1024, 1)
void nms_kernel(const float* __restrict__ heat, const float* __restrict__ coords,
                const int* __restrict__ bidx, int N) {
    int b = blockIdx.x;
    int lo = 0, hi = N;
    while (lo < hi) { int m = (lo + hi) >> 1; if (bidx[m] < b) lo = m + 1; else hi = m; }
    int s = lo; hi = N;
    while (lo < hi) { int m = (lo + hi) >> 1; if (bidx[m] <= b) lo = m + 1; else hi = m; }
    int e = lo, nb = e - s;

    __shared__ float rv[32]; __shared__ int ri[32];
    __shared__ float cc[3]; __shared__ int have;
    if (threadIdx.x == 0) have = 0;

    const float NEG = __int_as_float(0xff800000);
    int lane = threadIdx.x & 31, w = threadIdx.x >> 5;

    if (nb <= 32768) {
        float hv[32];
        #pragma unroll
        for (int ii = 0; ii < 32; ii++) {
            int t = ii*1024 + threadIdx.x;
            hv[ii] = (t < nb) ? heat[s + t] : NEG;
        }
        __syncthreads();
        for (int k = 0; k < KK; k++) {
            int h = have;
            float cx = 0.f, cy = 0.f, cz = 0.f;
            if (h) { cx = cc[0]; cy = cc[1]; cz = cc[2]; }
            float best = NEG; int bi = 0x7fffffff;
            #pragma unroll
            for (int ii = 0; ii < 32; ii++) {
                int t = ii*1024 + threadIdx.x;
                if (t >= nb) break;
                float v = hv[ii];
                if (h && v != NEG) {
                    int g = s + t;
                    float dx = coords[g*3]   - cx;
                    float dy = coords[g*3+1] - cy;
                    float dz = coords[g*3+2] - cz;
                    if (dx*dx + dy*dy + dz*dz < R2C) { v = NEG; hv[ii] = NEG; }
                }
                if (v > best) { best = v; bi = t; }
            }
            #pragma unroll
            for (int o = 16; o; o >>= 1) {
                float ov = __shfl_down_sync(0xffffffffu, best, o);
                int   oi = __shfl_down_sync(0xffffffffu, bi, o);
                if (ov > best || (ov == best && oi < bi)) { best = ov; bi = oi; }
            }
            if (lane == 0) { rv[w] = best; ri[w] = bi; }
            __syncthreads();
            if (w == 0) {
                best = rv[lane]; bi = ri[lane];
                #pragma unroll
                for (int o = 16; o; o >>= 1) {
                    float ov = __shfl_down_sync(0xffffffffu, best, o);
                    int   oi = __shfl_down_sync(0xffffffffu, bi, o);
                    if (ov > best || (ov == best && oi < bi)) { best = ov; bi = oi; }
                }
                if (lane == 0) {
                    int chosen = (best == NEG) ? 0 : (s + bi);
                    g_topk[b*KK + k] = chosen;
                    cc[0] = coords[chosen*3]; cc[1] = coords[chosen*3+1]; cc[2] = coords[chosen*3+2];
                    have = 1;
                }
            }
            __syncthreads();
        }
    } else {
        float* buf = g_nmsbuf + s;
        for (int t = threadIdx.x; t < nb; t += 1024) buf[t] = heat[s + t];
        __syncthreads();
        for (int k = 0; k < KK; k++) {
            int h = have;
            float cx = 0.f, cy = 0.f, cz = 0.f;
            if (h) { cx = cc[0]; cy = cc[1]; cz = cc[2]; }
            float best = NEG; int bi = 0x7fffffff;
            for (int t = threadIdx.x; t < nb; t += 1024) {
                float v = buf[t];
                if (h && v != NEG) {
                    int g = s + t;
                    float dx = coords[g*3]   - cx;
                    float dy = coords[g*3+1] - cy;
                    float dz = coords[g*3+2] - cz;
                    if (dx*dx + dy*dy + dz*dz < R2C) { v = NEG; buf[t] = NEG; }
                }
                if (v > best) { best = v; bi = t; }
            }
            #pragma unroll
            for (int o = 16; o; o >>= 1) {
                float ov = __shfl_down_sync(0xffffffffu, best, o);
                int   oi = __shfl_down_sync(0xffffffffu, bi, o);
                if (ov > best || (ov == best && oi < bi)) { best = ov; bi = oi; }
            }
            if (lane == 0) { rv[w] = best; ri[w] = bi; }
            __syncthreads();
            if (w == 0) {
                best = rv[lane]; bi = ri[lane];
                #pragma unroll
                for (int o = 16; o; o >>= 1) {
                    float ov = __shfl_down_sync(0xffffffffu, best, o);
                    int   oi = __shfl_down_sync(0xffffffffu, bi, o);
                    if (ov > best || (ov == best && oi < bi)) { best = ov; bi = oi; }
                }
                if (lane == 0) {
                    int chosen = (best == NEG) ? 0 : (s + bi);
                    g_topk[b*KK + k] = chosen;
                    cc[0] = coords[chosen*3]; cc[1] = coords[chosen*3+1]; cc[2] = coords[chosen*3+2];
                    have = 1;
                }
            }
            __syncthreads();
        }
    }
}

// ---------------- tower layer: gridDim.y=2 (m-half / k-half), low regs, 3 CTAs/SM ----------------
__global__ __launch_bounds__(256, 3)
void tower_layer_kernel(const float* __restrict__ x, float* __restrict__ y,
                        const float* __restrict__ Wml, const float* __restrict__ Wkl,
                        const float* __restrict__ pstats,
                        int N, int layer0) {
    int half = blockIdx.y;
    if (layer0 && blockIdx.x == 0 && half == 0) {
        for (int t = threadIdx.x; t < 768; t += 256) {
            if (t < 384) g_stats[t] = 0.f;
            else         g_mstats[t - 384] = 0.f;
        }
    }
    __shared__ float Ws[32*32];          // this half's weights [d][j]
    __shared__ float smean[32], srstd[32];
    const float* Wl = half ? Wkl : Wml;
    for (int t = threadIdx.x; t < 1024; t += 256) Ws[t] = Wl[t];
    if (!layer0 && threadIdx.x < 32) {
        int c = half*32 + threadIdx.x;
        float s = pstats[c], q = pstats[64 + c];
        float m = s / (float)N;
        float v = q / (float)N - m*m;
        smean[threadIdx.x] = m;
        srstd[threadIdx.x] = rsqrtf(v + EPSF);
    }
    __syncthreads();

    int n = blockIdx.x * 256 + threadIdx.x;
    if (n >= N) return;

    float xv[32];
    if (layer0) {
        const float4* xr = (const float4*)(x + (size_t)n * 32);
        #pragma unroll
        for (int q = 0; q < 8; q++) {
            float4 v = xr[q]; int d = q*4;
            xv[d] = v.x; xv[d+1] = v.y; xv[d+2] = v.z; xv[d+3] = v.w;
        }
    } else {
        const float4* xr = (const float4*)(x + (size_t)n * 64 + half*32);
        #pragma unroll
        for (int q = 0; q < 8; q++) {
            float4 v = xr[q]; int d = q*4;
            xv[d]   = fmaxf((v.x - smean[d])   * srstd[d],   0.f);
            xv[d+1] = fmaxf((v.y - smean[d+1]) * srstd[d+1], 0.f);
            xv[d+2] = fmaxf((v.z - smean[d+2]) * srstd[d+2], 0.f);
            xv[d+3] = fmaxf((v.w - smean[d+3]) * srstd[d+3], 0.f);
        }
    }
    u64 acc[16];
    #pragma unroll
    for (int j = 0; j < 16; j++) acc[j] = 0ull;
    #pragma unroll 4
    for (int d = 0; d < 32; d++) {
        u64 xd = dup2(xv[d]);
        const ulonglong2* wr = (const ulonglong2*)(Ws + d*32);
        #pragma unroll
        for (int q = 0; q < 4; q++) {
            ulonglong2 w = wr[q];
            acc[2*q]   = ffma2(xd, w.x, acc[2*q]);
            acc[2*q+1] = ffma2(xd, w.y, acc[2*q+1]);
        }
        #pragma unroll
        for (int q = 4; q < 8; q++) {
            ulonglong2 w = wr[q];
            acc[2*q]   = ffma2(xd, w.x, acc[2*q]);
            acc[2*q+1] = ffma2(xd, w.y, acc[2*q+1]);
        }
    }
    ulonglong2* yr = (ulonglong2*)(y + (size_t)n * 64 + half*32);
    #pragma unroll
    for (int q = 0; q < 8; q++) yr[q] = make_ulonglong2(acc[2*q], acc[2*q+1]);
}

// ---------------- column stats: 4 row-streams per thread, grid 256 ----------------
#define CS_ACC(vv, ss, qq) \
    ss.x += vv.x; ss.y += vv.y; ss.z += vv.z; ss.w += vv.w; \
    qq.x = fmaf(vv.x, vv.x, qq.x); qq.y = fmaf(vv.y, vv.y, qq.y); \
    qq.z = fmaf(vv.z, vv.z, qq.z); qq.w = fmaf(vv.w, vv.w, qq.w);

__global__ __launch_bounds__(256, 1)
void colstats_kernel(const float* __restrict__ y, float* __restrict__ ostats, int N) {
    int tid = threadIdx.x;
    int lane16 = tid & 15;
    int rg = tid >> 4;                 // 0..15
    float4 z = make_float4(0.f,0.f,0.f,0.f);
    float4 s0 = z, q0 = z, s1 = z, q1 = z, s2 = z, q2 = z, s3 = z, q3 = z;
    int r = blockIdx.x * 64 + rg;
    int stride = gridDim.x * 64;
    for (; r + 48 < N; r += stride) {
        float4 v0 = ((const float4*)(y + (size_t)r*64))[lane16];
        float4 v1 = ((const float4*)(y + (size_t)(r+16)*64))[lane16];
        float4 v2 = ((const float4*)(y + (size_t)(r+32)*64))[lane16];
        float4 v3 = ((const float4*)(y + (size_t)(r+48)*64))[lane16];
        CS_ACC(v0, s0, q0) CS_ACC(v1, s1, q1) CS_ACC(v2, s2, q2) CS_ACC(v3, s3, q3)
    }
    if (r < N)      { float4 v = ((const float4*)(y + (size_t)r*64))[lane16];      CS_ACC(v, s0, q0) }
    if (r + 16 < N) { float4 v = ((const float4*)(y + (size_t)(r+16)*64))[lane16]; CS_ACC(v, s1, q1) }
    if (r + 32 < N) { float4 v = ((const float4*)(y + (size_t)(r+32)*64))[lane16]; CS_ACC(v, s2, q2) }
    float4 s = make_float4(s0.x+s1.x+s2.x+s3.x, s0.y+s1.y+s2.y+s3.y,
                           s0.z+s1.z+s2.z+s3.z, s0.w+s1.w+s2.w+s3.w);
    float4 q = make_float4(q0.x+q1.x+q2.x+q3.x, q0.y+q1.y+q2.y+q3.y,
                           q0.z+q1.z+q2.z+q3.z, q0.w+q1.w+q2.w+q3.w);
    __shared__ float sm[256][8];
    sm[tid][0] = s.x; sm[tid][1] = s.y; sm[tid][2] = s.z; sm[tid][3] = s.w;
    sm[tid][4] = q.x; sm[tid][5] = q.y; sm[tid][6] = q.z; sm[tid][7] = q.w;
    __syncthreads();
    if (tid < 16) {
        float a0=0,a1=0,a2=0,a3=0,b0=0,b1=0,b2=0,b3=0;
        #pragma unroll
        for (int g = 0; g < 16; g++) {
            float* p = sm[tid + 16*g];
            a0 += p[0]; a1 += p[1]; a2 += p[2]; a3 += p[3];
            b0 += p[4]; b1 += p[5]; b2 += p[6]; b3 += p[7];
        }
        int c = tid*4;
        atomicAdd(&ostats[c],   a0); atomicAdd(&ostats[c+1], a1);
        atomicAdd(&ostats[c+2], a2); atomicAdd(&ostats[c+3], a3);
        atomicAdd(&ostats[64+c],   b0); atomicAdd(&ostats[64+c+1], b1);
        atomicAdd(&ostats[64+c+2], b2); atomicAdd(&ostats[64+c+3], b3);
    }
}

// ---------------- final projection: gridDim.y=2 (m-half / k-half) ----------------
__global__ __launch_bounds__(256, 3)
void feats_kernel(const float* __restrict__ yin,
                  const float* __restrict__ Wmo, const float* __restrict__ bmo,
                  const float* __restrict__ Wko, const float* __restrict__ bko,
                  const float* __restrict__ pstats, int N) {
    int half = blockIdx.y;
    __shared__ float Wos[32*16];
    __shared__ float bs[16];
    __shared__ float smean[32], srstd[32];
    const float* Wo = half ? Wko : Wmo;
    for (int t = threadIdx.x; t < 512; t += 256) Wos[t] = Wo[t];
    if (threadIdx.x < 16) bs[threadIdx.x] = half ? bko[threadIdx.x] : bmo[threadIdx.x];
    if (threadIdx.x < 32) {
        int c = half*32 + threadIdx.x;
        float s = pstats[c], q = pstats[64 + c];
        float m = s / (float)N;
        float v = q / (float)N - m*m;
        smean[threadIdx.x] = m; srstd[threadIdx.x] = rsqrtf(v + EPSF);
    }
    __syncthreads();
    int n = blockIdx.x * 256 + threadIdx.x;
    if (n >= N) return;

    float xv[32];
    const float4* xr = (const float4*)(yin + (size_t)n * 64 + half*32);
    #pragma unroll
    for (int q = 0; q < 8; q++) {
        float4 v = xr[q]; int d = q*4;
        xv[d]   = fmaxf((v.x - smean[d])   * srstd[d],   0.f);
        xv[d+1] = fmaxf((v.y - smean[d+1]) * srstd[d+1], 0.f);
        xv[d+2] = fmaxf((v.z - smean[d+2]) * srstd[d+2], 0.f);
        xv[d+3] = fmaxf((v.w - smean[d+3]) * srstd[d+3], 0.f);
    }
    u64 acc[8];
    #pragma unroll
    for (int j = 0; j < 8; j++) acc[j] = 0ull;
    #pragma unroll 4
    for (int d = 0; d < 32; d++) {
        u64 xd = dup2(xv[d]);
        const ulonglong2* wr = (const ulonglong2*)(Wos + d*16);
        #pragma unroll
        for (int q = 0; q < 4; q++) {
            ulonglong2 w = wr[q];
            acc[2*q]   = ffma2(xd, w.x, acc[2*q]);
            acc[2*q+1] = ffma2(xd, w.y, acc[2*q+1]);
        }
    }
    float* dst = half ? (g_kernf + (size_t)n * 16) : (g_maskf + (size_t)n * 16);
    #pragma unroll
    for (int q = 0; q < 8; q++) {
        float lo, hi; unpack2(acc[q], lo, hi);
        int j = q*2;
        dst[j] = lo + bs[j]; dst[j+1] = hi + bs[j+1];
    }
}

// ---------------- candidate gather + weight generator + aug-weight build ----------------
__global__ void cand_prep_kernel(const float* __restrict__ coords, const int* __restrict__ bidx,
                                 const float* __restrict__ Wwg, const float* __restrict__ bwg) {
    int i = blockIdx.x;
    int tid = threadIdx.x;
    __shared__ float ck[16];
    __shared__ float ws[337];
    __shared__ float cc[3];
    __shared__ int sidx;
    if (tid == 0) sidx = g_topk[i];
    __syncthreads();
    int idx = sidx;
    if (tid < 16) {
        float v = g_kernf[(size_t)idx*16 + tid];
        ck[tid] = v;
        g_feat[i*35 + tid] = v;
    } else if (tid < 32) {
        g_feat[i*35 + tid] = g_maskf[(size_t)idx*16 + (tid - 16)];
    } else if (tid < 35) {
        float c = coords[(size_t)idx*3 + (tid - 32)];
        g_feat[i*35 + tid] = c;
        g_ctr[i*3 + (tid - 32)] = c;
        cc[tid - 32] = c;
    } else if (tid == 35) {
        g_cb[i] = bidx[idx];
    }
    __syncthreads();
    if (tid < 337) {
        float w = bwg[tid];
        #pragma unroll
        for (int d = 0; d < 16; d++) w = fmaf(ck[d], Wwg[d*337 + tid], w);
        ws[tid] = w;
    }
    __syncthreads();
    int pair = i >> 1, hf = i & 1;
    float cx = cc[0], cy = cc[1], cz = cc[2];
    for (int t = tid; t < 320; t += blockDim.x) {
        int j = t / 20, d = t % 20;
        float v;
        if (d < 16)      v = ws[d*16 + j];
        else if (d < 19) v = ws[(16 + (d-16))*16 + j];
        else             v = ws[304 + j] - cx*ws[256 + j] - cy*ws[272 + j] - cz*ws[288 + j];
        g_w1aug2[pair*640 + j*40 + d*2 + hf] = v;
    }
    if (tid < 16) g_w2p[pair*32 + tid*2 + hf] = ws[320 + tid];
    if (tid == 16) g_b2p[pair*2 + hf] = ws[336];
}

// ---------------- dynamic mask head: FFMA2, LDS.128 weights, 8 cand-pairs/block ----------------
__global__ __launch_bounds__(128, 1)
void masks_kernel(const float* __restrict__ coords, float* __restrict__ out, int N) {
    __shared__ float w1t[8*16*40];
    __shared__ float w2s[8*16*2];
    __shared__ float b2s[8*2];
    int tid = threadIdx.x;
    int pbase = blockIdx.y * 8;

    {
        const float4* src = (const float4*)(g_w1aug2 + pbase*640);
        float4* dst = (float4*)w1t;
        for (int t = tid; t < 1280; t += 128) dst[t] = src[t];
        for (int t = tid; t < 256; t += 128) w2s[t] = g_w2p[pbase*32 + t];
        if (tid < 16) b2s[tid] = g_b2p[pbase*2 + tid];
    }
    __syncthreads();

    int n0 = blockIdx.x * 256 + tid;
    int n1 = n0 + 128;
    bool v0 = (n0 < N), v1 = (n1 < N);
    int s0 = v0 ? n0 : (N - 1);
    int s1 = v1 ? n1 : (N - 1);

    u64 x0[19], x1[19];
    {
        const float4* mr = (const float4*)(g_maskf + (size_t)s0 * 16);
        #pragma unroll
        for (int q = 0; q < 4; q++) {
            float4 m = mr[q];
            x0[q*4]   = dup2(m.x); x0[q*4+1] = dup2(m.y);
            x0[q*4+2] = dup2(m.z); x0[q*4+3] = dup2(m.w);
        }
        x0[16] = dup2(coords[(size_t)s0*3]);
        x0[17] = dup2(coords[(size_t)s0*3+1]);
        x0[18] = dup2(coords[(size_t)s0*3+2]);
    }
    {
        const float4* mr = (const float4*)(g_maskf + (size_t)s1 * 16);
        #pragma unroll
        for (int q = 0; q < 4; q++) {
            float4 m = mr[q];
            x1[q*4]   = dup2(m.x); x1[q*4+1] = dup2(m.y);
            x1[q*4+2] = dup2(m.z); x1[q*4+3] = dup2(m.w);
        }
        x1[16] = dup2(coords[(size_t)s1*3]);
        x1[17] = dup2(coords[(size_t)s1*3+1]);
        x1[18] = dup2(coords[(size_t)s1*3+2]);
    }

    size_t ostride = (size_t)N + IC;
    const u64* w2q = (const u64*)w2s;

    #pragma unroll
    for (int cp = 0; cp < 8; cp++) {
        u64 macc0 = 0ull, macc1 = 0ull;
        const float* wb = w1t + cp*640;
        #pragma unroll 4
        for (int j = 0; j < 16; j++) {
            const ulonglong2* wq2 = (const ulonglong2*)(wb + j*40);
            ulonglong2 wtail = wq2[9];
            u64 h0 = wtail.y;
            u64 h1 = wtail.y;
            #pragma unroll
            for (int q = 0; q < 9; q++) {
                ulonglong2 w = wq2[q];
                h0 = ffma2(x0[2*q],   w.x, h0);
                h1 = ffma2(x1[2*q],   w.x, h1);
                h0 = ffma2(x0[2*q+1], w.y, h0);
                h1 = ffma2(x1[2*q+1], w.y, h1);
            }
            h0 = ffma2(x0[18], wtail.x, h0);
            h1 = ffma2(x1[18], wtail.x, h1);

            u64 w2v = w2q[cp*16 + j];
            float a, b;
            unpack2(h0, a, b);
            h0 = pack2(fmaxf(a, 0.f), fmaxf(b, 0.f));
            macc0 = ffma2(h0, w2v, macc0);
            unpack2(h1, a, b);
            h1 = pack2(fmaxf(a, 0.f), fmaxf(b, 0.f));
            macc1 = ffma2(h1, w2v, macc1);
        }
        float ba = b2s[cp*2], bb = b2s[cp*2+1];
        int ci0 = (pbase + cp) * 2;
        float* row0 = out + (size_t)ci0 * ostride;
        float* row1 = out + (size_t)(ci0 + 1) * ostride;
        float a, b;
        unpack2(macc0, a, b);
        if (v0) { row0[n0] = sigmoidf_(a + ba); row1[n0] = sigmoidf_(b + bb); }
        unpack2(macc1, a, b);
        if (v1) { row0[n1] = sigmoidf_(a + ba); row1[n1] = sigmoidf_(b + bb); }
    }
}

// ---------------- merge tower layer ----------------
__global__ __launch_bounds__(256, 1)
void merge_layer_kernel(const float* __restrict__ xin, float* __restrict__ yout,
                        const float* __restrict__ Wgl,
                        const float* __restrict__ pstats, float* __restrict__ ostats,
                        int layer0) {
    __shared__ float Ws[35*35];
    __shared__ float featS[IC*35];
    __shared__ float smean[35], srstd[35];
    __shared__ float ps[8][70];
    int tid = threadIdx.x;
    for (int t = tid; t < 1225; t += 256) Ws[t] = Wgl[t];
    if (layer0) {
        for (int t = tid; t < IC*35; t += 256) featS[t] = g_feat[t];
    } else if (tid < 35) {
        float s = pstats[tid], q = pstats[64 + tid];
        float m = s / (float)MR;
        float v = q / (float)MR - m*m;
        smean[tid] = m; srstd[tid] = rsqrtf(v + EPSF);
    }
    __syncthreads();

    int row = blockIdx.x * 256 + tid;
    float xv[35];
    if (layer0) {
        int i = row >> 7, j = row & 127;
        #pragma unroll
        for (int c = 0; c < 35; c++)
            xv[c] = fmaxf(fabsf(featS[i*35 + c] - featS[j*35 + c]), 1e-6f);
    } else {
        #pragma unroll
        for (int c = 0; c < 35; c++)
            xv[c] = fmaxf((xin[(size_t)row*35 + c] - smean[c]) * srstd[c], 0.f);
    }
    float acc[35];
    #pragma unroll
    for (int c = 0; c < 35; c++) acc[c] = 0.f;
    for (int c = 0; c < 35; c++) {
        float xa = xv[c];
        const float* wr = Ws + c*35;
        #pragma unroll
        for (int c2 = 0; c2 < 35; c2++) acc[c2] = fmaf(xa, wr[c2], acc[c2]);
    }
    #pragma unroll
    for (int c = 0; c < 35; c++) yout[(size_t)row*35 + c] = acc[c];

    int lane = tid & 31, warp = tid >> 5;
    for (int c = 0; c < 35; c++) {
        float s = acc[c]; float q = s * s;
        #pragma unroll
        for (int o = 16; o; o >>= 1) {
            s += __shfl_down_sync(0xffffffffu, s, o);
            q += __shfl_down_sync(0xffffffffu, q, o);
        }
        if (lane == 0) { ps[warp][c] = s; ps[warp][35 + c] = q; }
    }
    __syncthreads();
    if (tid < 70) {
        float t = 0.f;
        #pragma unroll
        for (int w = 0; w < 8; w++) t += ps[w][tid];
        int target = (tid < 35) ? tid : (64 + tid - 35);
        atomicAdd(&ostats[target], t);
    }
}

// ---------------- merge output ----------------
__global__ __launch_bounds__(256, 1)
void merge_out_kernel(const float* __restrict__ xin,
                      const float* __restrict__ Wgo, const float* __restrict__ bgo,
                      const float* __restrict__ pstats,
                      float* __restrict__ out, int N) {
    __shared__ float wout[35];
    __shared__ float smean[35], srstd[35];
    int tid = threadIdx.x;
    if (tid < 35) {
        wout[tid] = Wgo[tid];
        float s = pstats[tid], q = pstats[64 + tid];
        float m = s / (float)MR;
        float v = q / (float)MR - m*m;
        smean[tid] = m; srstd[tid] = rsqrtf(v + EPSF);
    }
    __syncthreads();
    int row = blockIdx.x * 256 + tid;
    int i = row >> 7, j = row & 127;
    float acc = bgo[0];
    #pragma unroll
    for (int c = 0; c < 35; c++) {
        float x = fmaxf((xin[(size_t)row*35 + c] - smean[c]) * srstd[c], 0.f);
        acc = fmaf(x, wout[c], acc);
    }
    float v = (g_cb[i] != g_cb[j]) ? 0.f : sigmoidf_(acc);
    out[(size_t)i * ((size_t)N + IC) + (size_t)N + j] = v;
}

// ---------------- launch ----------------
extern "C" void kernel_launch(void* const* d_in, const int* in_sizes, int n_in,
                              void* d_out, int out_size) {
    const float* output_feats = (const float*)d_in[0];
    const float* coords       = (const float*)d_in[1];
    const float* heat         = (const float*)d_in[2];
    const int*   batch_idxs   = (const int*)  d_in[3];
    const float* Wm           = (const float*)d_in[4];
    const float* Wm_out       = (const float*)d_in[5];
    const float* bm_out       = (const float*)d_in[6];
    const float* Wk           = (const float*)d_in[7];
    const float* Wk_out       = (const float*)d_in[8];
    const float* bk_out       = (const float*)d_in[9];
    const float* Wg           = (const float*)d_in[10];
    const float* Wg_out       = (const float*)d_in[11];
    const float* bg_out       = (const float*)d_in[12];
    const float* Wwg          = (const float*)d_in[13];
    const float* bwg          = (const float*)d_in[14];
    float* out = (float*)d_out;
    int N = in_sizes[2];

    static cudaStream_t s_side = nullptr;
    static cudaEvent_t ev_fork = nullptr, ev_nms = nullptr, ev_cand = nullptr, ev_merge = nullptr;
    if (s_side == nullptr) {
        cudaStreamCreateWithFlags(&s_side, cudaStreamNonBlocking);
        cudaEventCreateWithFlags(&ev_fork, cudaEventDisableTiming);
        cudaEventCreateWithFlags(&ev_nms, cudaEventDisableTiming);
        cudaEventCreateWithFlags(&ev_cand, cudaEventDisableTiming);
        cudaEventCreateWithFlags(&ev_merge, cudaEventDisableTiming);
    }

    float *yA, *yB, *mA, *mB, *stats, *mstats;
    cudaGetSymbolAddress((void**)&yA, g_yA);
    cudaGetSymbolAddress((void**)&yB, g_yB);
    cudaGetSymbolAddress((void**)&mA, g_mA);
    cudaGetSymbolAddress((void**)&mB, g_mB);
    cudaGetSymbolAddress((void**)&stats, g_stats);
    cudaGetSymbolAddress((void**)&mstats, g_mstats);

    // fork: NMS on side stream, towers on main
    cudaEventRecord(ev_fork, (cudaStream_t)0);
    cudaStreamWaitEvent(s_side, ev_fork, 0);
    nms_kernel<<<NB, 1024, 0, s_side>>>(heat, coords, batch_idxs, N);
    cudaEventRecord(ev_nms, s_side);

    int tg = (N + 255) / 256;
    dim3 tgrid(tg, 2);
    tower_layer_kernel<<<tgrid, 256>>>(output_feats, yA, Wm,        Wk,        nullptr,     N, 1);
    colstats_kernel<<<256, 256>>>(yA, stats, N);
    tower_layer_kernel<<<tgrid, 256>>>(yA,           yB, Wm + 1024, Wk + 1024, stats,       N, 0);
    colstats_kernel<<<256, 256>>>(yB, stats + 128, N);
    tower_layer_kernel<<<tgrid, 256>>>(yB,           yA, Wm + 2048, Wk + 2048, stats + 128, N, 0);
    colstats_kernel<<<256, 256>>>(yA, stats + 256, N);
    feats_kernel<<<tgrid, 256>>>(yA, Wm_out, bm_out, Wk_out, bk_out, stats + 256, N);

    // join NMS; cand_prep needs NMS + feats
    cudaStreamWaitEvent((cudaStream_t)0, ev_nms, 0);
    cand_prep_kernel<<<IC, 352>>>(coords, batch_idxs, Wwg, bwg);
    cudaEventRecord(ev_cand, (cudaStream_t)0);

    // merge chain on side stream, overlapped with masks on main
    cudaStreamWaitEvent(s_side, ev_cand, 0);
    merge_layer_kernel<<<64, 256, 0, s_side>>>(nullptr, mA, Wg,        nullptr,      mstats,       1);
    merge_layer_kernel<<<64, 256, 0, s_side>>>(mA,      mB, Wg + 1225, mstats,       mstats + 128, 0);
    merge_layer_kernel<<<64, 256, 0, s_side>>>(mB,      mA, Wg + 2450, mstats + 128, mstats + 256, 0);
    merge_out_kernel<<<64, 256, 0, s_side>>>(mA, Wg_out, bg_out, mstats + 256, out, N);
    cudaEventRecord(ev_merge, s_side);

    dim3 mg((N + 255) / 256, 8);
    masks_kernel<<<mg, 128>>>(coords, out, N);

    // ensure graph end depends on merge chain
    cudaStreamWaitEvent((cudaStream_t)0, ev_merge, 0);
}

// round 13
// speedup vs baseline: 1.6480x; 1.0189x over previous
#include <cuda_runtime.h>
#include <math.h>
#include <stdint.h>

#define D32   32
#define OD    16
#define NB    4
#define KK    32
#define R2C   0.09f
#define EPSF  1e-5f
#define NMAX  100000
#define IC    128
#define MR    (IC*IC)

typedef unsigned long long u64;

// ---------------- device scratch (no allocations allowed) ----------------
__device__ float g_yA[NMAX*64];
__device__ float g_yB[NMAX*64];
__device__ float g_maskf[NMAX*OD];
__device__ float g_kernf[NMAX*OD];
__device__ float g_stats[3*128];
__device__ float g_mstats[3*128];
__device__ int   g_topk[IC];
__device__ float g_feat[IC*35];
__device__ float g_ctr[IC*3];
__device__ int   g_cb[IC];
__device__ float g_mA[MR*35];
__device__ float g_mB[MR*35];
__device__ float g_nmsbuf[NMAX];
__device__ float g_w1aug2[64*16*40];
__device__ float g_w2p[64*16*2];
__device__ float g_b2p[64*2];

__device__ __forceinline__ float sigmoidf_(float x) {
    return 1.0f / (1.0f + __expf(-x));
}
__device__ __forceinline__ u64 pack2(float lo, float hi) {
    u64 r; asm("mov.b64 %0, {%1, %2};" : "=l"(r) : "f"(lo), "f"(hi)); return r;
}
__device__ __forceinline__ u64 dup2(float x) { return pack2(x, x); }
__device__ __forceinline__ void unpack2(u64 v, float &lo, float &hi) {
    asm("mov.b64 {%0, %1}, %2;" : "=f"(lo), "=f"(hi) : "l"(v));
}
__device__ __forceinline__ u64 ffma2(u64 a, u64 b, u64 c) {
    u64 d; asm("fma.rn.f32x2 %0, %1, %2, %3;" : "=l"(d) : "l"(a), "l"(b), "l"(c)); return d;
}

// ---------------- greedy top-K NMS: heat register-resident ----------------
__global__ __launch_bounds__(1024, 1)
void nms_kernel(const float* __restrict__ heat, const float* __restrict__ coords,
                const int* __restrict__ bidx, int N) {
    int b = blockIdx.x;
    int lo = 0, hi = N;
    while (lo < hi) { int m = (lo + hi) >> 1; if (bidx[m] < b) lo = m + 1; else hi = m; }
    int s = lo; hi = N;
    while (lo < hi) { int m = (lo + hi) >> 1; if (bidx[m] <= b) lo = m + 1; else hi = m; }
    int e = lo, nb = e - s;

    __shared__ float rv[32]; __shared__ int ri[32];
    __shared__ float cc[3]; __shared__ int have;
    if (threadIdx.x == 0) have = 0;

    const float NEG = __int_as_float(0xff800000);
    int lane = threadIdx.x & 31, w = threadIdx.x >> 5;

    if (nb <= 32768) {
        float hv[32];
        #pragma unroll
        for (int ii = 0; ii < 32; ii++) {
            int t = ii*1024 + threadIdx.x;
            hv[ii] = (t < nb) ? heat[s + t] : NEG;
        }
        __syncthreads();
        for (int k = 0; k < KK; k++) {
            int h = have;
            float cx = 0.f, cy = 0.f, cz = 0.f;
            if (h) { cx = cc[0]; cy = cc[1]; cz = cc[2]; }
            float best = NEG; int bi = 0x7fffffff;
            #pragma unroll
            for (int ii = 0; ii < 32; ii++) {
                int t = ii*1024 + threadIdx.x;
                if (t >= nb) break;
                float v = hv[ii];
                if (h && v != NEG) {
                    int g = s + t;
                    float dx = coords[g*3]   - cx;
                    float dy = coords[g*3+1] - cy;
                    float dz = coords[g*3+2] - cz;
                    if (dx*dx + dy*dy + dz*dz < R2C) { v = NEG; hv[ii] = NEG; }
                }
                if (v > best) { best = v; bi = t; }
            }
            #pragma unroll
            for (int o = 16; o; o >>= 1) {
                float ov = __shfl_down_sync(0xffffffffu, best, o);
                int   oi = __shfl_down_sync(0xffffffffu, bi, o);
                if (ov > best || (ov == best && oi < bi)) { best = ov; bi = oi; }
            }
            if (lane == 0) { rv[w] = best; ri[w] = bi; }
            __syncthreads();
            if (w == 0) {
                best = rv[lane]; bi = ri[lane];
                #pragma unroll
                for (int o = 16; o; o >>= 1) {
                    float ov = __shfl_down_sync(0xffffffffu, best, o);
                    int   oi = __shfl_down_sync(0xffffffffu, bi, o);
                    if (ov > best || (ov == best && oi < bi)) { best = ov; bi = oi; }
                }
                if (lane == 0) {
                    int chosen = (best == NEG) ? 0 : (s + bi);
                    g_topk[b*KK + k] = chosen;
                    cc[0] = coords[chosen*3]; cc[1] = coords[chosen*3+1]; cc[2] = coords[chosen*3+2];
                    have = 1;
                }
            }
            __syncthreads();
        }
    } else {
        float* buf = g_nmsbuf + s;
        for (int t = threadIdx.x; t < nb; t += 1024) buf[t] = heat[s + t];
        __syncthreads();
        for (int k = 0; k < KK; k++) {
            int h = have;
            float cx = 0.f, cy = 0.f, cz = 0.f;
            if (h) { cx = cc[0]; cy = cc[1]; cz = cc[2]; }
            float best = NEG; int bi = 0x7fffffff;
            for (int t = threadIdx.x; t < nb; t += 1024) {
                float v = buf[t];
                if (h && v != NEG) {
                    int g = s + t;
                    float dx = coords[g*3]   - cx;
                    float dy = coords[g*3+1] - cy;
                    float dz = coords[g*3+2] - cz;
                    if (dx*dx + dy*dy + dz*dz < R2C) { v = NEG; buf[t] = NEG; }
                }
                if (v > best) { best = v; bi = t; }
            }
            #pragma unroll
            for (int o = 16; o; o >>= 1) {
                float ov = __shfl_down_sync(0xffffffffu, best, o);
                int   oi = __shfl_down_sync(0xffffffffu, bi, o);
                if (ov > best || (ov == best && oi < bi)) { best = ov; bi = oi; }
            }
            if (lane == 0) { rv[w] = best; ri[w] = bi; }
            __syncthreads();
            if (w == 0) {
                best = rv[lane]; bi = ri[lane];
                #pragma unroll
                for (int o = 16; o; o >>= 1) {
                    float ov = __shfl_down_sync(0xffffffffu, best, o);
                    int   oi = __shfl_down_sync(0xffffffffu, bi, o);
                    if (ov > best || (ov == best && oi < bi)) { best = ov; bi = oi; }
                }
                if (lane == 0) {
                    int chosen = (best == NEG) ? 0 : (s + bi);
                    g_topk[b*KK + k] = chosen;
                    cc[0] = coords[chosen*3]; cc[1] = coords[chosen*3+1]; cc[2] = coords[chosen*3+2];
                    have = 1;
                }
            }
            __syncthreads();
        }
    }
}

// ---------------- tower layer: tiled GEMM, split-K f32x2, 4pts x 4cols / thread ----------------
// gridDim.y = 2 (m-half / k-half). Tile = 128 points x 32 cols.
__global__ __launch_bounds__(256, 3)
void tower_layer_kernel(const float* __restrict__ x, float* __restrict__ y,
                        const float* __restrict__ Wml, const float* __restrict__ Wkl,
                        const float* __restrict__ pstats,
                        int N, int layer0) {
    int half = blockIdx.y;
    if (layer0 && blockIdx.x == 0 && half == 0) {
        for (int t = threadIdx.x; t < 768; t += 256) {
            if (t < 384) g_stats[t] = 0.f;
            else         g_mstats[t - 384] = 0.f;
        }
    }
    // Ws2: d-pair interleaved weights as u64: Ws2[d2][j] = {W[2*d2][j], W[2*d2+1][j]}
    __shared__ u64  Ws2[16*32];      // 4KB
    __shared__ float Xs[128*36];     // 18KB, stride 36 floats (144B, 16B-aligned)
    __shared__ float smean[32], srstd[32];
    const float* Wl = half ? Wkl : Wml;
    for (int t = threadIdx.x; t < 1024; t += 256) {
        int d = t >> 5, j = t & 31;
        float* dst = (float*)&Ws2[(d >> 1)*32 + j];
        dst[d & 1] = Wl[t];
    }
    if (!layer0 && threadIdx.x < 32) {
        int c = half*32 + threadIdx.x;
        float s = pstats[c], q = pstats[64 + c];
        float m = s / (float)N;
        float v = q / (float)N - m*m;
        smean[threadIdx.x] = m;
        srstd[threadIdx.x] = rsqrtf(v + EPSF);
    }
    __syncthreads();

    int pbase = blockIdx.x * 128;
    int instr = layer0 ? 32 : 64;
    int coff  = layer0 ? 0 : half*32;
    // stage X tile with BN+relu: 1024 float4, 4 per thread
    #pragma unroll
    for (int k = 0; k < 4; k++) {
        int f = threadIdx.x + k*256;
        int r = f >> 3, c4 = (f & 7) * 4;
        int n = pbase + r;
        int ns = (n < N) ? n : (N - 1);
        float4 v = *(const float4*)(x + (size_t)ns * instr + coff + c4);
        if (!layer0) {
            v.x = fmaxf((v.x - smean[c4])   * srstd[c4],   0.f);
            v.y = fmaxf((v.y - smean[c4+1]) * srstd[c4+1], 0.f);
            v.z = fmaxf((v.z - smean[c4+2]) * srstd[c4+2], 0.f);
            v.w = fmaxf((v.w - smean[c4+3]) * srstd[c4+3], 0.f);
        }
        *(float4*)&Xs[r*36 + c4] = v;
    }
    __syncthreads();

    int pg = threadIdx.x >> 3;        // 0..31 -> 4 points each
    int cg = threadIdx.x & 7;         // 0..7  -> 4 cols each
    int p0 = pg * 4;

    u64 acc[4][4];                    // [pt][col] = {even-d sum, odd-d sum}
    #pragma unroll
    for (int p = 0; p < 4; p++)
        #pragma unroll
        for (int c = 0; c < 4; c++) acc[p][c] = 0ull;

    #pragma unroll 2
    for (int d2 = 0; d2 < 16; d2 += 2) {
        // x pairs for 2 d-pairs (d = 2*d2 .. 2*d2+3) for 4 points
        ulonglong2 xq[4];
        #pragma unroll
        for (int p = 0; p < 4; p++)
            xq[p] = *(const ulonglong2*)&Xs[(p0 + p)*36 + d2*2];
        #pragma unroll
        for (int u = 0; u < 2; u++) {
            const ulonglong2* wr = (const ulonglong2*)&Ws2[(d2 + u)*32 + cg*4];
            ulonglong2 w0 = wr[0], w1 = wr[1];
            #pragma unroll
            for (int p = 0; p < 4; p++) {
                u64 xp = u ? xq[p].y : xq[p].x;
                acc[p][0] = ffma2(xp, w0.x, acc[p][0]);
                acc[p][1] = ffma2(xp, w0.y, acc[p][1]);
                acc[p][2] = ffma2(xp, w1.x, acc[p][2]);
                acc[p][3] = ffma2(xp, w1.y, acc[p][3]);
            }
        }
    }
    #pragma unroll
    for (int p = 0; p < 4; p++) {
        int n = pbase + p0 + p;
        if (n >= N) break;
        float4 o;
        float lo, hi;
        unpack2(acc[p][0], lo, hi); o.x = lo + hi;
        unpack2(acc[p][1], lo, hi); o.y = lo + hi;
        unpack2(acc[p][2], lo, hi); o.z = lo + hi;
        unpack2(acc[p][3], lo, hi); o.w = lo + hi;
        *(float4*)(y + (size_t)n * 64 + half*32 + cg*4) = o;
    }
}

// ---------------- column stats: 4 row-streams per thread, grid 256 ----------------
#define CS_ACC(vv, ss, qq) \
    ss.x += vv.x; ss.y += vv.y; ss.z += vv.z; ss.w += vv.w; \
    qq.x = fmaf(vv.x, vv.x, qq.x); qq.y = fmaf(vv.y, vv.y, qq.y); \
    qq.z = fmaf(vv.z, vv.z, qq.z); qq.w = fmaf(vv.w, vv.w, qq.w);

__global__ __launch_bounds__(256, 1)
void colstats_kernel(const float* __restrict__ y, float* __restrict__ ostats, int N) {
    int tid = threadIdx.x;
    int lane16 = tid & 15;
    int rg = tid >> 4;
    float4 z = make_float4(0.f,0.f,0.f,0.f);
    float4 s0 = z, q0 = z, s1 = z, q1 = z, s2 = z, q2 = z, s3 = z, q3 = z;
    int r = blockIdx.x * 64 + rg;
    int stride = gridDim.x * 64;
    for (; r + 48 < N; r += stride) {
        float4 v0 = ((const float4*)(y + (size_t)r*64))[lane16];
        float4 v1 = ((const float4*)(y + (size_t)(r+16)*64))[lane16];
        float4 v2 = ((const float4*)(y + (size_t)(r+32)*64))[lane16];
        float4 v3 = ((const float4*)(y + (size_t)(r+48)*64))[lane16];
        CS_ACC(v0, s0, q0) CS_ACC(v1, s1, q1) CS_ACC(v2, s2, q2) CS_ACC(v3, s3, q3)
    }
    if (r < N)      { float4 v = ((const float4*)(y + (size_t)r*64))[lane16];      CS_ACC(v, s0, q0) }
    if (r + 16 < N) { float4 v = ((const float4*)(y + (size_t)(r+16)*64))[lane16]; CS_ACC(v, s1, q1) }
    if (r + 32 < N) { float4 v = ((const float4*)(y + (size_t)(r+32)*64))[lane16]; CS_ACC(v, s2, q2) }
    float4 s = make_float4(s0.x+s1.x+s2.x+s3.x, s0.y+s1.y+s2.y+s3.y,
                           s0.z+s1.z+s2.z+s3.z, s0.w+s1.w+s2.w+s3.w);
    float4 q = make_float4(q0.x+q1.x+q2.x+q3.x, q0.y+q1.y+q2.y+q3.y,
                           q0.z+q1.z+q2.z+q3.z, q0.w+q1.w+q2.w+q3.w);
    __shared__ float sm[256][8];
    sm[tid][0] = s.x; sm[tid][1] = s.y; sm[tid][2] = s.z; sm[tid][3] = s.w;
    sm[tid][4] = q.x; sm[tid][5] = q.y; sm[tid][6] = q.z; sm[tid][7] = q.w;
    __syncthreads();
    if (tid < 16) {
        float a0=0,a1=0,a2=0,a3=0,b0=0,b1=0,b2=0,b3=0;
        #pragma unroll
        for (int g = 0; g < 16; g++) {
            float* p = sm[tid + 16*g];
            a0 += p[0]; a1 += p[1]; a2 += p[2]; a3 += p[3];
            b0 += p[4]; b1 += p[5]; b2 += p[6]; b3 += p[7];
        }
        int c = tid*4;
        atomicAdd(&ostats[c],   a0); atomicAdd(&ostats[c+1], a1);
        atomicAdd(&ostats[c+2], a2); atomicAdd(&ostats[c+3], a3);
        atomicAdd(&ostats[64+c],   b0); atomicAdd(&ostats[64+c+1], b1);
        atomicAdd(&ostats[64+c+2], b2); atomicAdd(&ostats[64+c+3], b3);
    }
}

// ---------------- final projection: gridDim.y=2 (m-half / k-half) ----------------
__global__ __launch_bounds__(256, 3)
void feats_kernel(const float* __restrict__ yin,
                  const float* __restrict__ Wmo, const float* __restrict__ bmo,
                  const float* __restrict__ Wko, const float* __restrict__ bko,
                  const float* __restrict__ pstats, int N) {
    int half = blockIdx.y;
    __shared__ float Wos[32*16];
    __shared__ float bs[16];
    __shared__ float smean[32], srstd[32];
    const float* Wo = half ? Wko : Wmo;
    for (int t = threadIdx.x; t < 512; t += 256) Wos[t] = Wo[t];
    if (threadIdx.x < 16) bs[threadIdx.x] = half ? bko[threadIdx.x] : bmo[threadIdx.x];
    if (threadIdx.x < 32) {
        int c = half*32 + threadIdx.x;
        float s = pstats[c], q = pstats[64 + c];
        float m = s / (float)N;
        float v = q / (float)N - m*m;
        smean[threadIdx.x] = m; srstd[threadIdx.x] = rsqrtf(v + EPSF);
    }
    __syncthreads();
    int n = blockIdx.x * 256 + threadIdx.x;
    if (n >= N) return;

    float xv[32];
    const float4* xr = (const float4*)(yin + (size_t)n * 64 + half*32);
    #pragma unroll
    for (int q = 0; q < 8; q++) {
        float4 v = xr[q]; int d = q*4;
        xv[d]   = fmaxf((v.x - smean[d])   * srstd[d],   0.f);
        xv[d+1] = fmaxf((v.y - smean[d+1]) * srstd[d+1], 0.f);
        xv[d+2] = fmaxf((v.z - smean[d+2]) * srstd[d+2], 0.f);
        xv[d+3] = fmaxf((v.w - smean[d+3]) * srstd[d+3], 0.f);
    }
    u64 acc[8];
    #pragma unroll
    for (int j = 0; j < 8; j++) acc[j] = 0ull;
    #pragma unroll 4
    for (int d = 0; d < 32; d++) {
        u64 xd = dup2(xv[d]);
        const ulonglong2* wr = (const ulonglong2*)(Wos + d*16);
        #pragma unroll
        for (int q = 0; q < 4; q++) {
            ulonglong2 w = wr[q];
            acc[2*q]   = ffma2(xd, w.x, acc[2*q]);
            acc[2*q+1] = ffma2(xd, w.y, acc[2*q+1]);
        }
    }
    float* dst = half ? (g_kernf + (size_t)n * 16) : (g_maskf + (size_t)n * 16);
    #pragma unroll
    for (int q = 0; q < 8; q++) {
        float lo, hi; unpack2(acc[q], lo, hi);
        int j = q*2;
        dst[j] = lo + bs[j]; dst[j+1] = hi + bs[j+1];
    }
}

// ---------------- candidate gather + weight generator + aug-weight build ----------------
__global__ void cand_prep_kernel(const float* __restrict__ coords, const int* __restrict__ bidx,
                                 const float* __restrict__ Wwg, const float* __restrict__ bwg) {
    int i = blockIdx.x;
    int tid = threadIdx.x;
    __shared__ float ck[16];
    __shared__ float ws[337];
    __shared__ float cc[3];
    __shared__ int sidx;
    if (tid == 0) sidx = g_topk[i];
    __syncthreads();
    int idx = sidx;
    if (tid < 16) {
        float v = g_kernf[(size_t)idx*16 + tid];
        ck[tid] = v;
        g_feat[i*35 + tid] = v;
    } else if (tid < 32) {
        g_feat[i*35 + tid] = g_maskf[(size_t)idx*16 + (tid - 16)];
    } else if (tid < 35) {
        float c = coords[(size_t)idx*3 + (tid - 32)];
        g_feat[i*35 + tid] = c;
        g_ctr[i*3 + (tid - 32)] = c;
        cc[tid - 32] = c;
    } else if (tid == 35) {
        g_cb[i] = bidx[idx];
    }
    __syncthreads();
    if (tid < 337) {
        float w = bwg[tid];
        #pragma unroll
        for (int d = 0; d < 16; d++) w = fmaf(ck[d], Wwg[d*337 + tid], w);
        ws[tid] = w;
    }
    __syncthreads();
    int pair = i >> 1, hf = i & 1;
    float cx = cc[0], cy = cc[1], cz = cc[2];
    for (int t = tid; t < 320; t += blockDim.x) {
        int j = t / 20, d = t % 20;
        float v;
        if (d < 16)      v = ws[d*16 + j];
        else if (d < 19) v = ws[(16 + (d-16))*16 + j];
        else             v = ws[304 + j] - cx*ws[256 + j] - cy*ws[272 + j] - cz*ws[288 + j];
        g_w1aug2[pair*640 + j*40 + d*2 + hf] = v;
    }
    if (tid < 16) g_w2p[pair*32 + tid*2 + hf] = ws[320 + tid];
    if (tid == 16) g_b2p[pair*2 + hf] = ws[336];
}

// ---------------- dynamic mask head: FFMA2, 4 points/thread, 8 cand-pairs/block ----------------
__global__ __launch_bounds__(128, 1)
void masks_kernel(const float* __restrict__ coords, float* __restrict__ out, int N) {
    __shared__ float w1t[8*16*40];
    __shared__ float w2s[8*16*2];
    __shared__ float b2s[8*2];
    int tid = threadIdx.x;
    int pbase = blockIdx.y * 8;

    {
        const float4* src = (const float4*)(g_w1aug2 + pbase*640);
        float4* dst = (float4*)w1t;
        for (int t = tid; t < 1280; t += 128) dst[t] = src[t];
        for (int t = tid; t < 256; t += 128) w2s[t] = g_w2p[pbase*32 + t];
        if (tid < 16) b2s[tid] = g_b2p[pbase*2 + tid];
    }
    __syncthreads();

    int nbase = blockIdx.x * 512 + tid;
    int nn[4]; bool vv[4];
    u64 x0[19], x1[19], x2[19], x3[19];
    #pragma unroll
    for (int k = 0; k < 4; k++) {
        int n = nbase + k*128;
        nn[k] = n;
        vv[k] = (n < N);
    }
    {
        int s0 = vv[0] ? nn[0] : (N-1);
        const float4* mr = (const float4*)(g_maskf + (size_t)s0 * 16);
        #pragma unroll
        for (int q = 0; q < 4; q++) {
            float4 m = mr[q];
            x0[q*4] = dup2(m.x); x0[q*4+1] = dup2(m.y); x0[q*4+2] = dup2(m.z); x0[q*4+3] = dup2(m.w);
        }
        x0[16] = dup2(coords[(size_t)s0*3]); x0[17] = dup2(coords[(size_t)s0*3+1]); x0[18] = dup2(coords[(size_t)s0*3+2]);
    }
    {
        int s1 = vv[1] ? nn[1] : (N-1);
        const float4* mr = (const float4*)(g_maskf + (size_t)s1 * 16);
        #pragma unroll
        for (int q = 0; q < 4; q++) {
            float4 m = mr[q];
            x1[q*4] = dup2(m.x); x1[q*4+1] = dup2(m.y); x1[q*4+2] = dup2(m.z); x1[q*4+3] = dup2(m.w);
        }
        x1[16] = dup2(coords[(size_t)s1*3]); x1[17] = dup2(coords[(size_t)s1*3+1]); x1[18] = dup2(coords[(size_t)s1*3+2]);
    }
    {
        int s2 = vv[2] ? nn[2] : (N-1);
        const float4* mr = (const float4*)(g_maskf + (size_t)s2 * 16);
        #pragma unroll
        for (int q = 0; q < 4; q++) {
            float4 m = mr[q];
            x2[q*4] = dup2(m.x); x2[q*4+1] = dup2(m.y); x2[q*4+2] = dup2(m.z); x2[q*4+3] = dup2(m.w);
        }
        x2[16] = dup2(coords[(size_t)s2*3]); x2[17] = dup2(coords[(size_t)s2*3+1]); x2[18] = dup2(coords[(size_t)s2*3+2]);
    }
    {
        int s3 = vv[3] ? nn[3] : (N-1);
        const float4* mr = (const float4*)(g_maskf + (size_t)s3 * 16);
        #pragma unroll
        for (int q = 0; q < 4; q++) {
            float4 m = mr[q];
            x3[q*4] = dup2(m.x); x3[q*4+1] = dup2(m.y); x3[q*4+2] = dup2(m.z); x3[q*4+3] = dup2(m.w);
        }
        x3[16] = dup2(coords[(size_t)s3*3]); x3[17] = dup2(coords[(size_t)s3*3+1]); x3[18] = dup2(coords[(size_t)s3*3+2]);
    }

    size_t ostride = (size_t)N + IC;
    const u64* w2q = (const u64*)w2s;

    #pragma unroll 1
    for (int cp = 0; cp < 8; cp++) {
        u64 macc0 = 0ull, macc1 = 0ull, macc2 = 0ull, macc3 = 0ull;
        const float* wb = w1t + cp*640;
        #pragma unroll 2
        for (int j = 0; j < 16; j++) {
            const ulonglong2* wq2 = (const ulonglong2*)(wb + j*40);
            ulonglong2 wtail = wq2[9];
            u64 h0 = wtail.y, h1 = wtail.y, h2 = wtail.y, h3 = wtail.y;
            #pragma unroll
            for (int q = 0; q < 9; q++) {
                ulonglong2 w = wq2[q];
                h0 = ffma2(x0[2*q], w.x, h0); h0 = ffma2(x0[2*q+1], w.y, h0);
                h1 = ffma2(x1[2*q], w.x, h1); h1 = ffma2(x1[2*q+1], w.y, h1);
                h2 = ffma2(x2[2*q], w.x, h2); h2 = ffma2(x2[2*q+1], w.y, h2);
                h3 = ffma2(x3[2*q], w.x, h3); h3 = ffma2(x3[2*q+1], w.y, h3);
            }
            h0 = ffma2(x0[18], wtail.x, h0);
            h1 = ffma2(x1[18], wtail.x, h1);
            h2 = ffma2(x2[18], wtail.x, h2);
            h3 = ffma2(x3[18], wtail.x, h3);

            u64 w2v = w2q[cp*16 + j];
            float a, b;
            unpack2(h0, a, b); h0 = pack2(fmaxf(a,0.f), fmaxf(b,0.f)); macc0 = ffma2(h0, w2v, macc0);
            unpack2(h1, a, b); h1 = pack2(fmaxf(a,0.f), fmaxf(b,0.f)); macc1 = ffma2(h1, w2v, macc1);
            unpack2(h2, a, b); h2 = pack2(fmaxf(a,0.f), fmaxf(b,0.f)); macc2 = ffma2(h2, w2v, macc2);
            unpack2(h3, a, b); h3 = pack2(fmaxf(a,0.f), fmaxf(b,0.f)); macc3 = ffma2(h3, w2v, macc3);
        }
        float ba = b2s[cp*2], bb = b2s[cp*2+1];
        int ci0 = (pbase + cp) * 2;
        float* row0 = out + (size_t)ci0 * ostride;
        float* row1 = out + (size_t)(ci0 + 1) * ostride;
        float a, b;
        unpack2(macc0, a, b);
        if (vv[0]) { row0[nn[0]] = sigmoidf_(a + ba); row1[nn[0]] = sigmoidf_(b + bb); }
        unpack2(macc1, a, b);
        if (vv[1]) { row0[nn[1]] = sigmoidf_(a + ba); row1[nn[1]] = sigmoidf_(b + bb); }
        unpack2(macc2, a, b);
        if (vv[2]) { row0[nn[2]] = sigmoidf_(a + ba); row1[nn[2]] = sigmoidf_(b + bb); }
        unpack2(macc3, a, b);
        if (vv[3]) { row0[nn[3]] = sigmoidf_(a + ba); row1[nn[3]] = sigmoidf_(b + bb); }
    }
}

// ---------------- merge tower layer ----------------
__global__ __launch_bounds__(256, 1)
void merge_layer_kernel(const float* __restrict__ xin, float* __restrict__ yout,
                        const float* __restrict__ Wgl,
                        const float* __restrict__ pstats, float* __restrict__ ostats,
                        int layer0) {
    __shared__ float Ws[35*35];
    __shared__ float featS[IC*35];
    __shared__ float smean[35], srstd[35];
    __shared__ float ps[8][70];
    int tid = threadIdx.x;
    for (int t = tid; t < 1225; t += 256) Ws[t] = Wgl[t];
    if (layer0) {
        for (int t = tid; t < IC*35; t += 256) featS[t] = g_feat[t];
    } else if (tid < 35) {
        float s = pstats[tid], q = pstats[64 + tid];
        float m = s / (float)MR;
        float v = q / (float)MR - m*m;
        smean[tid] = m; srstd[tid] = rsqrtf(v + EPSF);
    }
    __syncthreads();

    int row = blockIdx.x * 256 + tid;
    float xv[35];
    if (layer0) {
        int i = row >> 7, j = row & 127;
        #pragma unroll
        for (int c = 0; c < 35; c++)
            xv[c] = fmaxf(fabsf(featS[i*35 + c] - featS[j*35 + c]), 1e-6f);
    } else {
        #pragma unroll
        for (int c = 0; c < 35; c++)
            xv[c] = fmaxf((xin[(size_t)row*35 + c] - smean[c]) * srstd[c], 0.f);
    }
    float acc[35];
    #pragma unroll
    for (int c = 0; c < 35; c++) acc[c] = 0.f;
    for (int c = 0; c < 35; c++) {
        float xa = xv[c];
        const float* wr = Ws + c*35;
        #pragma unroll
        for (int c2 = 0; c2 < 35; c2++) acc[c2] = fmaf(xa, wr[c2], acc[c2]);
    }
    #pragma unroll
    for (int c = 0; c < 35; c++) yout[(size_t)row*35 + c] = acc[c];

    int lane = tid & 31, warp = tid >> 5;
    for (int c = 0; c < 35; c++) {
        float s = acc[c]; float q = s * s;
        #pragma unroll
        for (int o = 16; o; o >>= 1) {
            s += __shfl_down_sync(0xffffffffu, s, o);
            q += __shfl_down_sync(0xffffffffu, q, o);
        }
        if (lane == 0) { ps[warp][c] = s; ps[warp][35 + c] = q; }
    }
    __syncthreads();
    if (tid < 70) {
        float t = 0.f;
        #pragma unroll
        for (int w = 0; w < 8; w++) t += ps[w][tid];
        int target = (tid < 35) ? tid : (64 + tid - 35);
        atomicAdd(&ostats[target], t);
    }
}

// ---------------- merge output ----------------
__global__ __launch_bounds__(256, 1)
void merge_out_kernel(const float* __restrict__ xin,
                      const float* __restrict__ Wgo, const float* __restrict__ bgo,
                      const float* __restrict__ pstats,
                      float* __restrict__ out, int N) {
    __shared__ float wout[35];
    __shared__ float smean[35], srstd[35];
    int tid = threadIdx.x;
    if (tid < 35) {
        wout[tid] = Wgo[tid];
        float s = pstats[tid], q = pstats[64 + tid];
        float m = s / (float)MR;
        float v = q / (float)MR - m*m;
        smean[tid] = m; srstd[tid] = rsqrtf(v + EPSF);
    }
    __syncthreads();
    int row = blockIdx.x * 256 + tid;
    int i = row >> 7, j = row & 127;
    float acc = bgo[0];
    #pragma unroll
    for (int c = 0; c < 35; c++) {
        float x = fmaxf((xin[(size_t)row*35 + c] - smean[c]) * srstd[c], 0.f);
        acc = fmaf(x, wout[c], acc);
    }
    float v = (g_cb[i] != g_cb[j]) ? 0.f : sigmoidf_(acc);
    out[(size_t)i * ((size_t)N + IC) + (size_t)N + j] = v;
}

// ---------------- launch ----------------
extern "C" void kernel_launch(void* const* d_in, const int* in_sizes, int n_in,
                              void* d_out, int out_size) {
    const float* output_feats = (const float*)d_in[0];
    const float* coords       = (const float*)d_in[1];
    const float* heat         = (const float*)d_in[2];
    const int*   batch_idxs   = (const int*)  d_in[3];
    const float* Wm           = (const float*)d_in[4];
    const float* Wm_out       = (const float*)d_in[5];
    const float* bm_out       = (const float*)d_in[6];
    const float* Wk           = (const float*)d_in[7];
    const float* Wk_out       = (const float*)d_in[8];
    const float* bk_out       = (const float*)d_in[9];
    const float* Wg           = (const float*)d_in[10];
    const float* Wg_out       = (const float*)d_in[11];
    const float* bg_out       = (const float*)d_in[12];
    const float* Wwg          = (const float*)d_in[13];
    const float* bwg          = (const float*)d_in[14];
    float* out = (float*)d_out;
    int N = in_sizes[2];

    static cudaStream_t s_side = nullptr;
    static cudaEvent_t ev_fork = nullptr, ev_nms = nullptr, ev_cand = nullptr, ev_merge = nullptr;
    if (s_side == nullptr) {
        cudaStreamCreateWithFlags(&s_side, cudaStreamNonBlocking);
        cudaEventCreateWithFlags(&ev_fork, cudaEventDisableTiming);
        cudaEventCreateWithFlags(&ev_nms, cudaEventDisableTiming);
        cudaEventCreateWithFlags(&ev_cand, cudaEventDisableTiming);
        cudaEventCreateWithFlags(&ev_merge, cudaEventDisableTiming);
    }

    float *yA, *yB, *mA, *mB, *stats, *mstats;
    cudaGetSymbolAddress((void**)&yA, g_yA);
    cudaGetSymbolAddress((void**)&yB, g_yB);
    cudaGetSymbolAddress((void**)&mA, g_mA);
    cudaGetSymbolAddress((void**)&mB, g_mB);
    cudaGetSymbolAddress((void**)&stats, g_stats);
    cudaGetSymbolAddress((void**)&mstats, g_mstats);

    // fork: NMS on side stream, towers on main
    cudaEventRecord(ev_fork, (cudaStream_t)0);
    cudaStreamWaitEvent(s_side, ev_fork, 0);
    nms_kernel<<<NB, 1024, 0, s_side>>>(heat, coords, batch_idxs, N);
    cudaEventRecord(ev_nms, s_side);

    int tg = (N + 127) / 128;
    dim3 tgrid(tg, 2);
    tower_layer_kernel<<<tgrid, 256>>>(output_feats, yA, Wm,        Wk,        nullptr,     N, 1);
    colstats_kernel<<<256, 256>>>(yA, stats, N);
    tower_layer_kernel<<<tgrid, 256>>>(yA,           yB, Wm + 1024, Wk + 1024, stats,       N, 0);
    colstats_kernel<<<256, 256>>>(yB, stats + 128, N);
    tower_layer_kernel<<<tgrid, 256>>>(yB,           yA, Wm + 2048, Wk + 2048, stats + 128, N, 0);
    colstats_kernel<<<256, 256>>>(yA, stats + 256, N);
    dim3 fgrid((N + 255) / 256, 2);
    feats_kernel<<<fgrid, 256>>>(yA, Wm_out, bm_out, Wk_out, bk_out, stats + 256, N);

    // join NMS; cand_prep needs NMS + feats
    cudaStreamWaitEvent((cudaStream_t)0, ev_nms, 0);
    cand_prep_kernel<<<IC, 352>>>(coords, batch_idxs, Wwg, bwg);
    cudaEventRecord(ev_cand, (cudaStream_t)0);

    // merge chain on side stream, overlapped with masks on main
    cudaStreamWaitEvent(s_side, ev_cand, 0);
    merge_layer_kernel<<<64, 256, 0, s_side>>>(nullptr, mA, Wg,        nullptr,      mstats,       1);
    merge_layer_kernel<<<64, 256, 0, s_side>>>(mA,      mB, Wg + 1225, mstats,       mstats + 128, 0);
    merge_layer_kernel<<<64, 256, 0, s_side>>>(mB,      mA, Wg + 2450, mstats + 128, mstats + 256, 0);
    merge_out_kernel<<<64, 256, 0, s_side>>>(mA, Wg_out, bg_out, mstats + 256, out, N);
    cudaEventRecord(ev_merge, s_side);

    dim3 mg((N + 511) / 512, 8);
    masks_kernel<<<mg, 128>>>(coords, out, N);

    // ensure graph end depends on merge chain
    cudaStreamWaitEvent((cudaStream_t)0, ev_merge, 0);
}